// round 1
// baseline (speedup 1.0000x reference)
#include <cuda_runtime.h>
#include <cuda_bf16.h>

// Problem constants
#define Bv   2
#define Sv   2048
#define Dv   1024
#define Hv   16
#define DKv  64
#define Fv   4096
#define Mv   (Bv * Sv)      // 4096 rows
#define LN_EPS 1e-6f

// ---------------------------------------------------------------------------
// Scratch (no cudaMalloc allowed -> __device__ globals)
// ---------------------------------------------------------------------------
__device__ float g_q   [(size_t)Mv * Dv];
__device__ float g_k   [(size_t)Mv * Dv];
__device__ float g_v   [(size_t)Mv * Dv];
__device__ float g_attn[(size_t)Mv * Dv];
__device__ float g_tmp [(size_t)Mv * Dv];   // attn proj, later ff2 output
__device__ float g_h   [(size_t)Mv * Dv];
__device__ float g_ff1 [(size_t)Mv * Fv];
__device__ float g_sc  [(size_t)Bv * Hv * Sv * Sv];   // 536 MB scores

// ---------------------------------------------------------------------------
// SGEMM: C[M,N] = A[M,K] @ W[K,N] + bias (optional ReLU)
// BM=BN=128, BK=8, 256 threads, 8x8 per thread. All dims multiples -> no guards.
// ---------------------------------------------------------------------------
#define BM 128
#define BN 128
#define BK 8
#define TM 8
#define TN 8

template <bool RELU>
__global__ void __launch_bounds__(256) sgemm_bias(
    int M, int N, int K,
    const float* __restrict__ A, const float* __restrict__ W,
    const float* __restrict__ bias, float* __restrict__ C)
{
    const int cRow = blockIdx.y;
    const int cCol = blockIdx.x;
    const int tid  = threadIdx.x;

    __shared__ float As[BK][BM];
    __shared__ float Bs[BK][BN];

    A += (size_t)cRow * BM * K;
    W += (size_t)cCol * BN;
    C += (size_t)cRow * BM * N + (size_t)cCol * BN;
    const float* biasB = bias + (size_t)cCol * BN;

    const int innerRowA = tid >> 1;          // 0..127
    const int innerColA = (tid & 1) * 4;     // 0 or 4
    const int innerRowB = tid >> 5;          // 0..7
    const int innerColB = (tid & 31) * 4;    // 0..124

    const int threadRow = (tid >> 4) * TM;   // 0..120
    const int threadCol = (tid & 15) * TN;   // 0..120

    float acc[TM][TN] = {};
    float regM[TM], regN[TN];

    for (int k0 = 0; k0 < K; k0 += BK) {
        float4 a = *(const float4*)(A + (size_t)innerRowA * K + k0 + innerColA);
        As[innerColA + 0][innerRowA] = a.x;
        As[innerColA + 1][innerRowA] = a.y;
        As[innerColA + 2][innerRowA] = a.z;
        As[innerColA + 3][innerRowA] = a.w;
        *(float4*)(&Bs[innerRowB][innerColB]) =
            *(const float4*)(W + (size_t)(k0 + innerRowB) * N + innerColB);
        __syncthreads();

#pragma unroll
        for (int k = 0; k < BK; ++k) {
#pragma unroll
            for (int i = 0; i < TM; ++i) regM[i] = As[k][threadRow + i];
#pragma unroll
            for (int j = 0; j < TN; ++j) regN[j] = Bs[k][threadCol + j];
#pragma unroll
            for (int i = 0; i < TM; ++i)
#pragma unroll
                for (int j = 0; j < TN; ++j)
                    acc[i][j] += regM[i] * regN[j];
        }
        __syncthreads();
    }

#pragma unroll
    for (int i = 0; i < TM; ++i) {
        float* crow = C + (size_t)(threadRow + i) * N + threadCol;
#pragma unroll
        for (int j = 0; j < TN; j += 4) {
            float4 o;
            o.x = acc[i][j + 0] + biasB[threadCol + j + 0];
            o.y = acc[i][j + 1] + biasB[threadCol + j + 1];
            o.z = acc[i][j + 2] + biasB[threadCol + j + 2];
            o.w = acc[i][j + 3] + biasB[threadCol + j + 3];
            if (RELU) {
                o.x = fmaxf(o.x, 0.f); o.y = fmaxf(o.y, 0.f);
                o.z = fmaxf(o.z, 0.f); o.w = fmaxf(o.w, 0.f);
            }
            *(float4*)(crow + j) = o;
        }
    }
}

// ---------------------------------------------------------------------------
// Attention scores: s[b,h,i,j] = scale * sum_d q[b,i,h,d]*k[b,j,h,d]
// block = 64x64 output tile for one (b,h); 256 threads, 4x4 per thread.
// ---------------------------------------------------------------------------
__global__ void __launch_bounds__(256) attn_scores(
    const float* __restrict__ q, const float* __restrict__ k,
    float* __restrict__ s)
{
    const int bh = blockIdx.z;
    const int b  = bh / Hv;
    const int h  = bh % Hv;
    const int i0 = blockIdx.y * 64;
    const int j0 = blockIdx.x * 64;

    __shared__ float Qs[64][68];   // [d][i]
    __shared__ float Ks[64][68];   // [d][j]

    const int tid = threadIdx.x;
    const int tx  = tid & 15;      // d-group
    const int iy  = tid >> 4;      // row group
    const int d0  = tx * 4;

#pragma unroll
    for (int rep = 0; rep < 4; ++rep) {
        const int r = iy + rep * 16;
        float4 a = *(const float4*)(q + ((size_t)(b * Sv + i0 + r)) * Dv + h * DKv + d0);
        Qs[d0 + 0][r] = a.x; Qs[d0 + 1][r] = a.y;
        Qs[d0 + 2][r] = a.z; Qs[d0 + 3][r] = a.w;
        float4 c = *(const float4*)(k + ((size_t)(b * Sv + j0 + r)) * Dv + h * DKv + d0);
        Ks[d0 + 0][r] = c.x; Ks[d0 + 1][r] = c.y;
        Ks[d0 + 2][r] = c.z; Ks[d0 + 3][r] = c.w;
    }
    __syncthreads();

    const int r0 = (tid >> 4) * 4;
    const int c0 = (tid & 15) * 4;
    float acc[4][4] = {};

#pragma unroll
    for (int d = 0; d < 64; ++d) {
        float4 a  = *(const float4*)(&Qs[d][r0]);
        float4 bb = *(const float4*)(&Ks[d][c0]);
        acc[0][0] += a.x * bb.x; acc[0][1] += a.x * bb.y; acc[0][2] += a.x * bb.z; acc[0][3] += a.x * bb.w;
        acc[1][0] += a.y * bb.x; acc[1][1] += a.y * bb.y; acc[1][2] += a.y * bb.z; acc[1][3] += a.y * bb.w;
        acc[2][0] += a.z * bb.x; acc[2][1] += a.z * bb.y; acc[2][2] += a.z * bb.z; acc[2][3] += a.z * bb.w;
        acc[3][0] += a.w * bb.x; acc[3][1] += a.w * bb.y; acc[3][2] += a.w * bb.z; acc[3][3] += a.w * bb.w;
    }

    const float scale = 0.125f;  // 1/sqrt(64)
#pragma unroll
    for (int i = 0; i < 4; ++i) {
        float4 o;
        o.x = acc[i][0] * scale; o.y = acc[i][1] * scale;
        o.z = acc[i][2] * scale; o.w = acc[i][3] * scale;
        *(float4*)(s + ((size_t)bh * Sv + i0 + r0 + i) * Sv + j0 + c0) = o;
    }
}

// ---------------------------------------------------------------------------
// Row softmax over S=2048, one block per row, in-place.
// ---------------------------------------------------------------------------
__global__ void __launch_bounds__(256) softmax_rows(float* __restrict__ s)
{
    float* p = s + (size_t)blockIdx.x * Sv;
    const int tid = threadIdx.x;

    float v[8];
    float m = -1e30f;
#pragma unroll
    for (int t = 0; t < 8; ++t) { v[t] = p[t * 256 + tid]; m = fmaxf(m, v[t]); }

    __shared__ float red[8];
#pragma unroll
    for (int o = 16; o > 0; o >>= 1) m = fmaxf(m, __shfl_xor_sync(0xffffffffu, m, o));
    if ((tid & 31) == 0) red[tid >> 5] = m;
    __syncthreads();
    if (tid == 0) {
        float t = red[0];
#pragma unroll
        for (int i = 1; i < 8; ++i) t = fmaxf(t, red[i]);
        red[0] = t;
    }
    __syncthreads();
    m = red[0];
    __syncthreads();

    float sum = 0.f;
#pragma unroll
    for (int t = 0; t < 8; ++t) { v[t] = __expf(v[t] - m); sum += v[t]; }
#pragma unroll
    for (int o = 16; o > 0; o >>= 1) sum += __shfl_xor_sync(0xffffffffu, sum, o);
    if ((tid & 31) == 0) red[tid >> 5] = sum;
    __syncthreads();
    if (tid == 0) {
        float t = 0.f;
#pragma unroll
        for (int i = 0; i < 8; ++i) t += red[i];
        red[0] = t;
    }
    __syncthreads();
    const float inv = 1.0f / red[0];
#pragma unroll
    for (int t = 0; t < 8; ++t) p[t * 256 + tid] = v[t] * inv;
}

// ---------------------------------------------------------------------------
// PV: attn[b,i,h,d] = sum_j p[b,h,i,j] * v[b,j,h,d]
// block = 64 query rows x 64 head dims for one (b,h); loop over j tiles.
// ---------------------------------------------------------------------------
__global__ void __launch_bounds__(256) attn_pv(
    const float* __restrict__ p, const float* __restrict__ v,
    float* __restrict__ o)
{
    const int bh = blockIdx.y;
    const int b  = bh / Hv;
    const int h  = bh % Hv;
    const int i0 = blockIdx.x * 64;

    __shared__ float Ps[64][68];   // [j][i]
    __shared__ float Vs[64][68];   // [j][d]

    const int tid = threadIdx.x;
    const int tx  = tid & 15;
    const int iy  = tid >> 4;
    const int r0  = (tid >> 4) * 4;
    const int c0  = (tid & 15) * 4;

    float acc[4][4] = {};

    for (int jt = 0; jt < Sv; jt += 64) {
#pragma unroll
        for (int rep = 0; rep < 4; ++rep) {
            const int r  = iy + rep * 16;    // i (for Ps) or j (for Vs)
            const int j4 = tx * 4;
            float4 a = *(const float4*)(p + ((size_t)bh * Sv + i0 + r) * Sv + jt + j4);
            Ps[j4 + 0][r] = a.x; Ps[j4 + 1][r] = a.y;
            Ps[j4 + 2][r] = a.z; Ps[j4 + 3][r] = a.w;
            float4 c = *(const float4*)(v + ((size_t)(b * Sv + jt + r)) * Dv + h * DKv + j4);
            *(float4*)(&Vs[r][j4]) = c;
        }
        __syncthreads();

#pragma unroll
        for (int j = 0; j < 64; ++j) {
            float4 a  = *(const float4*)(&Ps[j][r0]);
            float4 bb = *(const float4*)(&Vs[j][c0]);
            acc[0][0] += a.x * bb.x; acc[0][1] += a.x * bb.y; acc[0][2] += a.x * bb.z; acc[0][3] += a.x * bb.w;
            acc[1][0] += a.y * bb.x; acc[1][1] += a.y * bb.y; acc[1][2] += a.y * bb.z; acc[1][3] += a.y * bb.w;
            acc[2][0] += a.z * bb.x; acc[2][1] += a.z * bb.y; acc[2][2] += a.z * bb.z; acc[2][3] += a.z * bb.w;
            acc[3][0] += a.w * bb.x; acc[3][1] += a.w * bb.y; acc[3][2] += a.w * bb.z; acc[3][3] += a.w * bb.w;
        }
        __syncthreads();
    }

#pragma unroll
    for (int i = 0; i < 4; ++i) {
        float4 ov;
        ov.x = acc[i][0]; ov.y = acc[i][1]; ov.z = acc[i][2]; ov.w = acc[i][3];
        *(float4*)(o + ((size_t)(b * Sv + i0 + r0 + i)) * Dv + h * DKv + c0) = ov;
    }
}

// ---------------------------------------------------------------------------
// Fused residual + LayerNorm: out = LN(a + r) * g + be, one block per row.
// ---------------------------------------------------------------------------
__global__ void __launch_bounds__(256) residual_ln(
    const float* __restrict__ a, const float* __restrict__ r,
    const float* __restrict__ g, const float* __restrict__ be,
    float* __restrict__ out)
{
    const size_t row = blockIdx.x;
    const int tid = threadIdx.x;

    const float4 va = *(const float4*)(a + row * Dv + tid * 4);
    const float4 vr = *(const float4*)(r + row * Dv + tid * 4);
    float4 x;
    x.x = va.x + vr.x; x.y = va.y + vr.y; x.z = va.z + vr.z; x.w = va.w + vr.w;

    float s  = x.x + x.y + x.z + x.w;
    float s2 = x.x * x.x + x.y * x.y + x.z * x.z + x.w * x.w;

    __shared__ float rs[8], rs2[8];
#pragma unroll
    for (int o = 16; o > 0; o >>= 1) {
        s  += __shfl_xor_sync(0xffffffffu, s,  o);
        s2 += __shfl_xor_sync(0xffffffffu, s2, o);
    }
    if ((tid & 31) == 0) { rs[tid >> 5] = s; rs2[tid >> 5] = s2; }
    __syncthreads();
    if (tid == 0) {
        float ts = 0.f, t2 = 0.f;
#pragma unroll
        for (int i = 0; i < 8; ++i) { ts += rs[i]; t2 += rs2[i]; }
        rs[0] = ts; rs2[0] = t2;
    }
    __syncthreads();

    const float mu  = rs[0] * (1.0f / Dv);
    const float var = rs2[0] * (1.0f / Dv) - mu * mu;
    const float inv = rsqrtf(var + LN_EPS);

    const float4 vg = *(const float4*)(g + tid * 4);
    const float4 vb = *(const float4*)(be + tid * 4);
    float4 o;
    o.x = (x.x - mu) * inv * vg.x + vb.x;
    o.y = (x.y - mu) * inv * vg.y + vb.y;
    o.z = (x.z - mu) * inv * vg.z + vb.z;
    o.w = (x.w - mu) * inv * vg.w + vb.w;
    *(float4*)(out + row * Dv + tid * 4) = o;
}

// ---------------------------------------------------------------------------
// Launch
// ---------------------------------------------------------------------------
extern "C" void kernel_launch(void* const* d_in, const int* in_sizes, int n_in,
                              void* d_out, int out_size)
{
    const float* x  = (const float*)d_in[0];
    const float* wq = (const float*)d_in[1];
    const float* bq = (const float*)d_in[2];
    const float* wk = (const float*)d_in[3];
    const float* bk = (const float*)d_in[4];
    const float* wv = (const float*)d_in[5];
    const float* bv = (const float*)d_in[6];
    const float* wo = (const float*)d_in[7];
    const float* bo = (const float*)d_in[8];
    const float* w1 = (const float*)d_in[9];
    const float* b1 = (const float*)d_in[10];
    const float* w2 = (const float*)d_in[11];
    const float* b2 = (const float*)d_in[12];
    const float* g1 = (const float*)d_in[13];
    const float* be1= (const float*)d_in[14];
    const float* g2 = (const float*)d_in[15];
    const float* be2= (const float*)d_in[16];
    float* out = (float*)d_out;

    float *q, *k, *v, *attn, *tmp, *h, *ff1, *sc;
    cudaGetSymbolAddress((void**)&q,    g_q);
    cudaGetSymbolAddress((void**)&k,    g_k);
    cudaGetSymbolAddress((void**)&v,    g_v);
    cudaGetSymbolAddress((void**)&attn, g_attn);
    cudaGetSymbolAddress((void**)&tmp,  g_tmp);
    cudaGetSymbolAddress((void**)&h,    g_h);
    cudaGetSymbolAddress((void**)&ff1,  g_ff1);
    cudaGetSymbolAddress((void**)&sc,   g_sc);

    const dim3 gemmDD(Dv / BN, Mv / BM);   // N=1024
    const dim3 gemmDF(Fv / BN, Mv / BM);   // N=4096

    // QKV projections
    sgemm_bias<false><<<gemmDD, 256>>>(Mv, Dv, Dv, x, wq, bq, q);
    sgemm_bias<false><<<gemmDD, 256>>>(Mv, Dv, Dv, x, wk, bk, k);
    sgemm_bias<false><<<gemmDD, 256>>>(Mv, Dv, Dv, x, wv, bv, v);

    // Attention
    attn_scores<<<dim3(Sv / 64, Sv / 64, Bv * Hv), 256>>>(q, k, sc);
    softmax_rows<<<Bv * Hv * Sv, 256>>>(sc);
    attn_pv<<<dim3(Sv / 64, Bv * Hv), 256>>>(sc, v, attn);

    // Output projection + residual LN1
    sgemm_bias<false><<<gemmDD, 256>>>(Mv, Dv, Dv, attn, wo, bo, tmp);
    residual_ln<<<Mv, 256>>>(x, tmp, g1, be1, h);

    // FFN + residual LN2
    sgemm_bias<true ><<<gemmDF, 256>>>(Mv, Fv, Dv, h, w1, b1, ff1);
    sgemm_bias<false><<<gemmDD, 256>>>(Mv, Dv, Fv, ff1, w2, b2, tmp);
    residual_ln<<<Mv, 256>>>(h, tmp, g2, be2, out);
}

// round 3
// speedup vs baseline: 1.6591x; 1.6591x over previous
#include <cuda_runtime.h>
#include <cstdint>

// Problem constants
#define Bv   2
#define Sv   2048
#define Dv   1024
#define Hv   16
#define DKv  64
#define Fv   4096
#define Mv   (Bv * Sv)      // 4096 rows
#define LN_EPS 1e-6f

// ---------------------------------------------------------------------------
// Scratch (no cudaMalloc allowed -> __device__ globals)
// ---------------------------------------------------------------------------
__device__ float g_q   [(size_t)Mv * Dv];
__device__ float g_k   [(size_t)Mv * Dv];
__device__ float g_v   [(size_t)Mv * Dv];
__device__ float g_attn[(size_t)Mv * Dv];
__device__ float g_tmp [(size_t)Mv * Dv];
__device__ float g_h   [(size_t)Mv * Dv];
__device__ float g_ff1 [(size_t)Mv * Fv];
__device__ float g_sc  [(size_t)Bv * Hv * Sv * Sv];   // scores
__device__ float g_wT  [(size_t)12 * 1024 * 1024];    // transposed tf32 weights

// ---------------------------------------------------------------------------
// Helpers
// ---------------------------------------------------------------------------
__device__ __forceinline__ uint32_t smem_u32(const void* p) {
    uint32_t a;
    asm("{ .reg .u64 t; cvta.to.shared.u64 t, %1; cvt.u32.u64 %0, t; }"
        : "=r"(a) : "l"(p));
    return a;
}
__device__ __forceinline__ float to_tf32(float x) {
    uint32_t u;
    asm("cvt.rna.tf32.f32 %0, %1;" : "=r"(u) : "f"(x));
    return __uint_as_float(u);
}
__device__ __forceinline__ uint32_t tf32u(float x) {
    uint32_t u;
    asm("cvt.rna.tf32.f32 %0, %1;" : "=r"(u) : "f"(x));
    return u;
}

// ---------------------------------------------------------------------------
// Weight transpose + tf32 rounding: WT[n][k] = tf32(W[k][n])
// ---------------------------------------------------------------------------
__global__ void __launch_bounds__(256) transpose_tf32(
    const float* __restrict__ W, float* __restrict__ WT, int K, int N)
{
    __shared__ float t[32][33];
    const int k0 = blockIdx.y * 32, n0 = blockIdx.x * 32;
    const int tx = threadIdx.x, ty0 = threadIdx.y;
#pragma unroll
    for (int i = 0; i < 4; ++i) {
        const int ty = ty0 + i * 8;
        t[ty][tx] = W[(size_t)(k0 + ty) * N + n0 + tx];
    }
    __syncthreads();
#pragma unroll
    for (int i = 0; i < 4; ++i) {
        const int ty = ty0 + i * 8;
        WT[(size_t)(n0 + ty) * K + k0 + tx] = to_tf32(t[tx][ty]);
    }
}

// ---------------------------------------------------------------------------
// Tensor-core GEMM via mma.sync tf32 (arch-agnostic PTX, runs on HMMA pipe).
// C[M,N] = A[M,K] @ WT[N,K]^T + bias (opt ReLU)
// CTA: 128x128 tile, BK=32, 8 warps (2x4 -> 64x32 warp tiles), cp.async
// double buffering. Smem stride 36 floats => conflict-free fragment loads.
// ---------------------------------------------------------------------------
#define GBK 32
#define GSTRIDE 36                       // floats per smem row (144 B, 16B aligned)
#define GSM_FLOATS (128 * GSTRIDE)       // one tile
#define GSMEM_BYTES (4 * GSM_FLOATS * 4) // 2 stages x (A,B) = 73728 B

template <bool RELU>
__global__ void __launch_bounds__(256)
gemm_mma(int K, int N, const float* __restrict__ A,
         const float* __restrict__ WT, const float* __restrict__ bias,
         float* __restrict__ C)
{
    extern __shared__ float sm[];
    const int m0 = blockIdx.y * 128;
    const int n0 = blockIdx.x * 128;
    const int tid  = threadIdx.x;
    const int lane = tid & 31;
    const int wid  = tid >> 5;
    const int wm = (wid >> 2) * 64;   // warp row offset (0/64)
    const int wn = (wid & 3) * 32;    // warp col offset (0/32/64/96)

    float* tA[2] = { sm,                  sm + 2 * GSM_FLOATS };
    float* tB[2] = { sm + GSM_FLOATS,     sm + 3 * GSM_FLOATS };
    const uint32_t uA[2] = { smem_u32(tA[0]), smem_u32(tA[1]) };
    const uint32_t uB[2] = { smem_u32(tB[0]), smem_u32(tB[1]) };

    const float* Ab = A  + (size_t)m0 * K;
    const float* Bb = WT + (size_t)n0 * K;
    const int nk = K / GBK;

    // acc[mt][nt][4]
    float acc[4][4][4] = {};

    // ---- stage loader: 128 rows x 32 floats per tile, 8 float4 per row ----
    auto load_stage = [&](int buf, int kt) {
#pragma unroll
        for (int i = 0; i < 4; ++i) {
            const int s   = tid + i * 256;     // 0..1023
            const int row = s >> 3;
            const int f   = s & 7;
            const float* ga = Ab + (size_t)row * K + kt * GBK + f * 4;
            const float* gb = Bb + (size_t)row * K + kt * GBK + f * 4;
            const uint32_t da = uA[buf] + (uint32_t)(row * (GSTRIDE * 4) + f * 16);
            const uint32_t db = uB[buf] + (uint32_t)(row * (GSTRIDE * 4) + f * 16);
            asm volatile("cp.async.cg.shared.global [%0], [%1], 16;" :: "r"(da), "l"(ga));
            asm volatile("cp.async.cg.shared.global [%0], [%1], 16;" :: "r"(db), "l"(gb));
        }
    };

    load_stage(0, 0);
    asm volatile("cp.async.commit_group;" ::: "memory");

    const int r = lane >> 2;   // group id 0..7
    const int c = lane & 3;    // thread-in-group 0..3

    for (int kt = 0; kt < nk; ++kt) {
        const int buf = kt & 1;
        if (kt + 1 < nk) load_stage(buf ^ 1, kt + 1);
        asm volatile("cp.async.commit_group;" ::: "memory");
        asm volatile("cp.async.wait_group 1;" ::: "memory");
        __syncthreads();

        const float* sa = tA[buf];
        const float* sb = tB[buf];

#pragma unroll
        for (int kk = 0; kk < 4; ++kk) {
            const int k0 = kk * 8;
            uint32_t afr[4][4];
            uint32_t bfr[4][2];
#pragma unroll
            for (int mt = 0; mt < 4; ++mt) {
                const float* base  = sa + (size_t)(wm + mt * 16 + r) * GSTRIDE + k0 + c;
                const float* base8 = base + 8 * GSTRIDE;
                afr[mt][0] = tf32u(base[0]);    // (row r,    col c)
                afr[mt][1] = tf32u(base8[0]);   // (row r+8,  col c)
                afr[mt][2] = tf32u(base[4]);    // (row r,    col c+4)
                afr[mt][3] = tf32u(base8[4]);   // (row r+8,  col c+4)
            }
#pragma unroll
            for (int nt = 0; nt < 4; ++nt) {
                const float* base = sb + (size_t)(wn + nt * 8 + r) * GSTRIDE + k0 + c;
                bfr[nt][0] = __float_as_uint(base[0]);   // (k c,   n r) - WT pre-rounded
                bfr[nt][1] = __float_as_uint(base[4]);   // (k c+4, n r)
            }
#pragma unroll
            for (int mt = 0; mt < 4; ++mt)
#pragma unroll
                for (int nt = 0; nt < 4; ++nt) {
                    float* d = acc[mt][nt];
                    asm volatile(
                        "mma.sync.aligned.m16n8k8.row.col.f32.tf32.tf32.f32 "
                        "{%0,%1,%2,%3}, {%4,%5,%6,%7}, {%8,%9}, {%0,%1,%2,%3};"
                        : "+f"(d[0]), "+f"(d[1]), "+f"(d[2]), "+f"(d[3])
                        : "r"(afr[mt][0]), "r"(afr[mt][1]),
                          "r"(afr[mt][2]), "r"(afr[mt][3]),
                          "r"(bfr[nt][0]), "r"(bfr[nt][1]));
                }
        }
        __syncthreads();
    }

    // ---- epilogue: bias (+ReLU), float2 stores ----
#pragma unroll
    for (int mt = 0; mt < 4; ++mt) {
        const int rg = m0 + wm + mt * 16 + r;
#pragma unroll
        for (int nt = 0; nt < 4; ++nt) {
            const int cg = n0 + wn + nt * 8 + c * 2;
            const float b0 = bias[cg], b1 = bias[cg + 1];
            float2 v0, v1;
            v0.x = acc[mt][nt][0] + b0; v0.y = acc[mt][nt][1] + b1;
            v1.x = acc[mt][nt][2] + b0; v1.y = acc[mt][nt][3] + b1;
            if (RELU) {
                v0.x = fmaxf(v0.x, 0.f); v0.y = fmaxf(v0.y, 0.f);
                v1.x = fmaxf(v1.x, 0.f); v1.y = fmaxf(v1.y, 0.f);
            }
            *(float2*)(C + (size_t)rg * N + cg)       = v0;
            *(float2*)(C + (size_t)(rg + 8) * N + cg) = v1;
        }
    }
}

// ---------------------------------------------------------------------------
// Attention scores: s[b,h,i,j] = scale * sum_d q[b,i,h,d]*k[b,j,h,d]
// ---------------------------------------------------------------------------
__global__ void __launch_bounds__(256) attn_scores(
    const float* __restrict__ q, const float* __restrict__ k,
    float* __restrict__ s)
{
    const int bh = blockIdx.z;
    const int b  = bh / Hv;
    const int h  = bh % Hv;
    const int i0 = blockIdx.y * 64;
    const int j0 = blockIdx.x * 64;

    __shared__ float Qs[64][68];
    __shared__ float Ks[64][68];

    const int tid = threadIdx.x;
    const int tx  = tid & 15;
    const int iy  = tid >> 4;
    const int d0  = tx * 4;

#pragma unroll
    for (int rep = 0; rep < 4; ++rep) {
        const int r = iy + rep * 16;
        float4 a = *(const float4*)(q + ((size_t)(b * Sv + i0 + r)) * Dv + h * DKv + d0);
        Qs[d0 + 0][r] = a.x; Qs[d0 + 1][r] = a.y;
        Qs[d0 + 2][r] = a.z; Qs[d0 + 3][r] = a.w;
        float4 c = *(const float4*)(k + ((size_t)(b * Sv + j0 + r)) * Dv + h * DKv + d0);
        Ks[d0 + 0][r] = c.x; Ks[d0 + 1][r] = c.y;
        Ks[d0 + 2][r] = c.z; Ks[d0 + 3][r] = c.w;
    }
    __syncthreads();

    const int r0 = (tid >> 4) * 4;
    const int c0 = (tid & 15) * 4;
    float acc[4][4] = {};

#pragma unroll
    for (int d = 0; d < 64; ++d) {
        float4 a  = *(const float4*)(&Qs[d][r0]);
        float4 bb = *(const float4*)(&Ks[d][c0]);
        acc[0][0] += a.x * bb.x; acc[0][1] += a.x * bb.y; acc[0][2] += a.x * bb.z; acc[0][3] += a.x * bb.w;
        acc[1][0] += a.y * bb.x; acc[1][1] += a.y * bb.y; acc[1][2] += a.y * bb.z; acc[1][3] += a.y * bb.w;
        acc[2][0] += a.z * bb.x; acc[2][1] += a.z * bb.y; acc[2][2] += a.z * bb.z; acc[2][3] += a.z * bb.w;
        acc[3][0] += a.w * bb.x; acc[3][1] += a.w * bb.y; acc[3][2] += a.w * bb.z; acc[3][3] += a.w * bb.w;
    }

    const float scale = 0.125f;
#pragma unroll
    for (int i = 0; i < 4; ++i) {
        float4 o;
        o.x = acc[i][0] * scale; o.y = acc[i][1] * scale;
        o.z = acc[i][2] * scale; o.w = acc[i][3] * scale;
        *(float4*)(s + ((size_t)bh * Sv + i0 + r0 + i) * Sv + j0 + c0) = o;
    }
}

// ---------------------------------------------------------------------------
// Row softmax over S=2048
// ---------------------------------------------------------------------------
__global__ void __launch_bounds__(256) softmax_rows(float* __restrict__ s)
{
    float* p = s + (size_t)blockIdx.x * Sv;
    const int tid = threadIdx.x;

    float v[8];
    float m = -1e30f;
#pragma unroll
    for (int t = 0; t < 8; ++t) { v[t] = p[t * 256 + tid]; m = fmaxf(m, v[t]); }

    __shared__ float red[8];
#pragma unroll
    for (int o = 16; o > 0; o >>= 1) m = fmaxf(m, __shfl_xor_sync(0xffffffffu, m, o));
    if ((tid & 31) == 0) red[tid >> 5] = m;
    __syncthreads();
    if (tid == 0) {
        float t = red[0];
#pragma unroll
        for (int i = 1; i < 8; ++i) t = fmaxf(t, red[i]);
        red[0] = t;
    }
    __syncthreads();
    m = red[0];
    __syncthreads();

    float sum = 0.f;
#pragma unroll
    for (int t = 0; t < 8; ++t) { v[t] = __expf(v[t] - m); sum += v[t]; }
#pragma unroll
    for (int o = 16; o > 0; o >>= 1) sum += __shfl_xor_sync(0xffffffffu, sum, o);
    if ((tid & 31) == 0) red[tid >> 5] = sum;
    __syncthreads();
    if (tid == 0) {
        float t = 0.f;
#pragma unroll
        for (int i = 0; i < 8; ++i) t += red[i];
        red[0] = t;
    }
    __syncthreads();
    const float inv = 1.0f / red[0];
#pragma unroll
    for (int t = 0; t < 8; ++t) p[t * 256 + tid] = v[t] * inv;
}

// ---------------------------------------------------------------------------
// PV: attn[b,i,h,d] = sum_j p[b,h,i,j] * v[b,j,h,d]
// ---------------------------------------------------------------------------
__global__ void __launch_bounds__(256) attn_pv(
    const float* __restrict__ p, const float* __restrict__ v,
    float* __restrict__ o)
{
    const int bh = blockIdx.y;
    const int b  = bh / Hv;
    const int h  = bh % Hv;
    const int i0 = blockIdx.x * 64;

    __shared__ float Ps[64][68];
    __shared__ float Vs[64][68];

    const int tid = threadIdx.x;
    const int tx  = tid & 15;
    const int iy  = tid >> 4;
    const int r0  = (tid >> 4) * 4;
    const int c0  = (tid & 15) * 4;

    float acc[4][4] = {};

    for (int jt = 0; jt < Sv; jt += 64) {
#pragma unroll
        for (int rep = 0; rep < 4; ++rep) {
            const int r  = iy + rep * 16;
            const int j4 = tx * 4;
            float4 a = *(const float4*)(p + ((size_t)bh * Sv + i0 + r) * Sv + jt + j4);
            Ps[j4 + 0][r] = a.x; Ps[j4 + 1][r] = a.y;
            Ps[j4 + 2][r] = a.z; Ps[j4 + 3][r] = a.w;
            float4 c = *(const float4*)(v + ((size_t)(b * Sv + jt + r)) * Dv + h * DKv + j4);
            *(float4*)(&Vs[r][j4]) = c;
        }
        __syncthreads();

#pragma unroll
        for (int j = 0; j < 64; ++j) {
            float4 a  = *(const float4*)(&Ps[j][r0]);
            float4 bb = *(const float4*)(&Vs[j][c0]);
            acc[0][0] += a.x * bb.x; acc[0][1] += a.x * bb.y; acc[0][2] += a.x * bb.z; acc[0][3] += a.x * bb.w;
            acc[1][0] += a.y * bb.x; acc[1][1] += a.y * bb.y; acc[1][2] += a.y * bb.z; acc[1][3] += a.y * bb.w;
            acc[2][0] += a.z * bb.x; acc[2][1] += a.z * bb.y; acc[2][2] += a.z * bb.z; acc[2][3] += a.z * bb.w;
            acc[3][0] += a.w * bb.x; acc[3][1] += a.w * bb.y; acc[3][2] += a.w * bb.z; acc[3][3] += a.w * bb.w;
        }
        __syncthreads();
    }

#pragma unroll
    for (int i = 0; i < 4; ++i) {
        float4 ov;
        ov.x = acc[i][0]; ov.y = acc[i][1]; ov.z = acc[i][2]; ov.w = acc[i][3];
        *(float4*)(o + ((size_t)(b * Sv + i0 + r0 + i)) * Dv + h * DKv + c0) = ov;
    }
}

// ---------------------------------------------------------------------------
// Fused residual + LayerNorm
// ---------------------------------------------------------------------------
__global__ void __launch_bounds__(256) residual_ln(
    const float* __restrict__ a, const float* __restrict__ r,
    const float* __restrict__ g, const float* __restrict__ be,
    float* __restrict__ out)
{
    const size_t row = blockIdx.x;
    const int tid = threadIdx.x;

    const float4 va = *(const float4*)(a + row * Dv + tid * 4);
    const float4 vr = *(const float4*)(r + row * Dv + tid * 4);
    float4 x;
    x.x = va.x + vr.x; x.y = va.y + vr.y; x.z = va.z + vr.z; x.w = va.w + vr.w;

    float s  = x.x + x.y + x.z + x.w;
    float s2 = x.x * x.x + x.y * x.y + x.z * x.z + x.w * x.w;

    __shared__ float rs[8], rs2[8];
#pragma unroll
    for (int o = 16; o > 0; o >>= 1) {
        s  += __shfl_xor_sync(0xffffffffu, s,  o);
        s2 += __shfl_xor_sync(0xffffffffu, s2, o);
    }
    if ((tid & 31) == 0) { rs[tid >> 5] = s; rs2[tid >> 5] = s2; }
    __syncthreads();
    if (tid == 0) {
        float ts = 0.f, t2 = 0.f;
#pragma unroll
        for (int i = 0; i < 8; ++i) { ts += rs[i]; t2 += rs2[i]; }
        rs[0] = ts; rs2[0] = t2;
    }
    __syncthreads();

    const float mu  = rs[0] * (1.0f / Dv);
    const float var = rs2[0] * (1.0f / Dv) - mu * mu;
    const float inv = rsqrtf(var + LN_EPS);

    const float4 vg = *(const float4*)(g + tid * 4);
    const float4 vb = *(const float4*)(be + tid * 4);
    float4 o;
    o.x = (x.x - mu) * inv * vg.x + vb.x;
    o.y = (x.y - mu) * inv * vg.y + vb.y;
    o.z = (x.z - mu) * inv * vg.z + vb.z;
    o.w = (x.w - mu) * inv * vg.w + vb.w;
    *(float4*)(out + row * Dv + tid * 4) = o;
}

// ---------------------------------------------------------------------------
// Launch
// ---------------------------------------------------------------------------
extern "C" void kernel_launch(void* const* d_in, const int* in_sizes, int n_in,
                              void* d_out, int out_size)
{
    const float* x  = (const float*)d_in[0];
    const float* wq = (const float*)d_in[1];
    const float* bq = (const float*)d_in[2];
    const float* wk = (const float*)d_in[3];
    const float* bk = (const float*)d_in[4];
    const float* wv = (const float*)d_in[5];
    const float* bv = (const float*)d_in[6];
    const float* wo = (const float*)d_in[7];
    const float* bo = (const float*)d_in[8];
    const float* w1 = (const float*)d_in[9];
    const float* b1 = (const float*)d_in[10];
    const float* w2 = (const float*)d_in[11];
    const float* b2 = (const float*)d_in[12];
    const float* g1 = (const float*)d_in[13];
    const float* be1= (const float*)d_in[14];
    const float* g2 = (const float*)d_in[15];
    const float* be2= (const float*)d_in[16];
    float* out = (float*)d_out;

    float *q, *k, *v, *attn, *tmp, *h, *ff1, *sc, *wT;
    cudaGetSymbolAddress((void**)&q,    g_q);
    cudaGetSymbolAddress((void**)&k,    g_k);
    cudaGetSymbolAddress((void**)&v,    g_v);
    cudaGetSymbolAddress((void**)&attn, g_attn);
    cudaGetSymbolAddress((void**)&tmp,  g_tmp);
    cudaGetSymbolAddress((void**)&h,    g_h);
    cudaGetSymbolAddress((void**)&ff1,  g_ff1);
    cudaGetSymbolAddress((void**)&sc,   g_sc);
    cudaGetSymbolAddress((void**)&wT,   g_wT);

    const size_t MB1 = 1024 * 1024;
    float* wqT = wT + 0 * MB1;
    float* wkT = wT + 1 * MB1;
    float* wvT = wT + 2 * MB1;
    float* woT = wT + 3 * MB1;
    float* w1T = wT + 4 * MB1;   // [F, D]
    float* w2T = wT + 8 * MB1;   // [D, F]

    // Allow 72KB dynamic smem (idempotent; safe during capture)
    cudaFuncSetAttribute(gemm_mma<false>,
        cudaFuncAttributeMaxDynamicSharedMemorySize, GSMEM_BYTES);
    cudaFuncSetAttribute(gemm_mma<true>,
        cudaFuncAttributeMaxDynamicSharedMemorySize, GSMEM_BYTES);

    // Transpose + tf32-round weights
    dim3 tb(32, 8);
    transpose_tf32<<<dim3(Dv / 32, Dv / 32), tb>>>(wq, wqT, Dv, Dv);
    transpose_tf32<<<dim3(Dv / 32, Dv / 32), tb>>>(wk, wkT, Dv, Dv);
    transpose_tf32<<<dim3(Dv / 32, Dv / 32), tb>>>(wv, wvT, Dv, Dv);
    transpose_tf32<<<dim3(Dv / 32, Dv / 32), tb>>>(wo, woT, Dv, Dv);
    transpose_tf32<<<dim3(Fv / 32, Dv / 32), tb>>>(w1, w1T, Dv, Fv);
    transpose_tf32<<<dim3(Dv / 32, Fv / 32), tb>>>(w2, w2T, Fv, Dv);

    const dim3 gDD(Dv / 128, Mv / 128);   // (8, 32)
    const dim3 gDF(Fv / 128, Mv / 128);   // (32, 32)

    // QKV projections (tensor cores, tf32 mma.sync)
    gemm_mma<false><<<gDD, 256, GSMEM_BYTES>>>(Dv, Dv, x, wqT, bq, q);
    gemm_mma<false><<<gDD, 256, GSMEM_BYTES>>>(Dv, Dv, x, wkT, bk, k);
    gemm_mma<false><<<gDD, 256, GSMEM_BYTES>>>(Dv, Dv, x, wvT, bv, v);

    // Attention (fp32 CUDA-core pipeline)
    attn_scores<<<dim3(Sv / 64, Sv / 64, Bv * Hv), 256>>>(q, k, sc);
    softmax_rows<<<Bv * Hv * Sv, 256>>>(sc);
    attn_pv<<<dim3(Sv / 64, Bv * Hv), 256>>>(sc, v, attn);

    // Output projection + residual LN1
    gemm_mma<false><<<gDD, 256, GSMEM_BYTES>>>(Dv, Dv, attn, woT, bo, tmp);
    residual_ln<<<Mv, 256>>>(x, tmp, g1, be1, h);

    // FFN + residual LN2
    gemm_mma<true ><<<gDF, 256, GSMEM_BYTES>>>(Dv, Fv, h, w1T, b1, ff1);
    gemm_mma<false><<<gDD, 256, GSMEM_BYTES>>>(Fv, Dv, ff1, w2T, b2, tmp);
    residual_ln<<<Mv, 256>>>(h, tmp, g2, be2, out);
}

// round 4
// speedup vs baseline: 2.7003x; 1.6276x over previous
#include <cuda_runtime.h>
#include <cstdint>

// Problem constants
#define Bv   2
#define Sv   2048
#define Dv   1024
#define Hv   16
#define DKv  64
#define Fv   4096
#define Mv   (Bv * Sv)      // 4096 rows
#define LN_EPS 1e-6f

// ---------------------------------------------------------------------------
// Scratch (no cudaMalloc allowed -> __device__ globals)
// ---------------------------------------------------------------------------
__device__ float g_q   [(size_t)Mv * Dv];
__device__ float g_k   [(size_t)Mv * Dv];
__device__ float g_v   [(size_t)Mv * Dv];
__device__ float g_attn[(size_t)Mv * Dv];
__device__ float g_tmp [(size_t)Mv * Dv];
__device__ float g_h   [(size_t)Mv * Dv];
__device__ float g_ff1 [(size_t)Mv * Fv];
__device__ float g_wT  [(size_t)12 * 1024 * 1024];    // transposed tf32 weights

// ---------------------------------------------------------------------------
// Helpers
// ---------------------------------------------------------------------------
__device__ __forceinline__ uint32_t smem_u32(const void* p) {
    uint32_t a;
    asm("{ .reg .u64 t; cvta.to.shared.u64 t, %1; cvt.u32.u64 %0, t; }"
        : "=r"(a) : "l"(p));
    return a;
}
__device__ __forceinline__ float to_tf32(float x) {
    uint32_t u;
    asm("cvt.rna.tf32.f32 %0, %1;" : "=r"(u) : "f"(x));
    return __uint_as_float(u);
}
__device__ __forceinline__ uint32_t tf32u(float x) {
    uint32_t u;
    asm("cvt.rna.tf32.f32 %0, %1;" : "=r"(u) : "f"(x));
    return u;
}
__device__ __forceinline__ void mma_tf32(
    float* d, const uint32_t* a, uint32_t b0, uint32_t b1)
{
    asm volatile(
        "mma.sync.aligned.m16n8k8.row.col.f32.tf32.tf32.f32 "
        "{%0,%1,%2,%3}, {%4,%5,%6,%7}, {%8,%9}, {%0,%1,%2,%3};"
        : "+f"(d[0]), "+f"(d[1]), "+f"(d[2]), "+f"(d[3])
        : "r"(a[0]), "r"(a[1]), "r"(a[2]), "r"(a[3]), "r"(b0), "r"(b1));
}

// ---------------------------------------------------------------------------
// Weight transpose + tf32 rounding: WT[n][k] = tf32(W[k][n])
// ---------------------------------------------------------------------------
__global__ void __launch_bounds__(256) transpose_tf32(
    const float* __restrict__ W, float* __restrict__ WT, int K, int N)
{
    __shared__ float t[32][33];
    const int k0 = blockIdx.y * 32, n0 = blockIdx.x * 32;
    const int tx = threadIdx.x, ty0 = threadIdx.y;
#pragma unroll
    for (int i = 0; i < 4; ++i) {
        const int ty = ty0 + i * 8;
        t[ty][tx] = W[(size_t)(k0 + ty) * N + n0 + tx];
    }
    __syncthreads();
#pragma unroll
    for (int i = 0; i < 4; ++i) {
        const int ty = ty0 + i * 8;
        WT[(size_t)(n0 + ty) * K + k0 + tx] = to_tf32(t[tx][ty]);
    }
}

// ---------------------------------------------------------------------------
// Tensor-core GEMM via mma.sync tf32.
// C[M,N] = A[M,K] @ WT[N,K]^T + bias (opt ReLU)
// ---------------------------------------------------------------------------
#define GBK 32
#define GSTRIDE 36
#define GSM_FLOATS (128 * GSTRIDE)
#define GSMEM_BYTES (4 * GSM_FLOATS * 4)

template <bool RELU>
__global__ void __launch_bounds__(256)
gemm_mma(int K, int N, const float* __restrict__ A,
         const float* __restrict__ WT, const float* __restrict__ bias,
         float* __restrict__ C)
{
    extern __shared__ float sm[];
    const int m0 = blockIdx.y * 128;
    const int n0 = blockIdx.x * 128;
    const int tid  = threadIdx.x;
    const int lane = tid & 31;
    const int wid  = tid >> 5;
    const int wm = (wid >> 2) * 64;
    const int wn = (wid & 3) * 32;

    float* tA[2] = { sm,                  sm + 2 * GSM_FLOATS };
    float* tB[2] = { sm + GSM_FLOATS,     sm + 3 * GSM_FLOATS };
    const uint32_t uA[2] = { smem_u32(tA[0]), smem_u32(tA[1]) };
    const uint32_t uB[2] = { smem_u32(tB[0]), smem_u32(tB[1]) };

    const float* Ab = A  + (size_t)m0 * K;
    const float* Bb = WT + (size_t)n0 * K;
    const int nk = K / GBK;

    float acc[4][4][4] = {};

    auto load_stage = [&](int buf, int kt) {
#pragma unroll
        for (int i = 0; i < 4; ++i) {
            const int s   = tid + i * 256;
            const int row = s >> 3;
            const int f   = s & 7;
            const float* ga = Ab + (size_t)row * K + kt * GBK + f * 4;
            const float* gb = Bb + (size_t)row * K + kt * GBK + f * 4;
            const uint32_t da = uA[buf] + (uint32_t)(row * (GSTRIDE * 4) + f * 16);
            const uint32_t db = uB[buf] + (uint32_t)(row * (GSTRIDE * 4) + f * 16);
            asm volatile("cp.async.cg.shared.global [%0], [%1], 16;" :: "r"(da), "l"(ga));
            asm volatile("cp.async.cg.shared.global [%0], [%1], 16;" :: "r"(db), "l"(gb));
        }
    };

    load_stage(0, 0);
    asm volatile("cp.async.commit_group;" ::: "memory");

    const int r = lane >> 2;
    const int c = lane & 3;

    for (int kt = 0; kt < nk; ++kt) {
        const int buf = kt & 1;
        if (kt + 1 < nk) load_stage(buf ^ 1, kt + 1);
        asm volatile("cp.async.commit_group;" ::: "memory");
        asm volatile("cp.async.wait_group 1;" ::: "memory");
        __syncthreads();

        const float* sa = tA[buf];
        const float* sb = tB[buf];

#pragma unroll
        for (int kk = 0; kk < 4; ++kk) {
            const int k0 = kk * 8;
            uint32_t afr[4][4];
            uint32_t bfr[4][2];
#pragma unroll
            for (int mt = 0; mt < 4; ++mt) {
                const float* base  = sa + (size_t)(wm + mt * 16 + r) * GSTRIDE + k0 + c;
                const float* base8 = base + 8 * GSTRIDE;
                afr[mt][0] = tf32u(base[0]);
                afr[mt][1] = tf32u(base8[0]);
                afr[mt][2] = tf32u(base[4]);
                afr[mt][3] = tf32u(base8[4]);
            }
#pragma unroll
            for (int nt = 0; nt < 4; ++nt) {
                const float* base = sb + (size_t)(wn + nt * 8 + r) * GSTRIDE + k0 + c;
                bfr[nt][0] = __float_as_uint(base[0]);
                bfr[nt][1] = __float_as_uint(base[4]);
            }
#pragma unroll
            for (int mt = 0; mt < 4; ++mt)
#pragma unroll
                for (int nt = 0; nt < 4; ++nt)
                    mma_tf32(acc[mt][nt], afr[mt], bfr[nt][0], bfr[nt][1]);
        }
        __syncthreads();
    }

#pragma unroll
    for (int mt = 0; mt < 4; ++mt) {
        const int rg = m0 + wm + mt * 16 + r;
#pragma unroll
        for (int nt = 0; nt < 4; ++nt) {
            const int cg = n0 + wn + nt * 8 + c * 2;
            const float b0 = bias[cg], b1 = bias[cg + 1];
            float2 v0, v1;
            v0.x = acc[mt][nt][0] + b0; v0.y = acc[mt][nt][1] + b1;
            v1.x = acc[mt][nt][2] + b0; v1.y = acc[mt][nt][3] + b1;
            if (RELU) {
                v0.x = fmaxf(v0.x, 0.f); v0.y = fmaxf(v0.y, 0.f);
                v1.x = fmaxf(v1.x, 0.f); v1.y = fmaxf(v1.y, 0.f);
            }
            *(float2*)(C + (size_t)rg * N + cg)       = v0;
            *(float2*)(C + (size_t)(rg + 8) * N + cg) = v1;
        }
    }
}

// ---------------------------------------------------------------------------
// Fused flash attention (tf32 mma.sync + online softmax).
// CTA = 64 Q rows of one (b,h); 4 warps x 16 rows; 32 KV tiles of 64,
// cp.async double-buffered. Q fragments register-resident (pre-scaled).
// attn[b,i,h,d] = softmax_j(q.k/8) . v
// ---------------------------------------------------------------------------
#define KSTRIDE 68
#define VSTRIDE 72
#define PSTRIDE 68
#define FA_SMEM_FLOATS (2*64*KSTRIDE + 2*64*VSTRIDE + 4*16*PSTRIDE)
#define FA_SMEM_BYTES  (FA_SMEM_FLOATS * 4)

__global__ void __launch_bounds__(128)
flash_attn(const float* __restrict__ q, const float* __restrict__ k,
           const float* __restrict__ v, float* __restrict__ o)
{
    extern __shared__ float sm[];
    float* Kt[2] = { sm, sm + 64 * KSTRIDE };
    float* Vt[2] = { sm + 2*64*KSTRIDE, sm + 2*64*KSTRIDE + 64*VSTRIDE };
    float* Pt    = sm + 2*64*KSTRIDE + 2*64*VSTRIDE;

    const int bh = blockIdx.y;
    const int b  = bh >> 4;
    const int h  = bh & 15;
    const int i0 = blockIdx.x * 64;

    const int tid  = threadIdx.x;
    const int lane = tid & 31;
    const int wid  = tid >> 5;
    const int r = lane >> 2;
    const int c = lane & 3;

    const uint32_t uK[2] = { smem_u32(Kt[0]), smem_u32(Kt[1]) };
    const uint32_t uV[2] = { smem_u32(Vt[0]), smem_u32(Vt[1]) };
    float* Pw = Pt + wid * 16 * PSTRIDE;

    // Q fragments, pre-scaled by 1/sqrt(dk)=0.125 (exact power of 2)
    uint32_t qa[8][4];
    {
        const float* qb = q + ((size_t)(b * Sv + i0 + wid * 16)) * Dv + h * DKv;
#pragma unroll
        for (int kk = 0; kk < 8; ++kk) {
            const int col = kk * 8 + c;
            qa[kk][0] = tf32u(0.125f * qb[(size_t)r * Dv + col]);
            qa[kk][1] = tf32u(0.125f * qb[(size_t)(r + 8) * Dv + col]);
            qa[kk][2] = tf32u(0.125f * qb[(size_t)r * Dv + col + 4]);
            qa[kk][3] = tf32u(0.125f * qb[(size_t)(r + 8) * Dv + col + 4]);
        }
    }

    float oacc[8][4] = {};
    float m_lo = -1e30f, m_hi = -1e30f;
    float l_lo = 0.f,    l_hi = 0.f;

    auto load_kv = [&](int buf, int jt) {
        const float* kb = k + ((size_t)(b * Sv + jt * 64)) * Dv + h * DKv;
        const float* vb = v + ((size_t)(b * Sv + jt * 64)) * Dv + h * DKv;
#pragma unroll
        for (int i = 0; i < 8; ++i) {
            const int s   = tid + i * 128;   // 0..1023
            const int row = s >> 4;
            const int f   = s & 15;
            const uint32_t dk_ = uK[buf] + (uint32_t)(row * (KSTRIDE * 4) + f * 16);
            const uint32_t dv_ = uV[buf] + (uint32_t)(row * (VSTRIDE * 4) + f * 16);
            asm volatile("cp.async.cg.shared.global [%0], [%1], 16;"
                         :: "r"(dk_), "l"(kb + (size_t)row * Dv + f * 4));
            asm volatile("cp.async.cg.shared.global [%0], [%1], 16;"
                         :: "r"(dv_), "l"(vb + (size_t)row * Dv + f * 4));
        }
    };

    load_kv(0, 0);
    asm volatile("cp.async.commit_group;" ::: "memory");

    const int NT = Sv / 64;   // 32 KV tiles
    for (int jt = 0; jt < NT; ++jt) {
        const int buf = jt & 1;
        if (jt + 1 < NT) load_kv(buf ^ 1, jt + 1);
        asm volatile("cp.async.commit_group;" ::: "memory");
        asm volatile("cp.async.wait_group 1;" ::: "memory");
        __syncthreads();

        const float* ks = Kt[buf];
        const float* vs = Vt[buf];

        // ---- S = Q K^T (pre-scaled) ----
        float sacc[8][4] = {};
#pragma unroll
        for (int kk = 0; kk < 8; ++kk) {
            const int k0 = kk * 8;
#pragma unroll
            for (int nt = 0; nt < 8; ++nt) {
                const float* kp = ks + (size_t)(nt * 8 + r) * KSTRIDE + k0 + c;
                mma_tf32(sacc[nt], qa[kk],
                         __float_as_uint(kp[0]), __float_as_uint(kp[4]));
            }
        }

        // ---- online softmax ----
        float tmx_lo = -1e30f, tmx_hi = -1e30f;
#pragma unroll
        for (int nt = 0; nt < 8; ++nt) {
            tmx_lo = fmaxf(tmx_lo, fmaxf(sacc[nt][0], sacc[nt][1]));
            tmx_hi = fmaxf(tmx_hi, fmaxf(sacc[nt][2], sacc[nt][3]));
        }
        tmx_lo = fmaxf(tmx_lo, __shfl_xor_sync(0xffffffffu, tmx_lo, 1));
        tmx_lo = fmaxf(tmx_lo, __shfl_xor_sync(0xffffffffu, tmx_lo, 2));
        tmx_hi = fmaxf(tmx_hi, __shfl_xor_sync(0xffffffffu, tmx_hi, 1));
        tmx_hi = fmaxf(tmx_hi, __shfl_xor_sync(0xffffffffu, tmx_hi, 2));

        const float mn_lo = fmaxf(m_lo, tmx_lo);
        const float mn_hi = fmaxf(m_hi, tmx_hi);
        const float cor_lo = __expf(m_lo - mn_lo);
        const float cor_hi = __expf(m_hi - mn_hi);

        float sum_lo = 0.f, sum_hi = 0.f;
#pragma unroll
        for (int nt = 0; nt < 8; ++nt) {
            const float p0 = __expf(sacc[nt][0] - mn_lo);
            const float p1 = __expf(sacc[nt][1] - mn_lo);
            const float p2 = __expf(sacc[nt][2] - mn_hi);
            const float p3 = __expf(sacc[nt][3] - mn_hi);
            sum_lo += p0 + p1;
            sum_hi += p2 + p3;
            float* plo = Pw + (size_t)r * PSTRIDE + nt * 8 + 2 * c;
            float* phi = Pw + (size_t)(r + 8) * PSTRIDE + nt * 8 + 2 * c;
            plo[0] = to_tf32(p0); plo[1] = to_tf32(p1);
            phi[0] = to_tf32(p2); phi[1] = to_tf32(p3);
            // rescale O
            oacc[nt][0] *= cor_lo; oacc[nt][1] *= cor_lo;
            oacc[nt][2] *= cor_hi; oacc[nt][3] *= cor_hi;
        }
        sum_lo += __shfl_xor_sync(0xffffffffu, sum_lo, 1);
        sum_lo += __shfl_xor_sync(0xffffffffu, sum_lo, 2);
        sum_hi += __shfl_xor_sync(0xffffffffu, sum_hi, 1);
        sum_hi += __shfl_xor_sync(0xffffffffu, sum_hi, 2);

        l_lo = l_lo * cor_lo + sum_lo;
        l_hi = l_hi * cor_hi + sum_hi;
        m_lo = mn_lo;
        m_hi = mn_hi;

        __syncwarp();

        // ---- O += P V ----
#pragma unroll
        for (int kk = 0; kk < 8; ++kk) {
            const int k0 = kk * 8;
            uint32_t pa[4];
            pa[0] = __float_as_uint(Pw[(size_t)r * PSTRIDE + k0 + c]);
            pa[1] = __float_as_uint(Pw[(size_t)(r + 8) * PSTRIDE + k0 + c]);
            pa[2] = __float_as_uint(Pw[(size_t)r * PSTRIDE + k0 + c + 4]);
            pa[3] = __float_as_uint(Pw[(size_t)(r + 8) * PSTRIDE + k0 + c + 4]);
#pragma unroll
            for (int nt = 0; nt < 8; ++nt) {
                const float* vp0 = vs + (size_t)(k0 + c) * VSTRIDE + nt * 8 + r;
                const float* vp1 = vs + (size_t)(k0 + c + 4) * VSTRIDE + nt * 8 + r;
                mma_tf32(oacc[nt], pa,
                         __float_as_uint(vp0[0]), __float_as_uint(vp1[0]));
            }
        }
        __syncthreads();
    }

    // ---- epilogue: normalize and store ----
    const float inv_lo = 1.0f / l_lo;
    const float inv_hi = 1.0f / l_hi;
    const size_t row_lo = (size_t)(b * Sv + i0 + wid * 16 + r);
#pragma unroll
    for (int nt = 0; nt < 8; ++nt) {
        const int col = h * DKv + nt * 8 + 2 * c;
        float2 lo, hi;
        lo.x = oacc[nt][0] * inv_lo; lo.y = oacc[nt][1] * inv_lo;
        hi.x = oacc[nt][2] * inv_hi; hi.y = oacc[nt][3] * inv_hi;
        *(float2*)(o + row_lo * Dv + col)        = lo;
        *(float2*)(o + (row_lo + 8) * Dv + col)  = hi;
    }
}

// ---------------------------------------------------------------------------
// Fused residual + LayerNorm
// ---------------------------------------------------------------------------
__global__ void __launch_bounds__(256) residual_ln(
    const float* __restrict__ a, const float* __restrict__ r,
    const float* __restrict__ g, const float* __restrict__ be,
    float* __restrict__ out)
{
    const size_t row = blockIdx.x;
    const int tid = threadIdx.x;

    const float4 va = *(const float4*)(a + row * Dv + tid * 4);
    const float4 vr = *(const float4*)(r + row * Dv + tid * 4);
    float4 x;
    x.x = va.x + vr.x; x.y = va.y + vr.y; x.z = va.z + vr.z; x.w = va.w + vr.w;

    float s  = x.x + x.y + x.z + x.w;
    float s2 = x.x * x.x + x.y * x.y + x.z * x.z + x.w * x.w;

    __shared__ float rs[8], rs2[8];
#pragma unroll
    for (int o = 16; o > 0; o >>= 1) {
        s  += __shfl_xor_sync(0xffffffffu, s,  o);
        s2 += __shfl_xor_sync(0xffffffffu, s2, o);
    }
    if ((tid & 31) == 0) { rs[tid >> 5] = s; rs2[tid >> 5] = s2; }
    __syncthreads();
    if (tid == 0) {
        float ts = 0.f, t2 = 0.f;
#pragma unroll
        for (int i = 0; i < 8; ++i) { ts += rs[i]; t2 += rs2[i]; }
        rs[0] = ts; rs2[0] = t2;
    }
    __syncthreads();

    const float mu  = rs[0] * (1.0f / Dv);
    const float var = rs2[0] * (1.0f / Dv) - mu * mu;
    const float inv = rsqrtf(var + LN_EPS);

    const float4 vg = *(const float4*)(g + tid * 4);
    const float4 vb = *(const float4*)(be + tid * 4);
    float4 o;
    o.x = (x.x - mu) * inv * vg.x + vb.x;
    o.y = (x.y - mu) * inv * vg.y + vb.y;
    o.z = (x.z - mu) * inv * vg.z + vb.z;
    o.w = (x.w - mu) * inv * vg.w + vb.w;
    *(float4*)(out + row * Dv + tid * 4) = o;
}

// ---------------------------------------------------------------------------
// Launch
// ---------------------------------------------------------------------------
extern "C" void kernel_launch(void* const* d_in, const int* in_sizes, int n_in,
                              void* d_out, int out_size)
{
    const float* x  = (const float*)d_in[0];
    const float* wq = (const float*)d_in[1];
    const float* bq = (const float*)d_in[2];
    const float* wk = (const float*)d_in[3];
    const float* bk = (const float*)d_in[4];
    const float* wv = (const float*)d_in[5];
    const float* bv = (const float*)d_in[6];
    const float* wo = (const float*)d_in[7];
    const float* bo = (const float*)d_in[8];
    const float* w1 = (const float*)d_in[9];
    const float* b1 = (const float*)d_in[10];
    const float* w2 = (const float*)d_in[11];
    const float* b2 = (const float*)d_in[12];
    const float* g1 = (const float*)d_in[13];
    const float* be1= (const float*)d_in[14];
    const float* g2 = (const float*)d_in[15];
    const float* be2= (const float*)d_in[16];
    float* out = (float*)d_out;

    float *q, *k, *v, *attn, *tmp, *h, *ff1, *wT;
    cudaGetSymbolAddress((void**)&q,    g_q);
    cudaGetSymbolAddress((void**)&k,    g_k);
    cudaGetSymbolAddress((void**)&v,    g_v);
    cudaGetSymbolAddress((void**)&attn, g_attn);
    cudaGetSymbolAddress((void**)&tmp,  g_tmp);
    cudaGetSymbolAddress((void**)&h,    g_h);
    cudaGetSymbolAddress((void**)&ff1,  g_ff1);
    cudaGetSymbolAddress((void**)&wT,   g_wT);

    const size_t MB1 = 1024 * 1024;
    float* wqT = wT + 0 * MB1;
    float* wkT = wT + 1 * MB1;
    float* wvT = wT + 2 * MB1;
    float* woT = wT + 3 * MB1;
    float* w1T = wT + 4 * MB1;   // [F, D]
    float* w2T = wT + 8 * MB1;   // [D, F]

    cudaFuncSetAttribute(gemm_mma<false>,
        cudaFuncAttributeMaxDynamicSharedMemorySize, GSMEM_BYTES);
    cudaFuncSetAttribute(gemm_mma<true>,
        cudaFuncAttributeMaxDynamicSharedMemorySize, GSMEM_BYTES);
    cudaFuncSetAttribute(flash_attn,
        cudaFuncAttributeMaxDynamicSharedMemorySize, FA_SMEM_BYTES);

    // Transpose + tf32-round weights
    dim3 tb(32, 8);
    transpose_tf32<<<dim3(Dv / 32, Dv / 32), tb>>>(wq, wqT, Dv, Dv);
    transpose_tf32<<<dim3(Dv / 32, Dv / 32), tb>>>(wk, wkT, Dv, Dv);
    transpose_tf32<<<dim3(Dv / 32, Dv / 32), tb>>>(wv, wvT, Dv, Dv);
    transpose_tf32<<<dim3(Dv / 32, Dv / 32), tb>>>(wo, woT, Dv, Dv);
    transpose_tf32<<<dim3(Fv / 32, Dv / 32), tb>>>(w1, w1T, Dv, Fv);
    transpose_tf32<<<dim3(Dv / 32, Fv / 32), tb>>>(w2, w2T, Fv, Dv);

    const dim3 gDD(Dv / 128, Mv / 128);   // (8, 32)
    const dim3 gDF(Fv / 128, Mv / 128);   // (32, 32)

    // QKV projections
    gemm_mma<false><<<gDD, 256, GSMEM_BYTES>>>(Dv, Dv, x, wqT, bq, q);
    gemm_mma<false><<<gDD, 256, GSMEM_BYTES>>>(Dv, Dv, x, wkT, bk, k);
    gemm_mma<false><<<gDD, 256, GSMEM_BYTES>>>(Dv, Dv, x, wvT, bv, v);

    // Fused flash attention
    flash_attn<<<dim3(Sv / 64, Bv * Hv), 128, FA_SMEM_BYTES>>>(q, k, v, attn);

    // Output projection + residual LN1
    gemm_mma<false><<<gDD, 256, GSMEM_BYTES>>>(Dv, Dv, attn, woT, bo, tmp);
    residual_ln<<<Mv, 256>>>(x, tmp, g1, be1, h);

    // FFN + residual LN2
    gemm_mma<true ><<<gDF, 256, GSMEM_BYTES>>>(Dv, Fv, h, w1T, b1, ff1);
    gemm_mma<false><<<gDD, 256, GSMEM_BYTES>>>(Fv, Dv, ff1, w2T, b2, tmp);
    residual_ln<<<Mv, 256>>>(h, tmp, g2, be2, out);
}

// round 5
// speedup vs baseline: 2.9400x; 1.0888x over previous
#include <cuda_runtime.h>
#include <cstdint>

// Problem constants
#define Bv   2
#define Sv   2048
#define Dv   1024
#define Hv   16
#define DKv  64
#define Fv   4096
#define Mv   (Bv * Sv)      // 4096 rows
#define QS   3072           // qkv row stride
#define LN_EPS 1e-6f

// ---------------------------------------------------------------------------
// Scratch (no cudaMalloc allowed -> __device__ globals)
// ---------------------------------------------------------------------------
__device__ float g_qkv [(size_t)Mv * QS];             // fused q|k|v
__device__ float g_xr  [(size_t)Mv * Dv];             // tf32-rounded x
__device__ float g_attn[(size_t)Mv * Dv];
__device__ float g_tmp [(size_t)Mv * Dv];
__device__ float g_h   [(size_t)Mv * Dv];
__device__ float g_ff1 [(size_t)Mv * Fv];
__device__ float g_wT  [(size_t)12 * 1024 * 1024];    // transposed tf32 weights
__device__ float g_bqkv[QS];

// ---------------------------------------------------------------------------
// Helpers
// ---------------------------------------------------------------------------
__device__ __forceinline__ uint32_t smem_u32(const void* p) {
    uint32_t a;
    asm("{ .reg .u64 t; cvta.to.shared.u64 t, %1; cvt.u32.u64 %0, t; }"
        : "=r"(a) : "l"(p));
    return a;
}
__device__ __forceinline__ float to_tf32(float x) {
    uint32_t u;
    asm("cvt.rna.tf32.f32 %0, %1;" : "=r"(u) : "f"(x));
    return __uint_as_float(u);
}
__device__ __forceinline__ uint32_t tf32u(float x) {
    uint32_t u;
    asm("cvt.rna.tf32.f32 %0, %1;" : "=r"(u) : "f"(x));
    return u;
}
__device__ __forceinline__ void mma_tf32(
    float* d, const uint32_t* a, uint32_t b0, uint32_t b1)
{
    asm volatile(
        "mma.sync.aligned.m16n8k8.row.col.f32.tf32.tf32.f32 "
        "{%0,%1,%2,%3}, {%4,%5,%6,%7}, {%8,%9}, {%0,%1,%2,%3};"
        : "+f"(d[0]), "+f"(d[1]), "+f"(d[2]), "+f"(d[3])
        : "r"(a[0]), "r"(a[1]), "r"(a[2]), "r"(a[3]), "r"(b0), "r"(b1));
}

// ---------------------------------------------------------------------------
// Weight transpose + tf32 rounding: WT[n][k] = tf32(W[k][n])
// ---------------------------------------------------------------------------
__global__ void __launch_bounds__(256) transpose_tf32(
    const float* __restrict__ W, float* __restrict__ WT, int K, int N)
{
    __shared__ float t[32][33];
    const int k0 = blockIdx.y * 32, n0 = blockIdx.x * 32;
    const int tx = threadIdx.x, ty0 = threadIdx.y;
#pragma unroll
    for (int i = 0; i < 4; ++i) {
        const int ty = ty0 + i * 8;
        t[ty][tx] = W[(size_t)(k0 + ty) * N + n0 + tx];
    }
    __syncthreads();
#pragma unroll
    for (int i = 0; i < 4; ++i) {
        const int ty = ty0 + i * 8;
        WT[(size_t)(n0 + ty) * K + k0 + tx] = to_tf32(t[tx][ty]);
    }
}

// ---------------------------------------------------------------------------
// Small prep kernels
// ---------------------------------------------------------------------------
__global__ void __launch_bounds__(256) round_x_tf32(
    const float* __restrict__ x, float* __restrict__ y)
{
    const int i = blockIdx.x * 256 + threadIdx.x;
    float4 v = ((const float4*)x)[i];
    v.x = to_tf32(v.x); v.y = to_tf32(v.y);
    v.z = to_tf32(v.z); v.w = to_tf32(v.w);
    ((float4*)y)[i] = v;
}

__global__ void __launch_bounds__(256) pack_bias(
    const float* __restrict__ bq, const float* __restrict__ bk,
    const float* __restrict__ bv, float* __restrict__ dst)
{
    const int i = blockIdx.x * 256 + threadIdx.x;
    dst[i] = (i < 1024) ? bq[i] : ((i < 2048) ? bk[i - 1024] : bv[i - 2048]);
}

// ---------------------------------------------------------------------------
// Tensor-core GEMM via mma.sync tf32.
// C[M,N] = A[M,K] @ WT[N,K]^T + bias (opt ReLU, opt A-cvt, opt out-round)
// ---------------------------------------------------------------------------
#define GBK 32
#define GSTRIDE 36
#define GSM_FLOATS (128 * GSTRIDE)
#define GSMEM_BYTES (4 * GSM_FLOATS * 4)

template <bool RELU, bool CVTA, bool CVTOUT>
__global__ void __launch_bounds__(256)
gemm_mma(int K, int N, const float* __restrict__ A,
         const float* __restrict__ WT, const float* __restrict__ bias,
         float* __restrict__ C)
{
    extern __shared__ float sm[];
    const int m0 = blockIdx.y * 128;
    const int n0 = blockIdx.x * 128;
    const int tid  = threadIdx.x;
    const int lane = tid & 31;
    const int wid  = tid >> 5;
    const int wm = (wid >> 2) * 64;
    const int wn = (wid & 3) * 32;

    float* tA[2] = { sm,                  sm + 2 * GSM_FLOATS };
    float* tB[2] = { sm + GSM_FLOATS,     sm + 3 * GSM_FLOATS };
    const uint32_t uA[2] = { smem_u32(tA[0]), smem_u32(tA[1]) };
    const uint32_t uB[2] = { smem_u32(tB[0]), smem_u32(tB[1]) };

    const float* Ab = A  + (size_t)m0 * K;
    const float* Bb = WT + (size_t)n0 * K;
    const int nk = K / GBK;

    float acc[4][4][4] = {};

    auto load_stage = [&](int buf, int kt) {
#pragma unroll
        for (int i = 0; i < 4; ++i) {
            const int s   = tid + i * 256;
            const int row = s >> 3;
            const int f   = s & 7;
            const float* ga = Ab + (size_t)row * K + kt * GBK + f * 4;
            const float* gb = Bb + (size_t)row * K + kt * GBK + f * 4;
            const uint32_t da = uA[buf] + (uint32_t)(row * (GSTRIDE * 4) + f * 16);
            const uint32_t db = uB[buf] + (uint32_t)(row * (GSTRIDE * 4) + f * 16);
            asm volatile("cp.async.cg.shared.global [%0], [%1], 16;" :: "r"(da), "l"(ga));
            asm volatile("cp.async.cg.shared.global [%0], [%1], 16;" :: "r"(db), "l"(gb));
        }
    };

    load_stage(0, 0);
    asm volatile("cp.async.commit_group;" ::: "memory");

    const int r = lane >> 2;
    const int c = lane & 3;

    for (int kt = 0; kt < nk; ++kt) {
        const int buf = kt & 1;
        if (kt + 1 < nk) load_stage(buf ^ 1, kt + 1);
        asm volatile("cp.async.commit_group;" ::: "memory");
        asm volatile("cp.async.wait_group 1;" ::: "memory");
        __syncthreads();

        const float* sa = tA[buf];
        const float* sb = tB[buf];

#pragma unroll
        for (int kk = 0; kk < 4; ++kk) {
            const int k0 = kk * 8;
            uint32_t afr[4][4];
            uint32_t bfr[4][2];
#pragma unroll
            for (int mt = 0; mt < 4; ++mt) {
                const float* base  = sa + (size_t)(wm + mt * 16 + r) * GSTRIDE + k0 + c;
                const float* base8 = base + 8 * GSTRIDE;
                if (CVTA) {
                    afr[mt][0] = tf32u(base[0]);
                    afr[mt][1] = tf32u(base8[0]);
                    afr[mt][2] = tf32u(base[4]);
                    afr[mt][3] = tf32u(base8[4]);
                } else {
                    afr[mt][0] = __float_as_uint(base[0]);
                    afr[mt][1] = __float_as_uint(base8[0]);
                    afr[mt][2] = __float_as_uint(base[4]);
                    afr[mt][3] = __float_as_uint(base8[4]);
                }
            }
#pragma unroll
            for (int nt = 0; nt < 4; ++nt) {
                const float* base = sb + (size_t)(wn + nt * 8 + r) * GSTRIDE + k0 + c;
                bfr[nt][0] = __float_as_uint(base[0]);
                bfr[nt][1] = __float_as_uint(base[4]);
            }
#pragma unroll
            for (int mt = 0; mt < 4; ++mt)
#pragma unroll
                for (int nt = 0; nt < 4; ++nt)
                    mma_tf32(acc[mt][nt], afr[mt], bfr[nt][0], bfr[nt][1]);
        }
        __syncthreads();
    }

#pragma unroll
    for (int mt = 0; mt < 4; ++mt) {
        const int rg = m0 + wm + mt * 16 + r;
#pragma unroll
        for (int nt = 0; nt < 4; ++nt) {
            const int cg = n0 + wn + nt * 8 + c * 2;
            const float b0 = bias[cg], b1 = bias[cg + 1];
            float2 v0, v1;
            v0.x = acc[mt][nt][0] + b0; v0.y = acc[mt][nt][1] + b1;
            v1.x = acc[mt][nt][2] + b0; v1.y = acc[mt][nt][3] + b1;
            if (RELU) {
                v0.x = fmaxf(v0.x, 0.f); v0.y = fmaxf(v0.y, 0.f);
                v1.x = fmaxf(v1.x, 0.f); v1.y = fmaxf(v1.y, 0.f);
            }
            if (CVTOUT) {
                v0.x = to_tf32(v0.x); v0.y = to_tf32(v0.y);
                v1.x = to_tf32(v1.x); v1.y = to_tf32(v1.y);
            }
            *(float2*)(C + (size_t)rg * N + cg)       = v0;
            *(float2*)(C + (size_t)(rg + 8) * N + cg) = v1;
        }
    }
}

// ---------------------------------------------------------------------------
// Fused flash attention (tf32 mma.sync + online softmax).
// CTA = 64 Q rows of one (b,h); 4 warps x 16 rows; 32 KV tiles of 64,
// cp.async double-buffered. P tile ALIASES K[buf] (K fully consumed before
// P is written; guarded by __syncthreads). q/k/v pre-rounded tf32, fused
// layout with row stride QS=3072.
// ---------------------------------------------------------------------------
#define KSTRIDE 68
#define VSTRIDE 72
#define FA_SMEM_FLOATS (2*64*KSTRIDE + 2*64*VSTRIDE)
#define FA_SMEM_BYTES  (FA_SMEM_FLOATS * 4)   // 71680

__global__ void __launch_bounds__(128)
flash_attn(const float* __restrict__ qkv, float* __restrict__ o)
{
    extern __shared__ float sm[];
    float* Kt[2] = { sm, sm + 64 * KSTRIDE };
    float* Vt[2] = { sm + 2*64*KSTRIDE, sm + 2*64*KSTRIDE + 64*VSTRIDE };

    const int bh = blockIdx.y;
    const int b  = bh >> 4;
    const int h  = bh & 15;
    const int i0 = blockIdx.x * 64;

    const int tid  = threadIdx.x;
    const int lane = tid & 31;
    const int wid  = tid >> 5;
    const int r = lane >> 2;
    const int c = lane & 3;

    const uint32_t uK[2] = { smem_u32(Kt[0]), smem_u32(Kt[1]) };
    const uint32_t uV[2] = { smem_u32(Vt[0]), smem_u32(Vt[1]) };

    // Q fragments: pre-rounded tf32; 0.125 scale is exact in tf32.
    uint32_t qa[8][4];
    {
        const float* qb = qkv + (size_t)(b * Sv + i0 + wid * 16) * QS + h * DKv;
#pragma unroll
        for (int kk = 0; kk < 8; ++kk) {
            const int col = kk * 8 + c;
            qa[kk][0] = __float_as_uint(0.125f * qb[(size_t)r * QS + col]);
            qa[kk][1] = __float_as_uint(0.125f * qb[(size_t)(r + 8) * QS + col]);
            qa[kk][2] = __float_as_uint(0.125f * qb[(size_t)r * QS + col + 4]);
            qa[kk][3] = __float_as_uint(0.125f * qb[(size_t)(r + 8) * QS + col + 4]);
        }
    }

    float oacc[8][4] = {};
    float m_lo = -1e30f, m_hi = -1e30f;
    float l_lo = 0.f,    l_hi = 0.f;

    auto load_kv = [&](int buf, int jt) {
        const float* kb = qkv + (size_t)(b * Sv + jt * 64) * QS + 1024 + h * DKv;
        const float* vb = qkv + (size_t)(b * Sv + jt * 64) * QS + 2048 + h * DKv;
#pragma unroll
        for (int i = 0; i < 8; ++i) {
            const int s   = tid + i * 128;   // 0..1023
            const int row = s >> 4;
            const int f   = s & 15;
            const uint32_t dk_ = uK[buf] + (uint32_t)(row * (KSTRIDE * 4) + f * 16);
            const uint32_t dv_ = uV[buf] + (uint32_t)(row * (VSTRIDE * 4) + f * 16);
            asm volatile("cp.async.cg.shared.global [%0], [%1], 16;"
                         :: "r"(dk_), "l"(kb + (size_t)row * QS + f * 4));
            asm volatile("cp.async.cg.shared.global [%0], [%1], 16;"
                         :: "r"(dv_), "l"(vb + (size_t)row * QS + f * 4));
        }
    };

    load_kv(0, 0);
    asm volatile("cp.async.commit_group;" ::: "memory");

    const int NT = Sv / 64;   // 32 KV tiles
    for (int jt = 0; jt < NT; ++jt) {
        const int buf = jt & 1;
        if (jt + 1 < NT) load_kv(buf ^ 1, jt + 1);
        asm volatile("cp.async.commit_group;" ::: "memory");
        asm volatile("cp.async.wait_group 1;" ::: "memory");
        __syncthreads();   // K/V[buf] ready; all prior P reads completed

        const float* ks = Kt[buf];
        const float* vs = Vt[buf];
        float* Pw = Kt[buf] + wid * 16 * KSTRIDE;   // P aliases K[buf]

        // ---- S = Q K^T (pre-scaled) ----
        float sacc[8][4] = {};
#pragma unroll
        for (int kk = 0; kk < 8; ++kk) {
            const int k0 = kk * 8;
#pragma unroll
            for (int nt = 0; nt < 8; ++nt) {
                const float* kp = ks + (size_t)(nt * 8 + r) * KSTRIDE + k0 + c;
                mma_tf32(sacc[nt], qa[kk],
                         __float_as_uint(kp[0]), __float_as_uint(kp[4]));
            }
        }
        __syncthreads();   // all warps done reading K[buf] before P overwrite

        // ---- online softmax ----
        float tmx_lo = -1e30f, tmx_hi = -1e30f;
#pragma unroll
        for (int nt = 0; nt < 8; ++nt) {
            tmx_lo = fmaxf(tmx_lo, fmaxf(sacc[nt][0], sacc[nt][1]));
            tmx_hi = fmaxf(tmx_hi, fmaxf(sacc[nt][2], sacc[nt][3]));
        }
        tmx_lo = fmaxf(tmx_lo, __shfl_xor_sync(0xffffffffu, tmx_lo, 1));
        tmx_lo = fmaxf(tmx_lo, __shfl_xor_sync(0xffffffffu, tmx_lo, 2));
        tmx_hi = fmaxf(tmx_hi, __shfl_xor_sync(0xffffffffu, tmx_hi, 1));
        tmx_hi = fmaxf(tmx_hi, __shfl_xor_sync(0xffffffffu, tmx_hi, 2));

        const float mn_lo = fmaxf(m_lo, tmx_lo);
        const float mn_hi = fmaxf(m_hi, tmx_hi);
        const float cor_lo = __expf(m_lo - mn_lo);
        const float cor_hi = __expf(m_hi - mn_hi);

        float sum_lo = 0.f, sum_hi = 0.f;
#pragma unroll
        for (int nt = 0; nt < 8; ++nt) {
            const float p0 = __expf(sacc[nt][0] - mn_lo);
            const float p1 = __expf(sacc[nt][1] - mn_lo);
            const float p2 = __expf(sacc[nt][2] - mn_hi);
            const float p3 = __expf(sacc[nt][3] - mn_hi);
            sum_lo += p0 + p1;
            sum_hi += p2 + p3;
            float2 plo, phi;
            plo.x = to_tf32(p0); plo.y = to_tf32(p1);
            phi.x = to_tf32(p2); phi.y = to_tf32(p3);
            *(float2*)(Pw + (size_t)r * KSTRIDE + nt * 8 + 2 * c)       = plo;
            *(float2*)(Pw + (size_t)(r + 8) * KSTRIDE + nt * 8 + 2 * c) = phi;
            oacc[nt][0] *= cor_lo; oacc[nt][1] *= cor_lo;
            oacc[nt][2] *= cor_hi; oacc[nt][3] *= cor_hi;
        }
        sum_lo += __shfl_xor_sync(0xffffffffu, sum_lo, 1);
        sum_lo += __shfl_xor_sync(0xffffffffu, sum_lo, 2);
        sum_hi += __shfl_xor_sync(0xffffffffu, sum_hi, 1);
        sum_hi += __shfl_xor_sync(0xffffffffu, sum_hi, 2);

        l_lo = l_lo * cor_lo + sum_lo;
        l_hi = l_hi * cor_hi + sum_hi;
        m_lo = mn_lo;
        m_hi = mn_hi;

        __syncwarp();

        // ---- O += P V ----
#pragma unroll
        for (int kk = 0; kk < 8; ++kk) {
            const int k0 = kk * 8;
            uint32_t pa[4];
            pa[0] = __float_as_uint(Pw[(size_t)r * KSTRIDE + k0 + c]);
            pa[1] = __float_as_uint(Pw[(size_t)(r + 8) * KSTRIDE + k0 + c]);
            pa[2] = __float_as_uint(Pw[(size_t)r * KSTRIDE + k0 + c + 4]);
            pa[3] = __float_as_uint(Pw[(size_t)(r + 8) * KSTRIDE + k0 + c + 4]);
#pragma unroll
            for (int nt = 0; nt < 8; ++nt) {
                const float* vp0 = vs + (size_t)(k0 + c) * VSTRIDE + nt * 8 + r;
                const float* vp1 = vs + (size_t)(k0 + c + 4) * VSTRIDE + nt * 8 + r;
                mma_tf32(oacc[nt], pa,
                         __float_as_uint(vp0[0]), __float_as_uint(vp1[0]));
            }
        }
        __syncthreads();   // all P reads done before next cp.async overwrites K[buf]
    }

    // ---- epilogue: normalize, round to tf32, store ----
    const float inv_lo = 1.0f / l_lo;
    const float inv_hi = 1.0f / l_hi;
    const size_t row_lo = (size_t)(b * Sv + i0 + wid * 16 + r);
#pragma unroll
    for (int nt = 0; nt < 8; ++nt) {
        const int col = h * DKv + nt * 8 + 2 * c;
        float2 lo, hi;
        lo.x = to_tf32(oacc[nt][0] * inv_lo); lo.y = to_tf32(oacc[nt][1] * inv_lo);
        hi.x = to_tf32(oacc[nt][2] * inv_hi); hi.y = to_tf32(oacc[nt][3] * inv_hi);
        *(float2*)(o + row_lo * Dv + col)        = lo;
        *(float2*)(o + (row_lo + 8) * Dv + col)  = hi;
    }
}

// ---------------------------------------------------------------------------
// Fused residual + LayerNorm
// ---------------------------------------------------------------------------
__global__ void __launch_bounds__(256) residual_ln(
    const float* __restrict__ a, const float* __restrict__ r,
    const float* __restrict__ g, const float* __restrict__ be,
    float* __restrict__ out)
{
    const size_t row = blockIdx.x;
    const int tid = threadIdx.x;

    const float4 va = *(const float4*)(a + row * Dv + tid * 4);
    const float4 vr = *(const float4*)(r + row * Dv + tid * 4);
    float4 x;
    x.x = va.x + vr.x; x.y = va.y + vr.y; x.z = va.z + vr.z; x.w = va.w + vr.w;

    float s  = x.x + x.y + x.z + x.w;
    float s2 = x.x * x.x + x.y * x.y + x.z * x.z + x.w * x.w;

    __shared__ float rs[8], rs2[8];
#pragma unroll
    for (int o = 16; o > 0; o >>= 1) {
        s  += __shfl_xor_sync(0xffffffffu, s,  o);
        s2 += __shfl_xor_sync(0xffffffffu, s2, o);
    }
    if ((tid & 31) == 0) { rs[tid >> 5] = s; rs2[tid >> 5] = s2; }
    __syncthreads();
    if (tid == 0) {
        float ts = 0.f, t2 = 0.f;
#pragma unroll
        for (int i = 0; i < 8; ++i) { ts += rs[i]; t2 += rs2[i]; }
        rs[0] = ts; rs2[0] = t2;
    }
    __syncthreads();

    const float mu  = rs[0] * (1.0f / Dv);
    const float var = rs2[0] * (1.0f / Dv) - mu * mu;
    const float inv = rsqrtf(var + LN_EPS);

    const float4 vg = *(const float4*)(g + tid * 4);
    const float4 vb = *(const float4*)(be + tid * 4);
    float4 o;
    o.x = (x.x - mu) * inv * vg.x + vb.x;
    o.y = (x.y - mu) * inv * vg.y + vb.y;
    o.z = (x.z - mu) * inv * vg.z + vb.z;
    o.w = (x.w - mu) * inv * vg.w + vb.w;
    *(float4*)(out + row * Dv + tid * 4) = o;
}

// ---------------------------------------------------------------------------
// Launch
// ---------------------------------------------------------------------------
extern "C" void kernel_launch(void* const* d_in, const int* in_sizes, int n_in,
                              void* d_out, int out_size)
{
    const float* x  = (const float*)d_in[0];
    const float* wq = (const float*)d_in[1];
    const float* bq = (const float*)d_in[2];
    const float* wk = (const float*)d_in[3];
    const float* bk = (const float*)d_in[4];
    const float* wv = (const float*)d_in[5];
    const float* bv = (const float*)d_in[6];
    const float* wo = (const float*)d_in[7];
    const float* bo = (const float*)d_in[8];
    const float* w1 = (const float*)d_in[9];
    const float* b1 = (const float*)d_in[10];
    const float* w2 = (const float*)d_in[11];
    const float* b2 = (const float*)d_in[12];
    const float* g1 = (const float*)d_in[13];
    const float* be1= (const float*)d_in[14];
    const float* g2 = (const float*)d_in[15];
    const float* be2= (const float*)d_in[16];
    float* out = (float*)d_out;

    float *qkv, *xr, *attn, *tmp, *h, *ff1, *wT, *bqkv;
    cudaGetSymbolAddress((void**)&qkv,  g_qkv);
    cudaGetSymbolAddress((void**)&xr,   g_xr);
    cudaGetSymbolAddress((void**)&attn, g_attn);
    cudaGetSymbolAddress((void**)&tmp,  g_tmp);
    cudaGetSymbolAddress((void**)&h,    g_h);
    cudaGetSymbolAddress((void**)&ff1,  g_ff1);
    cudaGetSymbolAddress((void**)&wT,   g_wT);
    cudaGetSymbolAddress((void**)&bqkv, g_bqkv);

    const size_t MB1 = 1024 * 1024;
    float* wqkvT = wT;               // [3072][1024] (q|k|v stacked)
    float* woT   = wT + 3 * MB1;
    float* w1T   = wT + 4 * MB1;     // [F, D]
    float* w2T   = wT + 8 * MB1;     // [D, F]

    cudaFuncSetAttribute(gemm_mma<false, false, true>,
        cudaFuncAttributeMaxDynamicSharedMemorySize, GSMEM_BYTES);
    cudaFuncSetAttribute(gemm_mma<false, false, false>,
        cudaFuncAttributeMaxDynamicSharedMemorySize, GSMEM_BYTES);
    cudaFuncSetAttribute(gemm_mma<true, true, true>,
        cudaFuncAttributeMaxDynamicSharedMemorySize, GSMEM_BYTES);
    cudaFuncSetAttribute(flash_attn,
        cudaFuncAttributeMaxDynamicSharedMemorySize, FA_SMEM_BYTES);

    // Weight prep
    dim3 tb(32, 8);
    transpose_tf32<<<dim3(Dv / 32, Dv / 32), tb>>>(wq, wT + 0 * MB1, Dv, Dv);
    transpose_tf32<<<dim3(Dv / 32, Dv / 32), tb>>>(wk, wT + 1 * MB1, Dv, Dv);
    transpose_tf32<<<dim3(Dv / 32, Dv / 32), tb>>>(wv, wT + 2 * MB1, Dv, Dv);
    transpose_tf32<<<dim3(Dv / 32, Dv / 32), tb>>>(wo, woT, Dv, Dv);
    transpose_tf32<<<dim3(Fv / 32, Dv / 32), tb>>>(w1, w1T, Dv, Fv);
    transpose_tf32<<<dim3(Dv / 32, Fv / 32), tb>>>(w2, w2T, Fv, Dv);
    pack_bias<<<QS / 256, 256>>>(bq, bk, bv, bqkv);
    round_x_tf32<<<(Mv * Dv / 4) / 256, 256>>>(x, xr);

    // Fused QKV projection: [4096,1024] @ [1024,3072] -> qkv
    gemm_mma<false, false, true><<<dim3(QS / 128, Mv / 128), 256, GSMEM_BYTES>>>(
        Dv, QS, xr, wqkvT, bqkv, qkv);

    // Fused flash attention (q/k/v tf32, fused layout)
    flash_attn<<<dim3(Sv / 64, Bv * Hv), 128, FA_SMEM_BYTES>>>(qkv, attn);

    const dim3 gDD(Dv / 128, Mv / 128);   // (8, 32)
    const dim3 gDF(Fv / 128, Mv / 128);   // (32, 32)

    // Output projection + residual LN1
    gemm_mma<false, false, false><<<gDD, 256, GSMEM_BYTES>>>(Dv, Dv, attn, woT, bo, tmp);
    residual_ln<<<Mv, 256>>>(x, tmp, g1, be1, h);

    // FFN + residual LN2
    gemm_mma<true, true, true><<<gDF, 256, GSMEM_BYTES>>>(Dv, Fv, h, w1T, b1, ff1);
    gemm_mma<false, false, false><<<gDD, 256, GSMEM_BYTES>>>(Fv, Dv, ff1, w2T, b2, tmp);
    residual_ln<<<Mv, 256>>>(h, tmp, g2, be2, out);
}

// round 6
// speedup vs baseline: 3.7199x; 1.2653x over previous
#include <cuda_runtime.h>
#include <cstdint>

// Problem constants
#define Bv   2
#define Sv   2048
#define Dv   1024
#define Hv   16
#define DKv  64
#define Fv   4096
#define Mv   (Bv * Sv)      // 4096 rows
#define QS   3072           // qkv row stride
#define LN_EPS 1e-6f

// ---------------------------------------------------------------------------
// Scratch (no cudaMalloc allowed -> __device__ globals)
// ---------------------------------------------------------------------------
__device__ float g_qkv [(size_t)Mv * QS];             // fused q|k|v
__device__ float g_xr  [(size_t)Mv * Dv];             // tf32-rounded x
__device__ float g_attn[(size_t)Mv * Dv];
__device__ float g_tmp [(size_t)Mv * Dv];
__device__ float g_h   [(size_t)Mv * Dv];
__device__ float g_ff1 [(size_t)Mv * Fv];
__device__ float g_wT  [(size_t)12 * 1024 * 1024];    // transposed tf32 weights
__device__ float g_bqkv[QS];

// ---------------------------------------------------------------------------
// Helpers
// ---------------------------------------------------------------------------
__device__ __forceinline__ uint32_t smem_u32(const void* p) {
    uint32_t a;
    asm("{ .reg .u64 t; cvta.to.shared.u64 t, %1; cvt.u32.u64 %0, t; }"
        : "=r"(a) : "l"(p));
    return a;
}
__device__ __forceinline__ float to_tf32(float x) {
    uint32_t u;
    asm("cvt.rna.tf32.f32 %0, %1;" : "=r"(u) : "f"(x));
    return __uint_as_float(u);
}
__device__ __forceinline__ uint32_t tf32u(float x) {
    uint32_t u;
    asm("cvt.rna.tf32.f32 %0, %1;" : "=r"(u) : "f"(x));
    return u;
}
__device__ __forceinline__ void mma_tf32(
    float* d, const uint32_t* a, uint32_t b0, uint32_t b1)
{
    asm volatile(
        "mma.sync.aligned.m16n8k8.row.col.f32.tf32.tf32.f32 "
        "{%0,%1,%2,%3}, {%4,%5,%6,%7}, {%8,%9}, {%0,%1,%2,%3};"
        : "+f"(d[0]), "+f"(d[1]), "+f"(d[2]), "+f"(d[3])
        : "r"(a[0]), "r"(a[1]), "r"(a[2]), "r"(a[3]), "r"(b0), "r"(b1));
}

// ---------------------------------------------------------------------------
// Batched weight transpose + tf32 rounding for the 4 DxD matrices.
// WT[n][k] = tf32(W[k][n]); blockIdx.z selects the matrix.
// ---------------------------------------------------------------------------
__global__ void __launch_bounds__(256) transpose4_tf32(
    const float* __restrict__ w0, const float* __restrict__ w1,
    const float* __restrict__ w2, const float* __restrict__ w3,
    float* __restrict__ dst)   // 4 x [1024][1024] stacked
{
    const float* srcs[4] = { w0, w1, w2, w3 };
    const float* W = srcs[blockIdx.z];
    float* WT = dst + (size_t)blockIdx.z * Dv * Dv;

    __shared__ float t[32][33];
    const int k0 = blockIdx.y * 32, n0 = blockIdx.x * 32;
    const int tx = threadIdx.x, ty0 = threadIdx.y;
#pragma unroll
    for (int i = 0; i < 4; ++i) {
        const int ty = ty0 + i * 8;
        t[ty][tx] = W[(size_t)(k0 + ty) * Dv + n0 + tx];
    }
    __syncthreads();
#pragma unroll
    for (int i = 0; i < 4; ++i) {
        const int ty = ty0 + i * 8;
        WT[(size_t)(n0 + ty) * Dv + k0 + tx] = to_tf32(t[tx][ty]);
    }
}

__global__ void __launch_bounds__(256) transpose_tf32(
    const float* __restrict__ W, float* __restrict__ WT, int K, int N)
{
    __shared__ float t[32][33];
    const int k0 = blockIdx.y * 32, n0 = blockIdx.x * 32;
    const int tx = threadIdx.x, ty0 = threadIdx.y;
#pragma unroll
    for (int i = 0; i < 4; ++i) {
        const int ty = ty0 + i * 8;
        t[ty][tx] = W[(size_t)(k0 + ty) * N + n0 + tx];
    }
    __syncthreads();
#pragma unroll
    for (int i = 0; i < 4; ++i) {
        const int ty = ty0 + i * 8;
        WT[(size_t)(n0 + ty) * K + k0 + tx] = to_tf32(t[tx][ty]);
    }
}

// ---------------------------------------------------------------------------
// Small prep kernels
// ---------------------------------------------------------------------------
__global__ void __launch_bounds__(256) round_x_tf32(
    const float* __restrict__ x, float* __restrict__ y)
{
    const int i = blockIdx.x * 256 + threadIdx.x;
    float4 v = ((const float4*)x)[i];
    v.x = to_tf32(v.x); v.y = to_tf32(v.y);
    v.z = to_tf32(v.z); v.w = to_tf32(v.w);
    ((float4*)y)[i] = v;
}

__global__ void __launch_bounds__(256) pack_bias(
    const float* __restrict__ bq, const float* __restrict__ bk,
    const float* __restrict__ bv, float* __restrict__ dst)
{
    const int i = blockIdx.x * 256 + threadIdx.x;
    dst[i] = (i < 1024) ? bq[i] : ((i < 2048) ? bk[i - 1024] : bv[i - 2048]);
}

// ---------------------------------------------------------------------------
// Tensor-core GEMM via mma.sync tf32.
// C[M,N] = A[M,K] @ WT[N,K]^T + bias (opt ReLU, opt A-cvt, opt out-round)
// 128 threads = 4 warps in 2x2 grid of 64x64 warp tiles (CTA tile 128x128).
// BK=32, 2-stage cp.async. LDS:MMA ratio = 1.0 (32 LDS / 32 MMA per kk-step).
// ---------------------------------------------------------------------------
#define GBK 32
#define GSTRIDE 36
#define GSM_FLOATS (128 * GSTRIDE)
#define GSMEM_BYTES (4 * GSM_FLOATS * 4)   // 73728

template <bool RELU, bool CVTA, bool CVTOUT>
__global__ void __launch_bounds__(128)
gemm_mma(int K, int N, const float* __restrict__ A,
         const float* __restrict__ WT, const float* __restrict__ bias,
         float* __restrict__ C)
{
    extern __shared__ float sm[];
    const int m0 = blockIdx.y * 128;
    const int n0 = blockIdx.x * 128;
    const int tid  = threadIdx.x;
    const int lane = tid & 31;
    const int wid  = tid >> 5;
    const int wm = (wid >> 1) * 64;   // warp row offset (0/64)
    const int wn = (wid & 1) * 64;    // warp col offset (0/64)

    float* tA[2] = { sm,                  sm + 2 * GSM_FLOATS };
    float* tB[2] = { sm + GSM_FLOATS,     sm + 3 * GSM_FLOATS };
    const uint32_t uA[2] = { smem_u32(tA[0]), smem_u32(tA[1]) };
    const uint32_t uB[2] = { smem_u32(tB[0]), smem_u32(tB[1]) };

    const float* Ab = A  + (size_t)m0 * K;
    const float* Bb = WT + (size_t)n0 * K;
    const int nk = K / GBK;

    float acc[4][8][4] = {};   // mt x nt x frag

    auto load_stage = [&](int buf, int kt) {
#pragma unroll
        for (int i = 0; i < 8; ++i) {
            const int s   = tid + i * 128;     // 0..1023
            const int row = s >> 3;
            const int f   = s & 7;
            const float* ga = Ab + (size_t)row * K + kt * GBK + f * 4;
            const float* gb = Bb + (size_t)row * K + kt * GBK + f * 4;
            const uint32_t da = uA[buf] + (uint32_t)(row * (GSTRIDE * 4) + f * 16);
            const uint32_t db = uB[buf] + (uint32_t)(row * (GSTRIDE * 4) + f * 16);
            asm volatile("cp.async.cg.shared.global [%0], [%1], 16;" :: "r"(da), "l"(ga));
            asm volatile("cp.async.cg.shared.global [%0], [%1], 16;" :: "r"(db), "l"(gb));
        }
    };

    load_stage(0, 0);
    asm volatile("cp.async.commit_group;" ::: "memory");

    const int r = lane >> 2;
    const int c = lane & 3;

    for (int kt = 0; kt < nk; ++kt) {
        const int buf = kt & 1;
        if (kt + 1 < nk) load_stage(buf ^ 1, kt + 1);
        asm volatile("cp.async.commit_group;" ::: "memory");
        asm volatile("cp.async.wait_group 1;" ::: "memory");
        __syncthreads();

        const float* sa = tA[buf];
        const float* sb = tB[buf];

#pragma unroll
        for (int kk = 0; kk < 4; ++kk) {
            const int k0 = kk * 8;
            uint32_t afr[4][4];
            uint32_t bfr[8][2];
#pragma unroll
            for (int mt = 0; mt < 4; ++mt) {
                const float* base  = sa + (size_t)(wm + mt * 16 + r) * GSTRIDE + k0 + c;
                const float* base8 = base + 8 * GSTRIDE;
                if (CVTA) {
                    afr[mt][0] = tf32u(base[0]);
                    afr[mt][1] = tf32u(base8[0]);
                    afr[mt][2] = tf32u(base[4]);
                    afr[mt][3] = tf32u(base8[4]);
                } else {
                    afr[mt][0] = __float_as_uint(base[0]);
                    afr[mt][1] = __float_as_uint(base8[0]);
                    afr[mt][2] = __float_as_uint(base[4]);
                    afr[mt][3] = __float_as_uint(base8[4]);
                }
            }
#pragma unroll
            for (int nt = 0; nt < 8; ++nt) {
                const float* base = sb + (size_t)(wn + nt * 8 + r) * GSTRIDE + k0 + c;
                bfr[nt][0] = __float_as_uint(base[0]);
                bfr[nt][1] = __float_as_uint(base[4]);
            }
#pragma unroll
            for (int mt = 0; mt < 4; ++mt)
#pragma unroll
                for (int nt = 0; nt < 8; ++nt)
                    mma_tf32(acc[mt][nt], afr[mt], bfr[nt][0], bfr[nt][1]);
        }
        __syncthreads();
    }

#pragma unroll
    for (int mt = 0; mt < 4; ++mt) {
        const int rg = m0 + wm + mt * 16 + r;
#pragma unroll
        for (int nt = 0; nt < 8; ++nt) {
            const int cg = n0 + wn + nt * 8 + c * 2;
            const float b0 = bias[cg], b1 = bias[cg + 1];
            float2 v0, v1;
            v0.x = acc[mt][nt][0] + b0; v0.y = acc[mt][nt][1] + b1;
            v1.x = acc[mt][nt][2] + b0; v1.y = acc[mt][nt][3] + b1;
            if (RELU) {
                v0.x = fmaxf(v0.x, 0.f); v0.y = fmaxf(v0.y, 0.f);
                v1.x = fmaxf(v1.x, 0.f); v1.y = fmaxf(v1.y, 0.f);
            }
            if (CVTOUT) {
                v0.x = to_tf32(v0.x); v0.y = to_tf32(v0.y);
                v1.x = to_tf32(v1.x); v1.y = to_tf32(v1.y);
            }
            *(float2*)(C + (size_t)rg * N + cg)       = v0;
            *(float2*)(C + (size_t)(rg + 8) * N + cg) = v1;
        }
    }
}

// ---------------------------------------------------------------------------
// Fused flash attention (tf32 mma.sync + online softmax).
// CTA = 64 Q rows of one (b,h); 4 warps x 16 rows; 32 KV tiles of 64,
// cp.async double-buffered. P tile ALIASES K[buf].
// ---------------------------------------------------------------------------
#define KSTRIDE 68
#define VSTRIDE 72
#define FA_SMEM_FLOATS (2*64*KSTRIDE + 2*64*VSTRIDE)
#define FA_SMEM_BYTES  (FA_SMEM_FLOATS * 4)   // 71680

__global__ void __launch_bounds__(128)
flash_attn(const float* __restrict__ qkv, float* __restrict__ o)
{
    extern __shared__ float sm[];
    float* Kt[2] = { sm, sm + 64 * KSTRIDE };
    float* Vt[2] = { sm + 2*64*KSTRIDE, sm + 2*64*KSTRIDE + 64*VSTRIDE };

    const int bh = blockIdx.y;
    const int b  = bh >> 4;
    const int h  = bh & 15;
    const int i0 = blockIdx.x * 64;

    const int tid  = threadIdx.x;
    const int lane = tid & 31;
    const int wid  = tid >> 5;
    const int r = lane >> 2;
    const int c = lane & 3;

    const uint32_t uK[2] = { smem_u32(Kt[0]), smem_u32(Kt[1]) };
    const uint32_t uV[2] = { smem_u32(Vt[0]), smem_u32(Vt[1]) };

    uint32_t qa[8][4];
    {
        const float* qb = qkv + (size_t)(b * Sv + i0 + wid * 16) * QS + h * DKv;
#pragma unroll
        for (int kk = 0; kk < 8; ++kk) {
            const int col = kk * 8 + c;
            qa[kk][0] = __float_as_uint(0.125f * qb[(size_t)r * QS + col]);
            qa[kk][1] = __float_as_uint(0.125f * qb[(size_t)(r + 8) * QS + col]);
            qa[kk][2] = __float_as_uint(0.125f * qb[(size_t)r * QS + col + 4]);
            qa[kk][3] = __float_as_uint(0.125f * qb[(size_t)(r + 8) * QS + col + 4]);
        }
    }

    float oacc[8][4] = {};
    float m_lo = -1e30f, m_hi = -1e30f;
    float l_lo = 0.f,    l_hi = 0.f;

    auto load_kv = [&](int buf, int jt) {
        const float* kb = qkv + (size_t)(b * Sv + jt * 64) * QS + 1024 + h * DKv;
        const float* vb = qkv + (size_t)(b * Sv + jt * 64) * QS + 2048 + h * DKv;
#pragma unroll
        for (int i = 0; i < 8; ++i) {
            const int s   = tid + i * 128;
            const int row = s >> 4;
            const int f   = s & 15;
            const uint32_t dk_ = uK[buf] + (uint32_t)(row * (KSTRIDE * 4) + f * 16);
            const uint32_t dv_ = uV[buf] + (uint32_t)(row * (VSTRIDE * 4) + f * 16);
            asm volatile("cp.async.cg.shared.global [%0], [%1], 16;"
                         :: "r"(dk_), "l"(kb + (size_t)row * QS + f * 4));
            asm volatile("cp.async.cg.shared.global [%0], [%1], 16;"
                         :: "r"(dv_), "l"(vb + (size_t)row * QS + f * 4));
        }
    };

    load_kv(0, 0);
    asm volatile("cp.async.commit_group;" ::: "memory");

    const int NT = Sv / 64;
    for (int jt = 0; jt < NT; ++jt) {
        const int buf = jt & 1;
        if (jt + 1 < NT) load_kv(buf ^ 1, jt + 1);
        asm volatile("cp.async.commit_group;" ::: "memory");
        asm volatile("cp.async.wait_group 1;" ::: "memory");
        __syncthreads();

        const float* ks = Kt[buf];
        const float* vs = Vt[buf];
        float* Pw = Kt[buf] + wid * 16 * KSTRIDE;

        float sacc[8][4] = {};
#pragma unroll
        for (int kk = 0; kk < 8; ++kk) {
            const int k0 = kk * 8;
#pragma unroll
            for (int nt = 0; nt < 8; ++nt) {
                const float* kp = ks + (size_t)(nt * 8 + r) * KSTRIDE + k0 + c;
                mma_tf32(sacc[nt], qa[kk],
                         __float_as_uint(kp[0]), __float_as_uint(kp[4]));
            }
        }
        __syncthreads();

        float tmx_lo = -1e30f, tmx_hi = -1e30f;
#pragma unroll
        for (int nt = 0; nt < 8; ++nt) {
            tmx_lo = fmaxf(tmx_lo, fmaxf(sacc[nt][0], sacc[nt][1]));
            tmx_hi = fmaxf(tmx_hi, fmaxf(sacc[nt][2], sacc[nt][3]));
        }
        tmx_lo = fmaxf(tmx_lo, __shfl_xor_sync(0xffffffffu, tmx_lo, 1));
        tmx_lo = fmaxf(tmx_lo, __shfl_xor_sync(0xffffffffu, tmx_lo, 2));
        tmx_hi = fmaxf(tmx_hi, __shfl_xor_sync(0xffffffffu, tmx_hi, 1));
        tmx_hi = fmaxf(tmx_hi, __shfl_xor_sync(0xffffffffu, tmx_hi, 2));

        const float mn_lo = fmaxf(m_lo, tmx_lo);
        const float mn_hi = fmaxf(m_hi, tmx_hi);
        const float cor_lo = __expf(m_lo - mn_lo);
        const float cor_hi = __expf(m_hi - mn_hi);

        float sum_lo = 0.f, sum_hi = 0.f;
#pragma unroll
        for (int nt = 0; nt < 8; ++nt) {
            const float p0 = __expf(sacc[nt][0] - mn_lo);
            const float p1 = __expf(sacc[nt][1] - mn_lo);
            const float p2 = __expf(sacc[nt][2] - mn_hi);
            const float p3 = __expf(sacc[nt][3] - mn_hi);
            sum_lo += p0 + p1;
            sum_hi += p2 + p3;
            float2 plo, phi;
            plo.x = to_tf32(p0); plo.y = to_tf32(p1);
            phi.x = to_tf32(p2); phi.y = to_tf32(p3);
            *(float2*)(Pw + (size_t)r * KSTRIDE + nt * 8 + 2 * c)       = plo;
            *(float2*)(Pw + (size_t)(r + 8) * KSTRIDE + nt * 8 + 2 * c) = phi;
            oacc[nt][0] *= cor_lo; oacc[nt][1] *= cor_lo;
            oacc[nt][2] *= cor_hi; oacc[nt][3] *= cor_hi;
        }
        sum_lo += __shfl_xor_sync(0xffffffffu, sum_lo, 1);
        sum_lo += __shfl_xor_sync(0xffffffffu, sum_lo, 2);
        sum_hi += __shfl_xor_sync(0xffffffffu, sum_hi, 1);
        sum_hi += __shfl_xor_sync(0xffffffffu, sum_hi, 2);

        l_lo = l_lo * cor_lo + sum_lo;
        l_hi = l_hi * cor_hi + sum_hi;
        m_lo = mn_lo;
        m_hi = mn_hi;

        __syncwarp();

#pragma unroll
        for (int kk = 0; kk < 8; ++kk) {
            const int k0 = kk * 8;
            uint32_t pa[4];
            pa[0] = __float_as_uint(Pw[(size_t)r * KSTRIDE + k0 + c]);
            pa[1] = __float_as_uint(Pw[(size_t)(r + 8) * KSTRIDE + k0 + c]);
            pa[2] = __float_as_uint(Pw[(size_t)r * KSTRIDE + k0 + c + 4]);
            pa[3] = __float_as_uint(Pw[(size_t)(r + 8) * KSTRIDE + k0 + c + 4]);
#pragma unroll
            for (int nt = 0; nt < 8; ++nt) {
                const float* vp0 = vs + (size_t)(k0 + c) * VSTRIDE + nt * 8 + r;
                const float* vp1 = vs + (size_t)(k0 + c + 4) * VSTRIDE + nt * 8 + r;
                mma_tf32(oacc[nt], pa,
                         __float_as_uint(vp0[0]), __float_as_uint(vp1[0]));
            }
        }
        __syncthreads();
    }

    const float inv_lo = 1.0f / l_lo;
    const float inv_hi = 1.0f / l_hi;
    const size_t row_lo = (size_t)(b * Sv + i0 + wid * 16 + r);
#pragma unroll
    for (int nt = 0; nt < 8; ++nt) {
        const int col = h * DKv + nt * 8 + 2 * c;
        float2 lo, hi;
        lo.x = to_tf32(oacc[nt][0] * inv_lo); lo.y = to_tf32(oacc[nt][1] * inv_lo);
        hi.x = to_tf32(oacc[nt][2] * inv_hi); hi.y = to_tf32(oacc[nt][3] * inv_hi);
        *(float2*)(o + row_lo * Dv + col)        = lo;
        *(float2*)(o + (row_lo + 8) * Dv + col)  = hi;
    }
}

// ---------------------------------------------------------------------------
// Fused residual + LayerNorm
// ---------------------------------------------------------------------------
__global__ void __launch_bounds__(256) residual_ln(
    const float* __restrict__ a, const float* __restrict__ r,
    const float* __restrict__ g, const float* __restrict__ be,
    float* __restrict__ out)
{
    const size_t row = blockIdx.x;
    const int tid = threadIdx.x;

    const float4 va = *(const float4*)(a + row * Dv + tid * 4);
    const float4 vr = *(const float4*)(r + row * Dv + tid * 4);
    float4 x;
    x.x = va.x + vr.x; x.y = va.y + vr.y; x.z = va.z + vr.z; x.w = va.w + vr.w;

    float s  = x.x + x.y + x.z + x.w;
    float s2 = x.x * x.x + x.y * x.y + x.z * x.z + x.w * x.w;

    __shared__ float rs[8], rs2[8];
#pragma unroll
    for (int o = 16; o > 0; o >>= 1) {
        s  += __shfl_xor_sync(0xffffffffu, s,  o);
        s2 += __shfl_xor_sync(0xffffffffu, s2, o);
    }
    if ((tid & 31) == 0) { rs[tid >> 5] = s; rs2[tid >> 5] = s2; }
    __syncthreads();
    if (tid == 0) {
        float ts = 0.f, t2 = 0.f;
#pragma unroll
        for (int i = 0; i < 8; ++i) { ts += rs[i]; t2 += rs2[i]; }
        rs[0] = ts; rs2[0] = t2;
    }
    __syncthreads();

    const float mu  = rs[0] * (1.0f / Dv);
    const float var = rs2[0] * (1.0f / Dv) - mu * mu;
    const float inv = rsqrtf(var + LN_EPS);

    const float4 vg = *(const float4*)(g + tid * 4);
    const float4 vb = *(const float4*)(be + tid * 4);
    float4 o;
    o.x = (x.x - mu) * inv * vg.x + vb.x;
    o.y = (x.y - mu) * inv * vg.y + vb.y;
    o.z = (x.z - mu) * inv * vg.z + vb.z;
    o.w = (x.w - mu) * inv * vg.w + vb.w;
    *(float4*)(out + row * Dv + tid * 4) = o;
}

// ---------------------------------------------------------------------------
// Launch
// ---------------------------------------------------------------------------
extern "C" void kernel_launch(void* const* d_in, const int* in_sizes, int n_in,
                              void* d_out, int out_size)
{
    const float* x  = (const float*)d_in[0];
    const float* wq = (const float*)d_in[1];
    const float* bq = (const float*)d_in[2];
    const float* wk = (const float*)d_in[3];
    const float* bk = (const float*)d_in[4];
    const float* wv = (const float*)d_in[5];
    const float* bv = (const float*)d_in[6];
    const float* wo = (const float*)d_in[7];
    const float* bo = (const float*)d_in[8];
    const float* w1 = (const float*)d_in[9];
    const float* b1 = (const float*)d_in[10];
    const float* w2 = (const float*)d_in[11];
    const float* b2 = (const float*)d_in[12];
    const float* g1 = (const float*)d_in[13];
    const float* be1= (const float*)d_in[14];
    const float* g2 = (const float*)d_in[15];
    const float* be2= (const float*)d_in[16];
    float* out = (float*)d_out;

    float *qkv, *xr, *attn, *tmp, *h, *ff1, *wT, *bqkv;
    cudaGetSymbolAddress((void**)&qkv,  g_qkv);
    cudaGetSymbolAddress((void**)&xr,   g_xr);
    cudaGetSymbolAddress((void**)&attn, g_attn);
    cudaGetSymbolAddress((void**)&tmp,  g_tmp);
    cudaGetSymbolAddress((void**)&h,    g_h);
    cudaGetSymbolAddress((void**)&ff1,  g_ff1);
    cudaGetSymbolAddress((void**)&wT,   g_wT);
    cudaGetSymbolAddress((void**)&bqkv, g_bqkv);

    const size_t MB1 = 1024 * 1024;
    float* wqkvT = wT;               // [3072][1024] (q|k|v stacked)
    float* woT   = wT + 3 * MB1;
    float* w1T   = wT + 4 * MB1;     // [F, D]
    float* w2T   = wT + 8 * MB1;     // [D, F]

    cudaFuncSetAttribute(gemm_mma<false, false, true>,
        cudaFuncAttributeMaxDynamicSharedMemorySize, GSMEM_BYTES);
    cudaFuncSetAttribute(gemm_mma<false, false, false>,
        cudaFuncAttributeMaxDynamicSharedMemorySize, GSMEM_BYTES);
    cudaFuncSetAttribute(gemm_mma<true, true, true>,
        cudaFuncAttributeMaxDynamicSharedMemorySize, GSMEM_BYTES);
    cudaFuncSetAttribute(flash_attn,
        cudaFuncAttributeMaxDynamicSharedMemorySize, FA_SMEM_BYTES);

    // Weight prep: batched DxD transposes (wq|wk|wv -> wqkvT, wo -> woT)
    dim3 tb(32, 8);
    transpose4_tf32<<<dim3(Dv / 32, Dv / 32, 4), tb>>>(wq, wk, wv, wo, wqkvT);
    transpose_tf32<<<dim3(Fv / 32, Dv / 32), tb>>>(w1, w1T, Dv, Fv);
    transpose_tf32<<<dim3(Dv / 32, Fv / 32), tb>>>(w2, w2T, Fv, Dv);
    pack_bias<<<QS / 256, 256>>>(bq, bk, bv, bqkv);
    round_x_tf32<<<(Mv * Dv / 4) / 256, 256>>>(x, xr);

    // Fused QKV projection: [4096,1024] @ [1024,3072] -> qkv
    gemm_mma<false, false, true><<<dim3(QS / 128, Mv / 128), 128, GSMEM_BYTES>>>(
        Dv, QS, xr, wqkvT, bqkv, qkv);

    // Fused flash attention
    flash_attn<<<dim3(Sv / 64, Bv * Hv), 128, FA_SMEM_BYTES>>>(qkv, attn);

    const dim3 gDD(Dv / 128, Mv / 128);   // (8, 32)
    const dim3 gDF(Fv / 128, Mv / 128);   // (32, 32)

    // Output projection + residual LN1
    gemm_mma<false, false, false><<<gDD, 128, GSMEM_BYTES>>>(Dv, Dv, attn, woT, bo, tmp);
    residual_ln<<<Mv, 256>>>(x, tmp, g1, be1, h);

    // FFN + residual LN2
    gemm_mma<true, true, true><<<gDF, 128, GSMEM_BYTES>>>(Dv, Fv, h, w1T, b1, ff1);
    gemm_mma<false, false, false><<<gDD, 128, GSMEM_BYTES>>>(Fv, Dv, ff1, w2T, b2, tmp);
    residual_ln<<<Mv, 256>>>(h, tmp, g2, be2, out);
}

// round 7
// speedup vs baseline: 3.9119x; 1.0516x over previous
#include <cuda_runtime.h>
#include <cstdint>

// Problem constants
#define Bv   2
#define Sv   2048
#define Dv   1024
#define Hv   16
#define DKv  64
#define Fv   4096
#define Mv   (Bv * Sv)      // 4096 rows
#define QS   3072           // qkv row stride
#define LN_EPS 1e-6f

// ---------------------------------------------------------------------------
// Scratch (no cudaMalloc allowed -> __device__ globals)
// ---------------------------------------------------------------------------
__device__ float g_qkv [(size_t)Mv * QS];             // fused q|k|v
__device__ float g_xr  [(size_t)Mv * Dv];             // tf32-rounded x
__device__ float g_attn[(size_t)Mv * Dv];
__device__ float g_tmp [(size_t)Mv * Dv];
__device__ float g_h   [(size_t)Mv * Dv];
__device__ float g_ff1 [(size_t)Mv * Fv];
__device__ float g_wT  [(size_t)12 * 1024 * 1024];    // transposed tf32 weights
__device__ float g_bqkv[QS];

// ---------------------------------------------------------------------------
// Helpers
// ---------------------------------------------------------------------------
__device__ __forceinline__ uint32_t smem_u32(const void* p) {
    uint32_t a;
    asm("{ .reg .u64 t; cvta.to.shared.u64 t, %1; cvt.u32.u64 %0, t; }"
        : "=r"(a) : "l"(p));
    return a;
}
__device__ __forceinline__ float to_tf32(float x) {
    uint32_t u;
    asm("cvt.rna.tf32.f32 %0, %1;" : "=r"(u) : "f"(x));
    return __uint_as_float(u);
}
__device__ __forceinline__ uint32_t tf32u(float x) {
    uint32_t u;
    asm("cvt.rna.tf32.f32 %0, %1;" : "=r"(u) : "f"(x));
    return u;
}
__device__ __forceinline__ void mma_tf32(
    float* d, const uint32_t* a, uint32_t b0, uint32_t b1)
{
    asm volatile(
        "mma.sync.aligned.m16n8k8.row.col.f32.tf32.tf32.f32 "
        "{%0,%1,%2,%3}, {%4,%5,%6,%7}, {%8,%9}, {%0,%1,%2,%3};"
        : "+f"(d[0]), "+f"(d[1]), "+f"(d[2]), "+f"(d[3])
        : "r"(a[0]), "r"(a[1]), "r"(a[2]), "r"(a[3]), "r"(b0), "r"(b1));
}

// ---------------------------------------------------------------------------
// Batched weight transpose + tf32 rounding for the 4 DxD matrices.
// ---------------------------------------------------------------------------
__global__ void __launch_bounds__(256) transpose4_tf32(
    const float* __restrict__ w0, const float* __restrict__ w1,
    const float* __restrict__ w2, const float* __restrict__ w3,
    float* __restrict__ dst)
{
    const float* srcs[4] = { w0, w1, w2, w3 };
    const float* W = srcs[blockIdx.z];
    float* WT = dst + (size_t)blockIdx.z * Dv * Dv;

    __shared__ float t[32][33];
    const int k0 = blockIdx.y * 32, n0 = blockIdx.x * 32;
    const int tx = threadIdx.x, ty0 = threadIdx.y;
#pragma unroll
    for (int i = 0; i < 4; ++i) {
        const int ty = ty0 + i * 8;
        t[ty][tx] = W[(size_t)(k0 + ty) * Dv + n0 + tx];
    }
    __syncthreads();
#pragma unroll
    for (int i = 0; i < 4; ++i) {
        const int ty = ty0 + i * 8;
        WT[(size_t)(n0 + ty) * Dv + k0 + tx] = to_tf32(t[tx][ty]);
    }
}

__global__ void __launch_bounds__(256) transpose_tf32(
    const float* __restrict__ W, float* __restrict__ WT, int K, int N)
{
    __shared__ float t[32][33];
    const int k0 = blockIdx.y * 32, n0 = blockIdx.x * 32;
    const int tx = threadIdx.x, ty0 = threadIdx.y;
#pragma unroll
    for (int i = 0; i < 4; ++i) {
        const int ty = ty0 + i * 8;
        t[ty][tx] = W[(size_t)(k0 + ty) * N + n0 + tx];
    }
    __syncthreads();
#pragma unroll
    for (int i = 0; i < 4; ++i) {
        const int ty = ty0 + i * 8;
        WT[(size_t)(n0 + ty) * K + k0 + tx] = to_tf32(t[tx][ty]);
    }
}

// ---------------------------------------------------------------------------
// Fused prep: rounds x to tf32 (blocks 0..4095) + packs qkv bias (3 blocks)
// ---------------------------------------------------------------------------
__global__ void __launch_bounds__(256) prep_x_bias(
    const float* __restrict__ x, float* __restrict__ y,
    const float* __restrict__ bq, const float* __restrict__ bk,
    const float* __restrict__ bv, float* __restrict__ bias)
{
    const int blk = blockIdx.x;
    if (blk < (Mv * Dv / 4) / 256) {
        const int i = blk * 256 + threadIdx.x;
        float4 v = ((const float4*)x)[i];
        v.x = to_tf32(v.x); v.y = to_tf32(v.y);
        v.z = to_tf32(v.z); v.w = to_tf32(v.w);
        ((float4*)y)[i] = v;
    } else {
        const int j = blk - (Mv * Dv / 4) / 256;   // 0..2
        const float* src = (j == 0) ? bq : (j == 1) ? bk : bv;
        ((float4*)bias)[j * 256 + threadIdx.x] = ((const float4*)src)[threadIdx.x];
    }
}

// ---------------------------------------------------------------------------
// Tensor-core GEMM via mma.sync tf32 (unchanged from R6).
// ---------------------------------------------------------------------------
#define GBK 32
#define GSTRIDE 36
#define GSM_FLOATS (128 * GSTRIDE)
#define GSMEM_BYTES (4 * GSM_FLOATS * 4)   // 73728

template <bool RELU, bool CVTA, bool CVTOUT>
__global__ void __launch_bounds__(128)
gemm_mma(int K, int N, const float* __restrict__ A,
         const float* __restrict__ WT, const float* __restrict__ bias,
         float* __restrict__ C)
{
    extern __shared__ float sm[];
    const int m0 = blockIdx.y * 128;
    const int n0 = blockIdx.x * 128;
    const int tid  = threadIdx.x;
    const int lane = tid & 31;
    const int wid  = tid >> 5;
    const int wm = (wid >> 1) * 64;
    const int wn = (wid & 1) * 64;

    float* tA[2] = { sm,                  sm + 2 * GSM_FLOATS };
    float* tB[2] = { sm + GSM_FLOATS,     sm + 3 * GSM_FLOATS };
    const uint32_t uA[2] = { smem_u32(tA[0]), smem_u32(tA[1]) };
    const uint32_t uB[2] = { smem_u32(tB[0]), smem_u32(tB[1]) };

    const float* Ab = A  + (size_t)m0 * K;
    const float* Bb = WT + (size_t)n0 * K;
    const int nk = K / GBK;

    float acc[4][8][4] = {};

    auto load_stage = [&](int buf, int kt) {
#pragma unroll
        for (int i = 0; i < 8; ++i) {
            const int s   = tid + i * 128;
            const int row = s >> 3;
            const int f   = s & 7;
            const float* ga = Ab + (size_t)row * K + kt * GBK + f * 4;
            const float* gb = Bb + (size_t)row * K + kt * GBK + f * 4;
            const uint32_t da = uA[buf] + (uint32_t)(row * (GSTRIDE * 4) + f * 16);
            const uint32_t db = uB[buf] + (uint32_t)(row * (GSTRIDE * 4) + f * 16);
            asm volatile("cp.async.cg.shared.global [%0], [%1], 16;" :: "r"(da), "l"(ga));
            asm volatile("cp.async.cg.shared.global [%0], [%1], 16;" :: "r"(db), "l"(gb));
        }
    };

    load_stage(0, 0);
    asm volatile("cp.async.commit_group;" ::: "memory");

    const int r = lane >> 2;
    const int c = lane & 3;

    for (int kt = 0; kt < nk; ++kt) {
        const int buf = kt & 1;
        if (kt + 1 < nk) load_stage(buf ^ 1, kt + 1);
        asm volatile("cp.async.commit_group;" ::: "memory");
        asm volatile("cp.async.wait_group 1;" ::: "memory");
        __syncthreads();

        const float* sa = tA[buf];
        const float* sb = tB[buf];

#pragma unroll
        for (int kk = 0; kk < 4; ++kk) {
            const int k0 = kk * 8;
            uint32_t afr[4][4];
            uint32_t bfr[8][2];
#pragma unroll
            for (int mt = 0; mt < 4; ++mt) {
                const float* base  = sa + (size_t)(wm + mt * 16 + r) * GSTRIDE + k0 + c;
                const float* base8 = base + 8 * GSTRIDE;
                if (CVTA) {
                    afr[mt][0] = tf32u(base[0]);
                    afr[mt][1] = tf32u(base8[0]);
                    afr[mt][2] = tf32u(base[4]);
                    afr[mt][3] = tf32u(base8[4]);
                } else {
                    afr[mt][0] = __float_as_uint(base[0]);
                    afr[mt][1] = __float_as_uint(base8[0]);
                    afr[mt][2] = __float_as_uint(base[4]);
                    afr[mt][3] = __float_as_uint(base8[4]);
                }
            }
#pragma unroll
            for (int nt = 0; nt < 8; ++nt) {
                const float* base = sb + (size_t)(wn + nt * 8 + r) * GSTRIDE + k0 + c;
                bfr[nt][0] = __float_as_uint(base[0]);
                bfr[nt][1] = __float_as_uint(base[4]);
            }
#pragma unroll
            for (int mt = 0; mt < 4; ++mt)
#pragma unroll
                for (int nt = 0; nt < 8; ++nt)
                    mma_tf32(acc[mt][nt], afr[mt], bfr[nt][0], bfr[nt][1]);
        }
        __syncthreads();
    }

#pragma unroll
    for (int mt = 0; mt < 4; ++mt) {
        const int rg = m0 + wm + mt * 16 + r;
#pragma unroll
        for (int nt = 0; nt < 8; ++nt) {
            const int cg = n0 + wn + nt * 8 + c * 2;
            const float b0 = bias[cg], b1 = bias[cg + 1];
            float2 v0, v1;
            v0.x = acc[mt][nt][0] + b0; v0.y = acc[mt][nt][1] + b1;
            v1.x = acc[mt][nt][2] + b0; v1.y = acc[mt][nt][3] + b1;
            if (RELU) {
                v0.x = fmaxf(v0.x, 0.f); v0.y = fmaxf(v0.y, 0.f);
                v1.x = fmaxf(v1.x, 0.f); v1.y = fmaxf(v1.y, 0.f);
            }
            if (CVTOUT) {
                v0.x = to_tf32(v0.x); v0.y = to_tf32(v0.y);
                v1.x = to_tf32(v1.x); v1.y = to_tf32(v1.y);
            }
            *(float2*)(C + (size_t)rg * N + cg)       = v0;
            *(float2*)(C + (size_t)(rg + 8) * N + cg) = v1;
        }
    }
}

// ---------------------------------------------------------------------------
// Fused flash attention v2 (tf32 mma.sync + online softmax).
// CTA = 128 Q rows of one (b,h); 4 warps x 32 rows (2 m-frags each).
// K/V B-frags reused across mt -> 1.25 LDS/MMA. P in dedicated per-warp smem.
// Q register-resident (pre-scaled by 1/8). 2 CTAs/SM.
// ---------------------------------------------------------------------------
#define KSTRIDE 68
#define VSTRIDE 72
#define PSTRIDE 68
#define FA_SMEM_FLOATS (2*64*KSTRIDE + 2*64*VSTRIDE + 128*PSTRIDE)
#define FA_SMEM_BYTES  (FA_SMEM_FLOATS * 4)   // 106496

__global__ void __launch_bounds__(128, 2)
flash_attn(const float* __restrict__ qkv, float* __restrict__ o)
{
    extern __shared__ float sm[];
    float* Kt[2] = { sm, sm + 64 * KSTRIDE };
    float* Vt[2] = { sm + 2*64*KSTRIDE, sm + 2*64*KSTRIDE + 64*VSTRIDE };
    float* Pt    = sm + 2*64*KSTRIDE + 2*64*VSTRIDE;

    const int bh = blockIdx.y;
    const int b  = bh >> 4;
    const int h  = bh & 15;
    const int i0 = blockIdx.x * 128;

    const int tid  = threadIdx.x;
    const int lane = tid & 31;
    const int wid  = tid >> 5;
    const int r = lane >> 2;
    const int c = lane & 3;

    const uint32_t uK[2] = { smem_u32(Kt[0]), smem_u32(Kt[1]) };
    const uint32_t uV[2] = { smem_u32(Vt[0]), smem_u32(Vt[1]) };
    float* Pw = Pt + wid * 32 * PSTRIDE;

    // Q fragments (2 m-frags x 8 kk), pre-scaled by 1/sqrt(dk)=0.125 (exact)
    uint32_t qa[2][8][4];
    {
        const float* qb = qkv + (size_t)(b * Sv + i0 + wid * 32) * QS + h * DKv;
#pragma unroll
        for (int mt = 0; mt < 2; ++mt)
#pragma unroll
            for (int kk = 0; kk < 8; ++kk) {
                const int col = kk * 8 + c;
                const float* q0 = qb + (size_t)(mt * 16 + r) * QS;
                const float* q8 = qb + (size_t)(mt * 16 + r + 8) * QS;
                qa[mt][kk][0] = __float_as_uint(0.125f * q0[col]);
                qa[mt][kk][1] = __float_as_uint(0.125f * q8[col]);
                qa[mt][kk][2] = __float_as_uint(0.125f * q0[col + 4]);
                qa[mt][kk][3] = __float_as_uint(0.125f * q8[col + 4]);
            }
    }

    float oacc[2][8][4] = {};
    float mrow[4] = { -1e30f, -1e30f, -1e30f, -1e30f };   // [2*mt + hi]
    float lrow[4] = { 0.f, 0.f, 0.f, 0.f };

    auto load_kv = [&](int buf, int jt) {
        const float* kb = qkv + (size_t)(b * Sv + jt * 64) * QS + 1024 + h * DKv;
        const float* vb = qkv + (size_t)(b * Sv + jt * 64) * QS + 2048 + h * DKv;
#pragma unroll
        for (int i = 0; i < 8; ++i) {
            const int s   = tid + i * 128;
            const int row = s >> 4;
            const int f   = s & 15;
            const uint32_t dk_ = uK[buf] + (uint32_t)(row * (KSTRIDE * 4) + f * 16);
            const uint32_t dv_ = uV[buf] + (uint32_t)(row * (VSTRIDE * 4) + f * 16);
            asm volatile("cp.async.cg.shared.global [%0], [%1], 16;"
                         :: "r"(dk_), "l"(kb + (size_t)row * QS + f * 4));
            asm volatile("cp.async.cg.shared.global [%0], [%1], 16;"
                         :: "r"(dv_), "l"(vb + (size_t)row * QS + f * 4));
        }
    };

    load_kv(0, 0);
    asm volatile("cp.async.commit_group;" ::: "memory");

    const int NT = Sv / 64;
    for (int jt = 0; jt < NT; ++jt) {
        const int buf = jt & 1;
        if (jt + 1 < NT) load_kv(buf ^ 1, jt + 1);
        asm volatile("cp.async.commit_group;" ::: "memory");
        asm volatile("cp.async.wait_group 1;" ::: "memory");
        __syncthreads();

        const float* ks = Kt[buf];
        const float* vs = Vt[buf];

        // ---- S = Q K^T : K-frag loaded once, reused across both m-frags ----
        float sacc[2][8][4] = {};
#pragma unroll
        for (int kk = 0; kk < 8; ++kk) {
            const int k0 = kk * 8;
#pragma unroll
            for (int nt = 0; nt < 8; ++nt) {
                const float* kp = ks + (size_t)(nt * 8 + r) * KSTRIDE + k0 + c;
                const uint32_t b0 = __float_as_uint(kp[0]);
                const uint32_t b1 = __float_as_uint(kp[4]);
                mma_tf32(sacc[0][nt], qa[0][kk], b0, b1);
                mma_tf32(sacc[1][nt], qa[1][kk], b0, b1);
            }
        }

        // ---- online softmax (per m-frag) + P store ----
#pragma unroll
        for (int mt = 0; mt < 2; ++mt) {
            float tl = -1e30f, th = -1e30f;
#pragma unroll
            for (int nt = 0; nt < 8; ++nt) {
                tl = fmaxf(tl, fmaxf(sacc[mt][nt][0], sacc[mt][nt][1]));
                th = fmaxf(th, fmaxf(sacc[mt][nt][2], sacc[mt][nt][3]));
            }
            tl = fmaxf(tl, __shfl_xor_sync(0xffffffffu, tl, 1));
            tl = fmaxf(tl, __shfl_xor_sync(0xffffffffu, tl, 2));
            th = fmaxf(th, __shfl_xor_sync(0xffffffffu, th, 1));
            th = fmaxf(th, __shfl_xor_sync(0xffffffffu, th, 2));

            const float mnl = fmaxf(mrow[2 * mt],     tl);
            const float mnh = fmaxf(mrow[2 * mt + 1], th);
            const float crl = __expf(mrow[2 * mt]     - mnl);
            const float crh = __expf(mrow[2 * mt + 1] - mnh);

            float sl = 0.f, sh = 0.f;
            float* prow0 = Pw + (size_t)(mt * 16 + r)     * PSTRIDE;
            float* prow8 = Pw + (size_t)(mt * 16 + r + 8) * PSTRIDE;
#pragma unroll
            for (int nt = 0; nt < 8; ++nt) {
                const float p0 = __expf(sacc[mt][nt][0] - mnl);
                const float p1 = __expf(sacc[mt][nt][1] - mnl);
                const float p2 = __expf(sacc[mt][nt][2] - mnh);
                const float p3 = __expf(sacc[mt][nt][3] - mnh);
                sl += p0 + p1;
                sh += p2 + p3;
                float2 plo, phi;
                plo.x = to_tf32(p0); plo.y = to_tf32(p1);
                phi.x = to_tf32(p2); phi.y = to_tf32(p3);
                *(float2*)(prow0 + nt * 8 + 2 * c) = plo;
                *(float2*)(prow8 + nt * 8 + 2 * c) = phi;
                oacc[mt][nt][0] *= crl; oacc[mt][nt][1] *= crl;
                oacc[mt][nt][2] *= crh; oacc[mt][nt][3] *= crh;
            }
            sl += __shfl_xor_sync(0xffffffffu, sl, 1);
            sl += __shfl_xor_sync(0xffffffffu, sl, 2);
            sh += __shfl_xor_sync(0xffffffffu, sh, 1);
            sh += __shfl_xor_sync(0xffffffffu, sh, 2);

            lrow[2 * mt]     = lrow[2 * mt]     * crl + sl;
            lrow[2 * mt + 1] = lrow[2 * mt + 1] * crh + sh;
            mrow[2 * mt]     = mnl;
            mrow[2 * mt + 1] = mnh;
        }
        __syncwarp();

        // ---- O += P V : V-frag loaded once, reused across both m-frags ----
#pragma unroll
        for (int kk = 0; kk < 8; ++kk) {
            const int k0 = kk * 8;
            uint32_t pa[2][4];
#pragma unroll
            for (int mt = 0; mt < 2; ++mt) {
                const float* p0 = Pw + (size_t)(mt * 16 + r)     * PSTRIDE + k0 + c;
                const float* p8 = Pw + (size_t)(mt * 16 + r + 8) * PSTRIDE + k0 + c;
                pa[mt][0] = __float_as_uint(p0[0]);
                pa[mt][1] = __float_as_uint(p8[0]);
                pa[mt][2] = __float_as_uint(p0[4]);
                pa[mt][3] = __float_as_uint(p8[4]);
            }
#pragma unroll
            for (int nt = 0; nt < 8; ++nt) {
                const float* vp0 = vs + (size_t)(k0 + c) * VSTRIDE + nt * 8 + r;
                const float* vp1 = vs + (size_t)(k0 + c + 4) * VSTRIDE + nt * 8 + r;
                const uint32_t b0 = __float_as_uint(vp0[0]);
                const uint32_t b1 = __float_as_uint(vp1[0]);
                mma_tf32(oacc[0][nt], pa[0], b0, b1);
                mma_tf32(oacc[1][nt], pa[1], b0, b1);
            }
        }
        __syncthreads();   // all reads of buf done before next cp.async overwrite
    }

    // ---- epilogue: normalize, round to tf32, store ----
#pragma unroll
    for (int mt = 0; mt < 2; ++mt) {
        const float inv_lo = 1.0f / lrow[2 * mt];
        const float inv_hi = 1.0f / lrow[2 * mt + 1];
        const size_t row_lo = (size_t)(b * Sv + i0 + wid * 32 + mt * 16 + r);
#pragma unroll
        for (int nt = 0; nt < 8; ++nt) {
            const int col = h * DKv + nt * 8 + 2 * c;
            float2 lo, hi;
            lo.x = to_tf32(oacc[mt][nt][0] * inv_lo);
            lo.y = to_tf32(oacc[mt][nt][1] * inv_lo);
            hi.x = to_tf32(oacc[mt][nt][2] * inv_hi);
            hi.y = to_tf32(oacc[mt][nt][3] * inv_hi);
            *(float2*)(o + row_lo * Dv + col)       = lo;
            *(float2*)(o + (row_lo + 8) * Dv + col) = hi;
        }
    }
}

// ---------------------------------------------------------------------------
// Fused residual + LayerNorm
// ---------------------------------------------------------------------------
__global__ void __launch_bounds__(256) residual_ln(
    const float* __restrict__ a, const float* __restrict__ r,
    const float* __restrict__ g, const float* __restrict__ be,
    float* __restrict__ out)
{
    const size_t row = blockIdx.x;
    const int tid = threadIdx.x;

    const float4 va = *(const float4*)(a + row * Dv + tid * 4);
    const float4 vr = *(const float4*)(r + row * Dv + tid * 4);
    float4 x;
    x.x = va.x + vr.x; x.y = va.y + vr.y; x.z = va.z + vr.z; x.w = va.w + vr.w;

    float s  = x.x + x.y + x.z + x.w;
    float s2 = x.x * x.x + x.y * x.y + x.z * x.z + x.w * x.w;

    __shared__ float rs[8], rs2[8];
#pragma unroll
    for (int o = 16; o > 0; o >>= 1) {
        s  += __shfl_xor_sync(0xffffffffu, s,  o);
        s2 += __shfl_xor_sync(0xffffffffu, s2, o);
    }
    if ((tid & 31) == 0) { rs[tid >> 5] = s; rs2[tid >> 5] = s2; }
    __syncthreads();
    if (tid == 0) {
        float ts = 0.f, t2 = 0.f;
#pragma unroll
        for (int i = 0; i < 8; ++i) { ts += rs[i]; t2 += rs2[i]; }
        rs[0] = ts; rs2[0] = t2;
    }
    __syncthreads();

    const float mu  = rs[0] * (1.0f / Dv);
    const float var = rs2[0] * (1.0f / Dv) - mu * mu;
    const float inv = rsqrtf(var + LN_EPS);

    const float4 vg = *(const float4*)(g + tid * 4);
    const float4 vb = *(const float4*)(be + tid * 4);
    float4 o;
    o.x = (x.x - mu) * inv * vg.x + vb.x;
    o.y = (x.y - mu) * inv * vg.y + vb.y;
    o.z = (x.z - mu) * inv * vg.z + vb.z;
    o.w = (x.w - mu) * inv * vg.w + vb.w;
    *(float4*)(out + row * Dv + tid * 4) = o;
}

// ---------------------------------------------------------------------------
// Launch
// ---------------------------------------------------------------------------
extern "C" void kernel_launch(void* const* d_in, const int* in_sizes, int n_in,
                              void* d_out, int out_size)
{
    const float* x  = (const float*)d_in[0];
    const float* wq = (const float*)d_in[1];
    const float* bq = (const float*)d_in[2];
    const float* wk = (const float*)d_in[3];
    const float* bk = (const float*)d_in[4];
    const float* wv = (const float*)d_in[5];
    const float* bv = (const float*)d_in[6];
    const float* wo = (const float*)d_in[7];
    const float* bo = (const float*)d_in[8];
    const float* w1 = (const float*)d_in[9];
    const float* b1 = (const float*)d_in[10];
    const float* w2 = (const float*)d_in[11];
    const float* b2 = (const float*)d_in[12];
    const float* g1 = (const float*)d_in[13];
    const float* be1= (const float*)d_in[14];
    const float* g2 = (const float*)d_in[15];
    const float* be2= (const float*)d_in[16];
    float* out = (float*)d_out;

    float *qkv, *xr, *attn, *tmp, *h, *ff1, *wT, *bqkv;
    cudaGetSymbolAddress((void**)&qkv,  g_qkv);
    cudaGetSymbolAddress((void**)&xr,   g_xr);
    cudaGetSymbolAddress((void**)&attn, g_attn);
    cudaGetSymbolAddress((void**)&tmp,  g_tmp);
    cudaGetSymbolAddress((void**)&h,    g_h);
    cudaGetSymbolAddress((void**)&ff1,  g_ff1);
    cudaGetSymbolAddress((void**)&wT,   g_wT);
    cudaGetSymbolAddress((void**)&bqkv, g_bqkv);

    const size_t MB1 = 1024 * 1024;
    float* wqkvT = wT;               // [3072][1024] (q|k|v stacked)
    float* woT   = wT + 3 * MB1;
    float* w1T   = wT + 4 * MB1;     // [F, D]
    float* w2T   = wT + 8 * MB1;     // [D, F]

    cudaFuncSetAttribute(gemm_mma<false, false, true>,
        cudaFuncAttributeMaxDynamicSharedMemorySize, GSMEM_BYTES);
    cudaFuncSetAttribute(gemm_mma<false, false, false>,
        cudaFuncAttributeMaxDynamicSharedMemorySize, GSMEM_BYTES);
    cudaFuncSetAttribute(gemm_mma<true, true, true>,
        cudaFuncAttributeMaxDynamicSharedMemorySize, GSMEM_BYTES);
    cudaFuncSetAttribute(flash_attn,
        cudaFuncAttributeMaxDynamicSharedMemorySize, FA_SMEM_BYTES);

    // Weight prep
    dim3 tb(32, 8);
    transpose4_tf32<<<dim3(Dv / 32, Dv / 32, 4), tb>>>(wq, wk, wv, wo, wqkvT);
    transpose_tf32<<<dim3(Fv / 32, Dv / 32), tb>>>(w1, w1T, Dv, Fv);
    transpose_tf32<<<dim3(Dv / 32, Fv / 32), tb>>>(w2, w2T, Fv, Dv);
    prep_x_bias<<<(Mv * Dv / 4) / 256 + 3, 256>>>(x, xr, bq, bk, bv, bqkv);

    // Fused QKV projection: [4096,1024] @ [1024,3072] -> qkv
    gemm_mma<false, false, true><<<dim3(QS / 128, Mv / 128), 128, GSMEM_BYTES>>>(
        Dv, QS, xr, wqkvT, bqkv, qkv);

    // Fused flash attention (128 Q rows per CTA)
    flash_attn<<<dim3(Sv / 128, Bv * Hv), 128, FA_SMEM_BYTES>>>(qkv, attn);

    const dim3 gDD(Dv / 128, Mv / 128);   // (8, 32)
    const dim3 gDF(Fv / 128, Mv / 128);   // (32, 32)

    // Output projection + residual LN1
    gemm_mma<false, false, false><<<gDD, 128, GSMEM_BYTES>>>(Dv, Dv, attn, woT, bo, tmp);
    residual_ln<<<Mv, 256>>>(x, tmp, g1, be1, h);

    // FFN + residual LN2
    gemm_mma<true, true, true><<<gDF, 128, GSMEM_BYTES>>>(Dv, Fv, h, w1T, b1, ff1);
    gemm_mma<false, false, false><<<gDD, 128, GSMEM_BYTES>>>(Fv, Dv, ff1, w2T, b2, tmp);
    residual_ln<<<Mv, 256>>>(h, tmp, g2, be2, out);
}

// round 8
// speedup vs baseline: 4.1658x; 1.0649x over previous
#include <cuda_runtime.h>
#include <cstdint>

// Problem constants
#define Bv   2
#define Sv   2048
#define Dv   1024
#define Hv   16
#define DKv  64
#define Fv   4096
#define Mv   (Bv * Sv)      // 4096 rows
#define QS   3072           // qkv row stride
#define LN_EPS 1e-6f

// Permutation of a contraction dim within 8-groups: logical j -> storage
// perm8(j) = j<4 ? 2j : 2j-7   (storage order [0,4,1,5,2,6,3,7])
// Makes mma.sync fragment pairs (k=c, k=c+4) adjacent -> LDS.64 / float2.

// ---------------------------------------------------------------------------
// Scratch (no cudaMalloc allowed -> __device__ globals)
// ---------------------------------------------------------------------------
__device__ float g_qkv [(size_t)Mv * QS];             // fused q|k|v (d-permuted)
__device__ float g_xr  [(size_t)Mv * Dv];             // tf32-rounded x (permuted)
__device__ float g_attn[(size_t)Mv * Dv];             // flash out (permuted)
__device__ float g_tmp [(size_t)Mv * Dv];             // wo out (STANDARD)
__device__ float g_tmp2[(size_t)Mv * Dv];             // ff2 out (permuted)
__device__ float g_h   [(size_t)Mv * Dv];             // LN1 out (permuted, tf32)
__device__ float g_ff1 [(size_t)Mv * Fv];             // ff1 out (permuted, tf32)
__device__ float g_wT  [(size_t)12 * 1024 * 1024];    // transposed tf32 weights (k-perm)
__device__ float g_bqkv[QS];

// ---------------------------------------------------------------------------
// Helpers
// ---------------------------------------------------------------------------
__device__ __forceinline__ uint32_t smem_u32(const void* p) {
    uint32_t a;
    asm("{ .reg .u64 t; cvta.to.shared.u64 t, %1; cvt.u32.u64 %0, t; }"
        : "=r"(a) : "l"(p));
    return a;
}
__device__ __forceinline__ float to_tf32(float x) {
    uint32_t u;
    asm("cvt.rna.tf32.f32 %0, %1;" : "=r"(u) : "f"(x));
    return __uint_as_float(u);
}
__device__ __forceinline__ void mma_tf32(
    float* d, const uint32_t* a, uint32_t b0, uint32_t b1)
{
    asm volatile(
        "mma.sync.aligned.m16n8k8.row.col.f32.tf32.tf32.f32 "
        "{%0,%1,%2,%3}, {%4,%5,%6,%7}, {%8,%9}, {%0,%1,%2,%3};"
        : "+f"(d[0]), "+f"(d[1]), "+f"(d[2]), "+f"(d[3])
        : "r"(a[0]), "r"(a[1]), "r"(a[2]), "r"(a[3]), "r"(b0), "r"(b1));
}
__device__ __forceinline__ int perm8i(int t) { return (t < 4) ? 2 * t : 2 * t - 7; }

// ---------------------------------------------------------------------------
// Batched weight transpose + tf32 rounding, k-dim PERMUTED within 8-groups.
// WT[n][perm(k)] = tf32(W[k][n])
// ---------------------------------------------------------------------------
__global__ void __launch_bounds__(256) transpose4_tf32(
    const float* __restrict__ w0, const float* __restrict__ w1,
    const float* __restrict__ w2, const float* __restrict__ w3,
    float* __restrict__ dst)
{
    const float* srcs[4] = { w0, w1, w2, w3 };
    const float* W = srcs[blockIdx.z];
    float* WT = dst + (size_t)blockIdx.z * Dv * Dv;

    __shared__ float t[32][33];
    const int k0 = blockIdx.y * 32, n0 = blockIdx.x * 32;
    const int tx = threadIdx.x, ty0 = threadIdx.y;
#pragma unroll
    for (int i = 0; i < 4; ++i) {
        const int ty = ty0 + i * 8;
        t[ty][tx] = W[(size_t)(k0 + ty) * Dv + n0 + tx];
    }
    __syncthreads();
    const int txs = (tx & ~7) | perm8i(tx & 7);
#pragma unroll
    for (int i = 0; i < 4; ++i) {
        const int ty = ty0 + i * 8;
        WT[(size_t)(n0 + ty) * Dv + k0 + txs] = to_tf32(t[tx][ty]);
    }
}

__global__ void __launch_bounds__(256) transpose_tf32(
    const float* __restrict__ W, float* __restrict__ WT, int K, int N)
{
    __shared__ float t[32][33];
    const int k0 = blockIdx.y * 32, n0 = blockIdx.x * 32;
    const int tx = threadIdx.x, ty0 = threadIdx.y;
#pragma unroll
    for (int i = 0; i < 4; ++i) {
        const int ty = ty0 + i * 8;
        t[ty][tx] = W[(size_t)(k0 + ty) * N + n0 + tx];
    }
    __syncthreads();
    const int txs = (tx & ~7) | perm8i(tx & 7);
#pragma unroll
    for (int i = 0; i < 4; ++i) {
        const int ty = ty0 + i * 8;
        WT[(size_t)(n0 + ty) * K + k0 + txs] = to_tf32(t[tx][ty]);
    }
}

// ---------------------------------------------------------------------------
// Fused prep: x -> xr (tf32-rounded, col-PERMUTED), + qkv bias pack.
// Each thread handles one 8-group of x.
// ---------------------------------------------------------------------------
#define PREP_XBLKS ((Mv * Dv / 8) / 256)   // 2048

__global__ void __launch_bounds__(256) prep_x_bias(
    const float* __restrict__ x, float* __restrict__ y,
    const float* __restrict__ bq, const float* __restrict__ bk,
    const float* __restrict__ bv, float* __restrict__ bias)
{
    const int blk = blockIdx.x;
    if (blk < PREP_XBLKS) {
        const size_t base = ((size_t)blk * 256 + threadIdx.x) * 8;
        const float4 a = *(const float4*)(x + base);
        const float4 b = *(const float4*)(x + base + 4);
        float4 s0, s1;   // storage: [l0,l4,l1,l5], [l2,l6,l3,l7]
        s0.x = to_tf32(a.x); s0.y = to_tf32(b.x);
        s0.z = to_tf32(a.y); s0.w = to_tf32(b.y);
        s1.x = to_tf32(a.z); s1.y = to_tf32(b.z);
        s1.z = to_tf32(a.w); s1.w = to_tf32(b.w);
        *(float4*)(y + base)     = s0;
        *(float4*)(y + base + 4) = s1;
    } else {
        const int j = blk - PREP_XBLKS;   // 0..2
        const float* src = (j == 0) ? bq : (j == 1) ? bk : bv;
        ((float4*)bias)[j * 256 + threadIdx.x] = ((const float4*)src)[threadIdx.x];
    }
}

// ---------------------------------------------------------------------------
// Tensor-core GEMM via mma.sync tf32. A and WT have k-dim PERMUTED -> float2
// fragment loads. GSTRIDE=40 is conflict-free for the float2 pattern
// (bank = 8r+2c is a lane permutation per half-warp phase).
// C = A @ WT^T + bias; PERMOUT scatters output cols into permuted convention.
// ---------------------------------------------------------------------------
#define GBK 32
#define GSTRIDE 40
#define GSM_FLOATS (128 * GSTRIDE)
#define GSMEM_BYTES (4 * GSM_FLOATS * 4)   // 81920

template <bool RELU, bool CVTOUT, bool PERMOUT>
__global__ void __launch_bounds__(128)
gemm_mma(int K, int N, const float* __restrict__ A,
         const float* __restrict__ WT, const float* __restrict__ bias,
         float* __restrict__ C)
{
    extern __shared__ float sm[];
    const int m0 = blockIdx.y * 128;
    const int n0 = blockIdx.x * 128;
    const int tid  = threadIdx.x;
    const int lane = tid & 31;
    const int wid  = tid >> 5;
    const int wm = (wid >> 1) * 64;
    const int wn = (wid & 1) * 64;

    float* tA[2] = { sm,              sm + 2 * GSM_FLOATS };
    float* tB[2] = { sm + GSM_FLOATS, sm + 3 * GSM_FLOATS };
    const uint32_t uA[2] = { smem_u32(tA[0]), smem_u32(tA[1]) };
    const uint32_t uB[2] = { smem_u32(tB[0]), smem_u32(tB[1]) };

    const float* Ab = A  + (size_t)m0 * K;
    const float* Bb = WT + (size_t)n0 * K;
    const int nk = K / GBK;

    float acc[4][8][4] = {};

    auto load_stage = [&](int buf, int kt) {
#pragma unroll
        for (int i = 0; i < 8; ++i) {
            const int s   = tid + i * 128;
            const int row = s >> 3;
            const int f   = s & 7;
            const float* ga = Ab + (size_t)row * K + kt * GBK + f * 4;
            const float* gb = Bb + (size_t)row * K + kt * GBK + f * 4;
            const uint32_t da = uA[buf] + (uint32_t)(row * (GSTRIDE * 4) + f * 16);
            const uint32_t db = uB[buf] + (uint32_t)(row * (GSTRIDE * 4) + f * 16);
            asm volatile("cp.async.cg.shared.global [%0], [%1], 16;" :: "r"(da), "l"(ga));
            asm volatile("cp.async.cg.shared.global [%0], [%1], 16;" :: "r"(db), "l"(gb));
        }
    };

    load_stage(0, 0);
    asm volatile("cp.async.commit_group;" ::: "memory");

    const int r = lane >> 2;
    const int c = lane & 3;

    for (int kt = 0; kt < nk; ++kt) {
        const int buf = kt & 1;
        if (kt + 1 < nk) load_stage(buf ^ 1, kt + 1);
        asm volatile("cp.async.commit_group;" ::: "memory");
        asm volatile("cp.async.wait_group 1;" ::: "memory");
        __syncthreads();

        const float* sa = tA[buf];
        const float* sb = tB[buf];

#pragma unroll
        for (int kk = 0; kk < 4; ++kk) {
            const int k0 = kk * 8;
            uint32_t afr[4][4];
            uint32_t bfr[8][2];
#pragma unroll
            for (int mt = 0; mt < 4; ++mt) {
                const float* base = sa + (size_t)(wm + mt * 16 + r) * GSTRIDE + k0 + 2 * c;
                const float2 lo = *(const float2*)(base);
                const float2 hi = *(const float2*)(base + 8 * GSTRIDE);
                afr[mt][0] = __float_as_uint(lo.x);
                afr[mt][1] = __float_as_uint(hi.x);
                afr[mt][2] = __float_as_uint(lo.y);
                afr[mt][3] = __float_as_uint(hi.y);
            }
#pragma unroll
            for (int nt = 0; nt < 8; ++nt) {
                const float2 bb = *(const float2*)(
                    sb + (size_t)(wn + nt * 8 + r) * GSTRIDE + k0 + 2 * c);
                bfr[nt][0] = __float_as_uint(bb.x);
                bfr[nt][1] = __float_as_uint(bb.y);
            }
#pragma unroll
            for (int mt = 0; mt < 4; ++mt)
#pragma unroll
                for (int nt = 0; nt < 8; ++nt)
                    mma_tf32(acc[mt][nt], afr[mt], bfr[nt][0], bfr[nt][1]);
        }
        __syncthreads();
    }

    // Epilogue. Logical cols per thread: (2c, 2c+1) in each 8-group.
    // PERMOUT storage offsets: perm8(2c), perm8(2c+1).
    const int p0 = (c < 2) ? 4 * c : 4 * c - 7;       // perm8(2c)
    const int p1 = (c < 2) ? 4 * c + 2 : 4 * c - 5;   // perm8(2c+1)
#pragma unroll
    for (int mt = 0; mt < 4; ++mt) {
        const int rg = m0 + wm + mt * 16 + r;
#pragma unroll
        for (int nt = 0; nt < 8; ++nt) {
            const int cgb = n0 + wn + nt * 8;
            const float b0 = bias[cgb + 2 * c], b1 = bias[cgb + 2 * c + 1];
            float2 v0, v1;
            v0.x = acc[mt][nt][0] + b0; v0.y = acc[mt][nt][1] + b1;
            v1.x = acc[mt][nt][2] + b0; v1.y = acc[mt][nt][3] + b1;
            if (RELU) {
                v0.x = fmaxf(v0.x, 0.f); v0.y = fmaxf(v0.y, 0.f);
                v1.x = fmaxf(v1.x, 0.f); v1.y = fmaxf(v1.y, 0.f);
            }
            if (CVTOUT) {
                v0.x = to_tf32(v0.x); v0.y = to_tf32(v0.y);
                v1.x = to_tf32(v1.x); v1.y = to_tf32(v1.y);
            }
            if (PERMOUT) {
                float* c0 = C + (size_t)rg * N + cgb;
                float* c8 = C + (size_t)(rg + 8) * N + cgb;
                c0[p0] = v0.x; c0[p1] = v0.y;
                c8[p0] = v1.x; c8[p1] = v1.y;
            } else {
                *(float2*)(C + (size_t)rg * N + cgb + 2 * c)       = v0;
                *(float2*)(C + (size_t)(rg + 8) * N + cgb + 2 * c) = v1;
            }
        }
    }
}

// ---------------------------------------------------------------------------
// Fused flash attention (tf32 mma.sync + base-2 online softmax).
// qkv has d-dim permuted: Q/K fragment pairs -> float2 (K/VSTRIDE=72
// conflict-free). V cols storage-ordered -> output naturally permuted.
// Q pre-scaled by 0.125*log2(e); softmax via exp2f (exact same math).
// ---------------------------------------------------------------------------
#define KSTRIDE 72
#define VSTRIDE 72
#define PSTRIDE 68
#define FA_SMEM_FLOATS (2*64*KSTRIDE + 2*64*VSTRIDE + 128*PSTRIDE)
#define FA_SMEM_BYTES  (FA_SMEM_FLOATS * 4)   // 108544

__global__ void __launch_bounds__(128, 2)
flash_attn(const float* __restrict__ qkv, float* __restrict__ o)
{
    extern __shared__ float sm[];
    float* Kt[2] = { sm, sm + 64 * KSTRIDE };
    float* Vt[2] = { sm + 2*64*KSTRIDE, sm + 2*64*KSTRIDE + 64*VSTRIDE };
    float* Pt    = sm + 2*64*KSTRIDE + 2*64*VSTRIDE;

    const int bh = blockIdx.y;
    const int b  = bh >> 4;
    const int h  = bh & 15;
    const int i0 = blockIdx.x * 128;

    const int tid  = threadIdx.x;
    const int lane = tid & 31;
    const int wid  = tid >> 5;
    const int r = lane >> 2;
    const int c = lane & 3;

    const uint32_t uK[2] = { smem_u32(Kt[0]), smem_u32(Kt[1]) };
    const uint32_t uV[2] = { smem_u32(Vt[0]), smem_u32(Vt[1]) };
    float* Pw = Pt + wid * 32 * PSTRIDE;

    const float qscale = 0.125f * 1.4426950408889634f;   // 1/sqrt(dk) * log2(e)

    // Q fragments: permuted storage -> float2 pairs
    uint32_t qa[2][8][4];
    {
        const float* qb = qkv + (size_t)(b * Sv + i0 + wid * 32) * QS + h * DKv;
#pragma unroll
        for (int mt = 0; mt < 2; ++mt)
#pragma unroll
            for (int kk = 0; kk < 8; ++kk) {
                const float2 f0 = *(const float2*)(qb + (size_t)(mt * 16 + r)     * QS + kk * 8 + 2 * c);
                const float2 f8 = *(const float2*)(qb + (size_t)(mt * 16 + r + 8) * QS + kk * 8 + 2 * c);
                qa[mt][kk][0] = __float_as_uint(qscale * f0.x);
                qa[mt][kk][1] = __float_as_uint(qscale * f8.x);
                qa[mt][kk][2] = __float_as_uint(qscale * f0.y);
                qa[mt][kk][3] = __float_as_uint(qscale * f8.y);
            }
    }

    float oacc[2][8][4] = {};
    float mrow[4] = { -1e30f, -1e30f, -1e30f, -1e30f };
    float lrow[4] = { 0.f, 0.f, 0.f, 0.f };

    auto load_kv = [&](int buf, int jt) {
        const float* kb = qkv + (size_t)(b * Sv + jt * 64) * QS + 1024 + h * DKv;
        const float* vb = qkv + (size_t)(b * Sv + jt * 64) * QS + 2048 + h * DKv;
#pragma unroll
        for (int i = 0; i < 8; ++i) {
            const int s   = tid + i * 128;
            const int row = s >> 4;
            const int f   = s & 15;
            const uint32_t dk_ = uK[buf] + (uint32_t)(row * (KSTRIDE * 4) + f * 16);
            const uint32_t dv_ = uV[buf] + (uint32_t)(row * (VSTRIDE * 4) + f * 16);
            asm volatile("cp.async.cg.shared.global [%0], [%1], 16;"
                         :: "r"(dk_), "l"(kb + (size_t)row * QS + f * 4));
            asm volatile("cp.async.cg.shared.global [%0], [%1], 16;"
                         :: "r"(dv_), "l"(vb + (size_t)row * QS + f * 4));
        }
    };

    load_kv(0, 0);
    asm volatile("cp.async.commit_group;" ::: "memory");

    const int NT = Sv / 64;
    for (int jt = 0; jt < NT; ++jt) {
        const int buf = jt & 1;
        if (jt + 1 < NT) load_kv(buf ^ 1, jt + 1);
        asm volatile("cp.async.commit_group;" ::: "memory");
        asm volatile("cp.async.wait_group 1;" ::: "memory");
        __syncthreads();

        const float* ks = Kt[buf];
        const float* vs = Vt[buf];

        // ---- S = Q K^T : K fragment pairs as float2 ----
        float sacc[2][8][4] = {};
#pragma unroll
        for (int kk = 0; kk < 8; ++kk) {
            const int k0 = kk * 8;
#pragma unroll
            for (int nt = 0; nt < 8; ++nt) {
                const float2 kp = *(const float2*)(
                    ks + (size_t)(nt * 8 + r) * KSTRIDE + k0 + 2 * c);
                const uint32_t b0 = __float_as_uint(kp.x);
                const uint32_t b1 = __float_as_uint(kp.y);
                mma_tf32(sacc[0][nt], qa[0][kk], b0, b1);
                mma_tf32(sacc[1][nt], qa[1][kk], b0, b1);
            }
        }

        // ---- base-2 online softmax ----
#pragma unroll
        for (int mt = 0; mt < 2; ++mt) {
            float tl = -1e30f, th = -1e30f;
#pragma unroll
            for (int nt = 0; nt < 8; ++nt) {
                tl = fmaxf(tl, fmaxf(sacc[mt][nt][0], sacc[mt][nt][1]));
                th = fmaxf(th, fmaxf(sacc[mt][nt][2], sacc[mt][nt][3]));
            }
            tl = fmaxf(tl, __shfl_xor_sync(0xffffffffu, tl, 1));
            tl = fmaxf(tl, __shfl_xor_sync(0xffffffffu, tl, 2));
            th = fmaxf(th, __shfl_xor_sync(0xffffffffu, th, 1));
            th = fmaxf(th, __shfl_xor_sync(0xffffffffu, th, 2));

            const float mnl = fmaxf(mrow[2 * mt],     tl);
            const float mnh = fmaxf(mrow[2 * mt + 1], th);
            const float crl = exp2f(mrow[2 * mt]     - mnl);
            const float crh = exp2f(mrow[2 * mt + 1] - mnh);

            float sl = 0.f, sh = 0.f;
            float* prow0 = Pw + (size_t)(mt * 16 + r)     * PSTRIDE;
            float* prow8 = Pw + (size_t)(mt * 16 + r + 8) * PSTRIDE;
#pragma unroll
            for (int nt = 0; nt < 8; ++nt) {
                const float p0 = exp2f(sacc[mt][nt][0] - mnl);
                const float p1 = exp2f(sacc[mt][nt][1] - mnl);
                const float p2 = exp2f(sacc[mt][nt][2] - mnh);
                const float p3 = exp2f(sacc[mt][nt][3] - mnh);
                sl += p0 + p1;
                sh += p2 + p3;
                float2 plo, phi;
                plo.x = to_tf32(p0); plo.y = to_tf32(p1);
                phi.x = to_tf32(p2); phi.y = to_tf32(p3);
                *(float2*)(prow0 + nt * 8 + 2 * c) = plo;
                *(float2*)(prow8 + nt * 8 + 2 * c) = phi;
                oacc[mt][nt][0] *= crl; oacc[mt][nt][1] *= crl;
                oacc[mt][nt][2] *= crh; oacc[mt][nt][3] *= crh;
            }
            sl += __shfl_xor_sync(0xffffffffu, sl, 1);
            sl += __shfl_xor_sync(0xffffffffu, sl, 2);
            sh += __shfl_xor_sync(0xffffffffu, sh, 1);
            sh += __shfl_xor_sync(0xffffffffu, sh, 2);

            lrow[2 * mt]     = lrow[2 * mt]     * crl + sl;
            lrow[2 * mt + 1] = lrow[2 * mt + 1] * crh + sh;
            mrow[2 * mt]     = mnl;
            mrow[2 * mt + 1] = mnh;
        }
        __syncwarp();

        // ---- O += P V ----
#pragma unroll
        for (int kk = 0; kk < 8; ++kk) {
            const int k0 = kk * 8;
            uint32_t pa[2][4];
#pragma unroll
            for (int mt = 0; mt < 2; ++mt) {
                const float* p0 = Pw + (size_t)(mt * 16 + r)     * PSTRIDE + k0 + c;
                const float* p8 = Pw + (size_t)(mt * 16 + r + 8) * PSTRIDE + k0 + c;
                pa[mt][0] = __float_as_uint(p0[0]);
                pa[mt][1] = __float_as_uint(p8[0]);
                pa[mt][2] = __float_as_uint(p0[4]);
                pa[mt][3] = __float_as_uint(p8[4]);
            }
#pragma unroll
            for (int nt = 0; nt < 8; ++nt) {
                const float* vp0 = vs + (size_t)(k0 + c) * VSTRIDE + nt * 8 + r;
                const float* vp1 = vs + (size_t)(k0 + c + 4) * VSTRIDE + nt * 8 + r;
                const uint32_t b0 = __float_as_uint(vp0[0]);
                const uint32_t b1 = __float_as_uint(vp1[0]);
                mma_tf32(oacc[0][nt], pa[0], b0, b1);
                mma_tf32(oacc[1][nt], pa[1], b0, b1);
            }
        }
        __syncthreads();
    }

    // ---- epilogue: normalize, round, store (cols already storage-ordered) ----
#pragma unroll
    for (int mt = 0; mt < 2; ++mt) {
        const float inv_lo = 1.0f / lrow[2 * mt];
        const float inv_hi = 1.0f / lrow[2 * mt + 1];
        const size_t row_lo = (size_t)(b * Sv + i0 + wid * 32 + mt * 16 + r);
#pragma unroll
        for (int nt = 0; nt < 8; ++nt) {
            const int col = h * DKv + nt * 8 + 2 * c;
            float2 lo, hi;
            lo.x = to_tf32(oacc[mt][nt][0] * inv_lo);
            lo.y = to_tf32(oacc[mt][nt][1] * inv_lo);
            hi.x = to_tf32(oacc[mt][nt][2] * inv_hi);
            hi.y = to_tf32(oacc[mt][nt][3] * inv_hi);
            *(float2*)(o + row_lo * Dv + col)       = lo;
            *(float2*)(o + (row_lo + 8) * Dv + col) = hi;
        }
    }
}

// ---------------------------------------------------------------------------
// Residual + LayerNorm, warp-per-row (no block barriers).
// LN1: inputs STANDARD (x, wo-out) -> output h PERMUTED + tf32-rounded.
// ---------------------------------------------------------------------------
__global__ void __launch_bounds__(256) residual_ln1(
    const float* __restrict__ a, const float* __restrict__ r,
    const float* __restrict__ g, const float* __restrict__ be,
    float* __restrict__ out)
{
    const size_t row = (size_t)blockIdx.x * 8 + (threadIdx.x >> 5);
    const int lane = threadIdx.x & 31;

    float v[32];
    float s = 0.f, s2 = 0.f;
#pragma unroll
    for (int gg = 0; gg < 4; ++gg) {
        const int gb = (gg * 32 + lane) * 8;
        const float4 a0 = *(const float4*)(a + row * Dv + gb);
        const float4 a1 = *(const float4*)(a + row * Dv + gb + 4);
        const float4 r0 = *(const float4*)(r + row * Dv + gb);
        const float4 r1 = *(const float4*)(r + row * Dv + gb + 4);
        float* vv = v + gg * 8;
        vv[0] = a0.x + r0.x; vv[1] = a0.y + r0.y; vv[2] = a0.z + r0.z; vv[3] = a0.w + r0.w;
        vv[4] = a1.x + r1.x; vv[5] = a1.y + r1.y; vv[6] = a1.z + r1.z; vv[7] = a1.w + r1.w;
#pragma unroll
        for (int i = 0; i < 8; ++i) { s += vv[i]; s2 += vv[i] * vv[i]; }
    }
#pragma unroll
    for (int o_ = 16; o_ > 0; o_ >>= 1) {
        s  += __shfl_xor_sync(0xffffffffu, s,  o_);
        s2 += __shfl_xor_sync(0xffffffffu, s2, o_);
    }
    const float mu  = s * (1.0f / Dv);
    const float var = s2 * (1.0f / Dv) - mu * mu;
    const float inv = rsqrtf(var + LN_EPS);

#pragma unroll
    for (int gg = 0; gg < 4; ++gg) {
        const int gb = (gg * 32 + lane) * 8;
        const float4 g0 = *(const float4*)(g + gb);
        const float4 g1v = *(const float4*)(g + gb + 4);
        const float4 b0 = *(const float4*)(be + gb);
        const float4 b1v = *(const float4*)(be + gb + 4);
        const float* vv = v + gg * 8;
        float y[8];
        y[0] = (vv[0] - mu) * inv * g0.x  + b0.x;
        y[1] = (vv[1] - mu) * inv * g0.y  + b0.y;
        y[2] = (vv[2] - mu) * inv * g0.z  + b0.z;
        y[3] = (vv[3] - mu) * inv * g0.w  + b0.w;
        y[4] = (vv[4] - mu) * inv * g1v.x + b1v.x;
        y[5] = (vv[5] - mu) * inv * g1v.y + b1v.y;
        y[6] = (vv[6] - mu) * inv * g1v.z + b1v.z;
        y[7] = (vv[7] - mu) * inv * g1v.w + b1v.w;
        float4 s0, s1;   // permuted storage: [y0,y4,y1,y5], [y2,y6,y3,y7]
        s0.x = to_tf32(y[0]); s0.y = to_tf32(y[4]);
        s0.z = to_tf32(y[1]); s0.w = to_tf32(y[5]);
        s1.x = to_tf32(y[2]); s1.y = to_tf32(y[6]);
        s1.z = to_tf32(y[3]); s1.w = to_tf32(y[7]);
        *(float4*)(out + row * Dv + gb)     = s0;
        *(float4*)(out + row * Dv + gb + 4) = s1;
    }
}

// LN2: inputs PERMUTED (h, ff2-out) -> output STANDARD.
__global__ void __launch_bounds__(256) residual_ln2(
    const float* __restrict__ a, const float* __restrict__ r,
    const float* __restrict__ g, const float* __restrict__ be,
    float* __restrict__ out)
{
    const size_t row = (size_t)blockIdx.x * 8 + (threadIdx.x >> 5);
    const int lane = threadIdx.x & 31;

    float v[32];   // logical order
    float s = 0.f, s2 = 0.f;
#pragma unroll
    for (int gg = 0; gg < 4; ++gg) {
        const int gb = (gg * 32 + lane) * 8;
        const float4 a0 = *(const float4*)(a + row * Dv + gb);      // [l0,l4,l1,l5]
        const float4 a1 = *(const float4*)(a + row * Dv + gb + 4);  // [l2,l6,l3,l7]
        const float4 r0 = *(const float4*)(r + row * Dv + gb);
        const float4 r1 = *(const float4*)(r + row * Dv + gb + 4);
        float* vv = v + gg * 8;
        vv[0] = a0.x + r0.x; vv[4] = a0.y + r0.y;
        vv[1] = a0.z + r0.z; vv[5] = a0.w + r0.w;
        vv[2] = a1.x + r1.x; vv[6] = a1.y + r1.y;
        vv[3] = a1.z + r1.z; vv[7] = a1.w + r1.w;
#pragma unroll
        for (int i = 0; i < 8; ++i) { s += vv[i]; s2 += vv[i] * vv[i]; }
    }
#pragma unroll
    for (int o_ = 16; o_ > 0; o_ >>= 1) {
        s  += __shfl_xor_sync(0xffffffffu, s,  o_);
        s2 += __shfl_xor_sync(0xffffffffu, s2, o_);
    }
    const float mu  = s * (1.0f / Dv);
    const float var = s2 * (1.0f / Dv) - mu * mu;
    const float inv = rsqrtf(var + LN_EPS);

#pragma unroll
    for (int gg = 0; gg < 4; ++gg) {
        const int gb = (gg * 32 + lane) * 8;
        const float4 g0 = *(const float4*)(g + gb);
        const float4 g1v = *(const float4*)(g + gb + 4);
        const float4 b0 = *(const float4*)(be + gb);
        const float4 b1v = *(const float4*)(be + gb + 4);
        const float* vv = v + gg * 8;
        float4 o0, o1;
        o0.x = (vv[0] - mu) * inv * g0.x  + b0.x;
        o0.y = (vv[1] - mu) * inv * g0.y  + b0.y;
        o0.z = (vv[2] - mu) * inv * g0.z  + b0.z;
        o0.w = (vv[3] - mu) * inv * g0.w  + b0.w;
        o1.x = (vv[4] - mu) * inv * g1v.x + b1v.x;
        o1.y = (vv[5] - mu) * inv * g1v.y + b1v.y;
        o1.z = (vv[6] - mu) * inv * g1v.z + b1v.z;
        o1.w = (vv[7] - mu) * inv * g1v.w + b1v.w;
        *(float4*)(out + row * Dv + gb)     = o0;
        *(float4*)(out + row * Dv + gb + 4) = o1;
    }
}

// ---------------------------------------------------------------------------
// Launch
// ---------------------------------------------------------------------------
extern "C" void kernel_launch(void* const* d_in, const int* in_sizes, int n_in,
                              void* d_out, int out_size)
{
    const float* x  = (const float*)d_in[0];
    const float* wq = (const float*)d_in[1];
    const float* bq = (const float*)d_in[2];
    const float* wk = (const float*)d_in[3];
    const float* bk = (const float*)d_in[4];
    const float* wv = (const float*)d_in[5];
    const float* bv = (const float*)d_in[6];
    const float* wo = (const float*)d_in[7];
    const float* bo = (const float*)d_in[8];
    const float* w1 = (const float*)d_in[9];
    const float* b1 = (const float*)d_in[10];
    const float* w2 = (const float*)d_in[11];
    const float* b2 = (const float*)d_in[12];
    const float* g1 = (const float*)d_in[13];
    const float* be1= (const float*)d_in[14];
    const float* g2 = (const float*)d_in[15];
    const float* be2= (const float*)d_in[16];
    float* out = (float*)d_out;

    float *qkv, *xr, *attn, *tmp, *tmp2, *h, *ff1, *wT, *bqkv;
    cudaGetSymbolAddress((void**)&qkv,  g_qkv);
    cudaGetSymbolAddress((void**)&xr,   g_xr);
    cudaGetSymbolAddress((void**)&attn, g_attn);
    cudaGetSymbolAddress((void**)&tmp,  g_tmp);
    cudaGetSymbolAddress((void**)&tmp2, g_tmp2);
    cudaGetSymbolAddress((void**)&h,    g_h);
    cudaGetSymbolAddress((void**)&ff1,  g_ff1);
    cudaGetSymbolAddress((void**)&wT,   g_wT);
    cudaGetSymbolAddress((void**)&bqkv, g_bqkv);

    const size_t MB1 = 1024 * 1024;
    float* wqkvT = wT;               // [3072][1024] q|k|v stacked, k-permuted
    float* woT   = wT + 3 * MB1;
    float* w1T   = wT + 4 * MB1;     // [F, D] k-permuted
    float* w2T   = wT + 8 * MB1;     // [D, F] k-permuted

    cudaFuncSetAttribute(gemm_mma<false, true,  true >,
        cudaFuncAttributeMaxDynamicSharedMemorySize, GSMEM_BYTES);
    cudaFuncSetAttribute(gemm_mma<false, false, false>,
        cudaFuncAttributeMaxDynamicSharedMemorySize, GSMEM_BYTES);
    cudaFuncSetAttribute(gemm_mma<true,  true,  true >,
        cudaFuncAttributeMaxDynamicSharedMemorySize, GSMEM_BYTES);
    cudaFuncSetAttribute(gemm_mma<false, false, true >,
        cudaFuncAttributeMaxDynamicSharedMemorySize, GSMEM_BYTES);
    cudaFuncSetAttribute(flash_attn,
        cudaFuncAttributeMaxDynamicSharedMemorySize, FA_SMEM_BYTES);

    // Weight prep (k-dim permuted)
    dim3 tb(32, 8);
    transpose4_tf32<<<dim3(Dv / 32, Dv / 32, 4), tb>>>(wq, wk, wv, wo, wqkvT);
    transpose_tf32<<<dim3(Fv / 32, Dv / 32), tb>>>(w1, w1T, Dv, Fv);
    transpose_tf32<<<dim3(Dv / 32, Fv / 32), tb>>>(w2, w2T, Fv, Dv);
    prep_x_bias<<<PREP_XBLKS + 3, 256>>>(x, xr, bq, bk, bv, bqkv);

    // Fused QKV projection -> qkv (permuted d-cols, tf32)
    gemm_mma<false, true, true><<<dim3(QS / 128, Mv / 128), 128, GSMEM_BYTES>>>(
        Dv, QS, xr, wqkvT, bqkv, qkv);

    // Flash attention -> attn (permuted, tf32)
    flash_attn<<<dim3(Sv / 128, Bv * Hv), 128, FA_SMEM_BYTES>>>(qkv, attn);

    const dim3 gDD(Dv / 128, Mv / 128);   // (8, 32)
    const dim3 gDF(Fv / 128, Mv / 128);   // (32, 32)

    // Output projection (standard out) + residual LN1 (permuted h, tf32)
    gemm_mma<false, false, false><<<gDD, 128, GSMEM_BYTES>>>(Dv, Dv, attn, woT, bo, tmp);
    residual_ln1<<<Mv / 8, 256>>>(x, tmp, g1, be1, h);

    // FFN (permuted chain) + residual LN2 (standard out)
    gemm_mma<true,  true,  true><<<gDF, 128, GSMEM_BYTES>>>(Dv, Fv, h, w1T, b1, ff1);
    gemm_mma<false, false, true><<<gDD, 128, GSMEM_BYTES>>>(Fv, Dv, ff1, w2T, b2, tmp2);
    residual_ln2<<<Mv / 8, 256>>>(h, tmp2, g2, be2, out);
}

// round 9
// speedup vs baseline: 7.0559x; 1.6938x over previous
#include <cuda_runtime.h>
#include <cuda_fp16.h>
#include <cstdint>

// Problem constants
#define Bv   2
#define Sv   2048
#define Dv   1024
#define Hv   16
#define DKv  64
#define Fv   4096
#define Mv   (Bv * Sv)      // 4096 rows
#define QS   3072           // qkv row stride (halves)
#define LN_EPS 1e-6f

// fp16 k-permutation: within each 16-group, pair p=(k&15)>>1 stored at slot
// perm8(p) = p<4 ? 2p : 2p-7 (pairs [0,1][8,9][2,3][10,11][4,5][12,13][6,7][14,15])
// -> mma m16n8k16 fragment quads (2c,2c+1,2c+8,2c+9) are contiguous = LDS.64.

// ---------------------------------------------------------------------------
// Scratch
// ---------------------------------------------------------------------------
__device__ __half g_qkv [(size_t)Mv * QS];            // q|k|v fp16, d perm16
__device__ __half g_xr  [(size_t)Mv * Dv];            // x fp16, perm16
__device__ __half g_attn[(size_t)Mv * Dv];            // flash out fp16, perm16
__device__ __half g_h   [(size_t)Mv * Dv];            // LN1 out fp16, perm16
__device__ float  g_hf  [(size_t)Mv * Dv];            // LN1 out fp32, standard
__device__ __half g_ff1 [(size_t)Mv * Fv];            // ff1 out fp16, perm16
__device__ __half g_vt  [(size_t)Bv * Dv * Sv];       // V transposed [b][d][jperm]
__device__ float  g_tmp [(size_t)Mv * Dv];            // wo out fp32 standard
__device__ float  g_tmp2[(size_t)Mv * Dv];            // ff2 out fp32 standard
__device__ __half g_w   [(size_t)12 * 1024 * 1024];   // fp16 weights, k perm16
__device__ float  g_bqkv[QS];

// ---------------------------------------------------------------------------
// Helpers
// ---------------------------------------------------------------------------
__device__ __forceinline__ uint32_t smem_u32(const void* p) {
    uint32_t a;
    asm("{ .reg .u64 t; cvta.to.shared.u64 t, %1; cvt.u32.u64 %0, t; }"
        : "=r"(a) : "l"(p));
    return a;
}
__device__ __forceinline__ int perm8i(int t) { return (t < 4) ? 2 * t : 2 * t - 7; }
__device__ __forceinline__ int kperm16(int k) {
    return (k & ~15) | (2 * perm8i((k & 15) >> 1) + (k & 1));
}
__device__ __forceinline__ uint32_t h2pack(float x, float y) {
    __half2 h = __floats2half2_rn(x, y);
    return *(uint32_t*)&h;
}
__device__ __forceinline__ void mma_f16(
    float* d, uint32_t a0, uint32_t a1, uint32_t a2, uint32_t a3,
    uint32_t b0, uint32_t b1)
{
    asm volatile(
        "mma.sync.aligned.m16n8k16.row.col.f32.f16.f16.f32 "
        "{%0,%1,%2,%3}, {%4,%5,%6,%7}, {%8,%9}, {%0,%1,%2,%3};"
        : "+f"(d[0]), "+f"(d[1]), "+f"(d[2]), "+f"(d[3])
        : "r"(a0), "r"(a1), "r"(a2), "r"(a3), "r"(b0), "r"(b1));
}

// ---------------------------------------------------------------------------
// Weight transposes -> fp16, k-dim perm16. WT[n][perm16(k)] = h(W[k][n])
// ---------------------------------------------------------------------------
__global__ void __launch_bounds__(256) transpose4_f16(
    const float* __restrict__ w0, const float* __restrict__ w1,
    const float* __restrict__ w2, const float* __restrict__ w3,
    __half* __restrict__ dst)
{
    const float* srcs[4] = { w0, w1, w2, w3 };
    const float* W = srcs[blockIdx.z];
    __half* WT = dst + (size_t)blockIdx.z * Dv * Dv;

    __shared__ float t[32][33];
    const int k0 = blockIdx.y * 32, n0 = blockIdx.x * 32;
    const int tx = threadIdx.x, ty0 = threadIdx.y;
#pragma unroll
    for (int i = 0; i < 4; ++i) {
        const int ty = ty0 + i * 8;
        t[ty][tx] = W[(size_t)(k0 + ty) * Dv + n0 + tx];
    }
    __syncthreads();
    const int txs = kperm16(tx);
#pragma unroll
    for (int i = 0; i < 4; ++i) {
        const int ty = ty0 + i * 8;
        WT[(size_t)(n0 + ty) * Dv + k0 + txs] = __float2half_rn(t[tx][ty]);
    }
}

__global__ void __launch_bounds__(256) transpose_f16(
    const float* __restrict__ W, __half* __restrict__ WT, int K, int N)
{
    __shared__ float t[32][33];
    const int k0 = blockIdx.y * 32, n0 = blockIdx.x * 32;
    const int tx = threadIdx.x, ty0 = threadIdx.y;
#pragma unroll
    for (int i = 0; i < 4; ++i) {
        const int ty = ty0 + i * 8;
        t[ty][tx] = W[(size_t)(k0 + ty) * N + n0 + tx];
    }
    __syncthreads();
    const int txs = kperm16(tx);
#pragma unroll
    for (int i = 0; i < 4; ++i) {
        const int ty = ty0 + i * 8;
        WT[(size_t)(n0 + ty) * K + k0 + txs] = __float2half_rn(t[tx][ty]);
    }
}

// ---------------------------------------------------------------------------
// prep: x (fp32) -> xr (fp16, perm16), + bias pack. Thread = one 16-group.
// Storage order: [l0,l1,l8,l9,l2,l3,l10,l11 | l4,l5,l12,l13,l6,l7,l14,l15]
// ---------------------------------------------------------------------------
#define PREP_XBLKS ((Mv * Dv / 16) / 256)   // 1024

__global__ void __launch_bounds__(256) prep_x_bias(
    const float* __restrict__ x, __half* __restrict__ y,
    const float* __restrict__ bq, const float* __restrict__ bk,
    const float* __restrict__ bv, float* __restrict__ bias)
{
    const int blk = blockIdx.x;
    if (blk < PREP_XBLKS) {
        const size_t base = ((size_t)blk * 256 + threadIdx.x) * 16;
        const float4 a = *(const float4*)(x + base);
        const float4 b = *(const float4*)(x + base + 4);
        const float4 cc = *(const float4*)(x + base + 8);
        const float4 d = *(const float4*)(x + base + 12);
        uint4 u0, u1;
        u0.x = h2pack(a.x, a.y);   u0.y = h2pack(cc.x, cc.y);
        u0.z = h2pack(a.z, a.w);   u0.w = h2pack(cc.z, cc.w);
        u1.x = h2pack(b.x, b.y);   u1.y = h2pack(d.x, d.y);
        u1.z = h2pack(b.z, b.w);   u1.w = h2pack(d.z, d.w);
        *(uint4*)(y + base)     = u0;
        *(uint4*)(y + base + 8) = u1;
    } else {
        const int j = blk - PREP_XBLKS;   // 0..2
        const float* src = (j == 0) ? bq : (j == 1) ? bk : bv;
        ((float4*)bias)[j * 256 + threadIdx.x] = ((const float4*)src)[threadIdx.x];
    }
}

// ---------------------------------------------------------------------------
// V transpose: qkv V-part [token][dperm] -> vt[b][dperm][jperm]
// ---------------------------------------------------------------------------
__global__ void __launch_bounds__(256) transpose_v(
    const __half* __restrict__ qkv, __half* __restrict__ vt)
{
    __shared__ __half t[64][66];
    const int j0 = blockIdx.x * 64, d0 = blockIdx.y * 64, b = blockIdx.z;
    const int tx = threadIdx.x, ty = threadIdx.y;   // 32 x 8

#pragma unroll
    for (int i = 0; i < 8; ++i) {
        const int j = ty + i * 8;
        const __half2 v = *(const __half2*)(
            qkv + (size_t)(b * Sv + j0 + j) * QS + 2048 + d0 + 2 * tx);
        t[2 * tx][j]     = __low2half(v);
        t[2 * tx + 1][j] = __high2half(v);
    }
    __syncthreads();
    const int js0 = kperm16(tx);
    const int js1 = kperm16(tx + 32);
#pragma unroll
    for (int i = 0; i < 8; ++i) {
        const int d = ty + i * 8;
        __half* dst = vt + ((size_t)b * Dv + d0 + d) * Sv + j0;
        dst[js0] = t[d][tx];
        dst[js1] = t[d][tx + 32];
    }
}

// ---------------------------------------------------------------------------
// fp16 tensor-core GEMM: C = A[M,K] @ WT[N,K]^T + bias.
// 4 warps, 64x64 warp tiles, BK=64 halves, 2-stage cp.async, stride 80 halves.
// HALFOUT: fp16 output with cols perm16'd. Else fp32 standard.
// ---------------------------------------------------------------------------
#define GBK 64
#define GSTR 80
#define GSM_H (128 * GSTR)
#define GSMEM_BYTES (4 * GSM_H * 2)   // 81920

template <bool RELU, bool HALFOUT>
__global__ void __launch_bounds__(128)
gemm_h(int K, int N, const __half* __restrict__ A,
       const __half* __restrict__ W, const float* __restrict__ bias,
       void* __restrict__ Cv)
{
    extern __shared__ __half smh[];
    const int m0 = blockIdx.y * 128;
    const int n0 = blockIdx.x * 128;
    const int tid  = threadIdx.x;
    const int lane = tid & 31;
    const int wid  = tid >> 5;
    const int wm = (wid >> 1) * 64;
    const int wn = (wid & 1) * 64;

    __half* tA[2] = { smh,           smh + 2 * GSM_H };
    __half* tB[2] = { smh + GSM_H,   smh + 3 * GSM_H };
    const uint32_t uA[2] = { smem_u32(tA[0]), smem_u32(tA[1]) };
    const uint32_t uB[2] = { smem_u32(tB[0]), smem_u32(tB[1]) };

    const __half* Ab = A + (size_t)m0 * K;
    const __half* Bb = W + (size_t)n0 * K;
    const int nk = K / GBK;

    float acc[4][8][4] = {};

    auto load_stage = [&](int buf, int kt) {
#pragma unroll
        for (int i = 0; i < 8; ++i) {
            const int s   = tid + i * 128;   // 0..1023
            const int row = s >> 3;
            const int f   = s & 7;
            const __half* ga = Ab + (size_t)row * K + kt * GBK + f * 8;
            const __half* gb = Bb + (size_t)row * K + kt * GBK + f * 8;
            const uint32_t da = uA[buf] + (uint32_t)(row * (GSTR * 2) + f * 16);
            const uint32_t db = uB[buf] + (uint32_t)(row * (GSTR * 2) + f * 16);
            asm volatile("cp.async.cg.shared.global [%0], [%1], 16;" :: "r"(da), "l"(ga));
            asm volatile("cp.async.cg.shared.global [%0], [%1], 16;" :: "r"(db), "l"(gb));
        }
    };

    load_stage(0, 0);
    asm volatile("cp.async.commit_group;" ::: "memory");

    const int r = lane >> 2;
    const int c = lane & 3;

    for (int kt = 0; kt < nk; ++kt) {
        const int buf = kt & 1;
        if (kt + 1 < nk) load_stage(buf ^ 1, kt + 1);
        asm volatile("cp.async.commit_group;" ::: "memory");
        asm volatile("cp.async.wait_group 1;" ::: "memory");
        __syncthreads();

        const __half* sa = tA[buf];
        const __half* sb = tB[buf];

#pragma unroll
        for (int kk = 0; kk < 4; ++kk) {           // 16-group within BK=64
            const int koff = kk * 16 + 4 * c;
            uint32_t afr[4][4];
            uint32_t bfr[8][2];
#pragma unroll
            for (int mt = 0; mt < 4; ++mt) {
                const __half* base = sa + (size_t)(wm + mt * 16 + r) * GSTR + koff;
                const uint2 u0 = *(const uint2*)base;
                const uint2 u8 = *(const uint2*)(base + 8 * GSTR);
                afr[mt][0] = u0.x; afr[mt][1] = u8.x;
                afr[mt][2] = u0.y; afr[mt][3] = u8.y;
            }
#pragma unroll
            for (int nt = 0; nt < 8; ++nt) {
                const uint2 bb = *(const uint2*)(
                    sb + (size_t)(wn + nt * 8 + r) * GSTR + koff);
                bfr[nt][0] = bb.x; bfr[nt][1] = bb.y;
            }
#pragma unroll
            for (int mt = 0; mt < 4; ++mt)
#pragma unroll
                for (int nt = 0; nt < 8; ++nt)
                    mma_f16(acc[mt][nt], afr[mt][0], afr[mt][1], afr[mt][2],
                            afr[mt][3], bfr[nt][0], bfr[nt][1]);
        }
        __syncthreads();
    }

#pragma unroll
    for (int mt = 0; mt < 4; ++mt) {
        const int rg = m0 + wm + mt * 16 + r;
#pragma unroll
        for (int nt = 0; nt < 8; ++nt) {
            const int cgb = n0 + wn + nt * 8;
            const float b0 = bias[cgb + 2 * c], b1 = bias[cgb + 2 * c + 1];
            float v00 = acc[mt][nt][0] + b0, v01 = acc[mt][nt][1] + b1;
            float v10 = acc[mt][nt][2] + b0, v11 = acc[mt][nt][3] + b1;
            if (RELU) {
                v00 = fmaxf(v00, 0.f); v01 = fmaxf(v01, 0.f);
                v10 = fmaxf(v10, 0.f); v11 = fmaxf(v11, 0.f);
            }
            if (HALFOUT) {
                __half* C = (__half*)Cv;
                const int off = n0 + wn + (nt >> 1) * 16 + 4 * c + (nt & 1) * 2;
                *(uint32_t*)(C + (size_t)rg * N + off)       = h2pack(v00, v01);
                *(uint32_t*)(C + (size_t)(rg + 8) * N + off) = h2pack(v10, v11);
            } else {
                float* C = (float*)Cv;
                float2 w0, w1;
                w0.x = v00; w0.y = v01; w1.x = v10; w1.y = v11;
                *(float2*)(C + (size_t)rg * N + cgb + 2 * c)       = w0;
                *(float2*)(C + (size_t)(rg + 8) * N + cgb + 2 * c) = w1;
            }
        }
    }
}

// ---------------------------------------------------------------------------
// fp16 flash attention. CTA = 128 Q rows of one (b,h); 4 warps x 32 rows.
// K tile [j][dperm], V tile (from vt) [dperm][jperm]; P fp16 jperm.
// Scores scaled by 0.125*log2(e) in fp32 post-MMA; base-2 online softmax.
// ---------------------------------------------------------------------------
#define FSTR 80
#define FA_SMEM_HALVES (4 * 64 * FSTR + 128 * FSTR)   // 30720
#define FA_SMEM_BYTES  (FA_SMEM_HALVES * 2)           // 61440

__global__ void __launch_bounds__(128, 2)
flash_attn(const __half* __restrict__ qkv, const __half* __restrict__ vt,
           __half* __restrict__ o)
{
    extern __shared__ __half fsh[];
    __half* Kt[2] = { fsh,               fsh + 64 * FSTR };
    __half* Vt[2] = { fsh + 2*64*FSTR,   fsh + 3*64*FSTR };
    __half* Pt    = fsh + 4*64*FSTR;

    const int bh = blockIdx.y;
    const int b  = bh >> 4;
    const int h  = bh & 15;
    const int i0 = blockIdx.x * 128;

    const int tid  = threadIdx.x;
    const int lane = tid & 31;
    const int wid  = tid >> 5;
    const int r = lane >> 2;
    const int c = lane & 3;

    const uint32_t uK[2] = { smem_u32(Kt[0]), smem_u32(Kt[1]) };
    const uint32_t uV[2] = { smem_u32(Vt[0]), smem_u32(Vt[1]) };
    __half* Pw = Pt + wid * 32 * FSTR;

    const float qscale = 0.125f * 1.4426950408889634f;

    // Q fragments (raw fp16; scaling folded into sacc post-MMA)
    uint32_t qa[2][4][4];
    {
        const __half* qb = qkv + (size_t)(b * Sv + i0 + wid * 32) * QS + h * DKv;
#pragma unroll
        for (int mt = 0; mt < 2; ++mt)
#pragma unroll
            for (int g = 0; g < 4; ++g) {
                const __half* q0 = qb + (size_t)(mt * 16 + r) * QS + g * 16 + 4 * c;
                const __half* q8 = q0 + (size_t)8 * QS;
                const uint2 u0 = *(const uint2*)q0;
                const uint2 u8 = *(const uint2*)q8;
                qa[mt][g][0] = u0.x; qa[mt][g][1] = u8.x;
                qa[mt][g][2] = u0.y; qa[mt][g][3] = u8.y;
            }
    }

    float oacc[2][8][4] = {};
    float mrow[4] = { -1e30f, -1e30f, -1e30f, -1e30f };
    float lrow[4] = { 0.f, 0.f, 0.f, 0.f };

    auto load_kv = [&](int buf, int jt) {
        const __half* kb = qkv + (size_t)(b * Sv + jt * 64) * QS + 1024 + h * DKv;
        const __half* vb = vt + ((size_t)b * Dv + h * DKv) * Sv + jt * 64;
#pragma unroll
        for (int i = 0; i < 4; ++i) {
            const int s   = tid + i * 128;   // 0..511
            const int row = s >> 3;          // 0..63
            const int f   = s & 7;
            const uint32_t dk_ = uK[buf] + (uint32_t)(row * (FSTR * 2) + f * 16);
            const uint32_t dv_ = uV[buf] + (uint32_t)(row * (FSTR * 2) + f * 16);
            asm volatile("cp.async.cg.shared.global [%0], [%1], 16;"
                         :: "r"(dk_), "l"(kb + (size_t)row * QS + f * 8));
            asm volatile("cp.async.cg.shared.global [%0], [%1], 16;"
                         :: "r"(dv_), "l"(vb + (size_t)row * Sv + f * 8));
        }
    };

    load_kv(0, 0);
    asm volatile("cp.async.commit_group;" ::: "memory");

    const int NT = Sv / 64;
    for (int jt = 0; jt < NT; ++jt) {
        const int buf = jt & 1;
        if (jt + 1 < NT) load_kv(buf ^ 1, jt + 1);
        asm volatile("cp.async.commit_group;" ::: "memory");
        asm volatile("cp.async.wait_group 1;" ::: "memory");
        __syncthreads();

        const __half* ks = Kt[buf];
        const __half* vs = Vt[buf];

        // ---- S = Q K^T ----
        float sacc[2][8][4] = {};
#pragma unroll
        for (int g = 0; g < 4; ++g) {
            const int koff = g * 16 + 4 * c;
#pragma unroll
            for (int nt = 0; nt < 8; ++nt) {
                const uint2 bb = *(const uint2*)(
                    ks + (size_t)(nt * 8 + r) * FSTR + koff);
                mma_f16(sacc[0][nt], qa[0][g][0], qa[0][g][1], qa[0][g][2],
                        qa[0][g][3], bb.x, bb.y);
                mma_f16(sacc[1][nt], qa[1][g][0], qa[1][g][1], qa[1][g][2],
                        qa[1][g][3], bb.x, bb.y);
            }
        }
#pragma unroll
        for (int mt = 0; mt < 2; ++mt)
#pragma unroll
            for (int nt = 0; nt < 8; ++nt) {
                sacc[mt][nt][0] *= qscale; sacc[mt][nt][1] *= qscale;
                sacc[mt][nt][2] *= qscale; sacc[mt][nt][3] *= qscale;
            }

        // ---- base-2 online softmax + fp16 P (jperm stores) ----
#pragma unroll
        for (int mt = 0; mt < 2; ++mt) {
            float tl = -1e30f, th = -1e30f;
#pragma unroll
            for (int nt = 0; nt < 8; ++nt) {
                tl = fmaxf(tl, fmaxf(sacc[mt][nt][0], sacc[mt][nt][1]));
                th = fmaxf(th, fmaxf(sacc[mt][nt][2], sacc[mt][nt][3]));
            }
            tl = fmaxf(tl, __shfl_xor_sync(0xffffffffu, tl, 1));
            tl = fmaxf(tl, __shfl_xor_sync(0xffffffffu, tl, 2));
            th = fmaxf(th, __shfl_xor_sync(0xffffffffu, th, 1));
            th = fmaxf(th, __shfl_xor_sync(0xffffffffu, th, 2));

            const float mnl = fmaxf(mrow[2 * mt],     tl);
            const float mnh = fmaxf(mrow[2 * mt + 1], th);
            const float crl = exp2f(mrow[2 * mt]     - mnl);
            const float crh = exp2f(mrow[2 * mt + 1] - mnh);

            float sl = 0.f, sh = 0.f;
            __half* prow0 = Pw + (size_t)(mt * 16 + r)     * FSTR;
            __half* prow8 = Pw + (size_t)(mt * 16 + r + 8) * FSTR;
#pragma unroll
            for (int nt = 0; nt < 8; ++nt) {
                const float p0 = exp2f(sacc[mt][nt][0] - mnl);
                const float p1 = exp2f(sacc[mt][nt][1] - mnl);
                const float p2 = exp2f(sacc[mt][nt][2] - mnh);
                const float p3 = exp2f(sacc[mt][nt][3] - mnh);
                sl += p0 + p1;
                sh += p2 + p3;
                const int off = (nt >> 1) * 16 + 4 * c + (nt & 1) * 2;
                *(uint32_t*)(prow0 + off) = h2pack(p0, p1);
                *(uint32_t*)(prow8 + off) = h2pack(p2, p3);
                oacc[mt][nt][0] *= crl; oacc[mt][nt][1] *= crl;
                oacc[mt][nt][2] *= crh; oacc[mt][nt][3] *= crh;
            }
            sl += __shfl_xor_sync(0xffffffffu, sl, 1);
            sl += __shfl_xor_sync(0xffffffffu, sl, 2);
            sh += __shfl_xor_sync(0xffffffffu, sh, 1);
            sh += __shfl_xor_sync(0xffffffffu, sh, 2);

            lrow[2 * mt]     = lrow[2 * mt]     * crl + sl;
            lrow[2 * mt + 1] = lrow[2 * mt + 1] * crh + sh;
            mrow[2 * mt]     = mnl;
            mrow[2 * mt + 1] = mnh;
        }
        __syncwarp();

        // ---- O += P V ----
#pragma unroll
        for (int g = 0; g < 4; ++g) {
            const int koff = g * 16 + 4 * c;
            uint32_t pa[2][4];
#pragma unroll
            for (int mt = 0; mt < 2; ++mt) {
                const __half* p0 = Pw + (size_t)(mt * 16 + r) * FSTR + koff;
                const uint2 u0 = *(const uint2*)p0;
                const uint2 u8 = *(const uint2*)(p0 + 8 * FSTR);
                pa[mt][0] = u0.x; pa[mt][1] = u8.x;
                pa[mt][2] = u0.y; pa[mt][3] = u8.y;
            }
#pragma unroll
            for (int nt = 0; nt < 8; ++nt) {
                const uint2 vv = *(const uint2*)(
                    vs + (size_t)(nt * 8 + r) * FSTR + koff);
                mma_f16(oacc[0][nt], pa[0][0], pa[0][1], pa[0][2], pa[0][3],
                        vv.x, vv.y);
                mma_f16(oacc[1][nt], pa[1][0], pa[1][1], pa[1][2], pa[1][3],
                        vv.x, vv.y);
            }
        }
        __syncthreads();
    }

    // ---- epilogue: normalize, fp16 store (cols already dperm) ----
#pragma unroll
    for (int mt = 0; mt < 2; ++mt) {
        const float inv_lo = 1.0f / lrow[2 * mt];
        const float inv_hi = 1.0f / lrow[2 * mt + 1];
        const size_t row_lo = (size_t)(b * Sv + i0 + wid * 32 + mt * 16 + r);
#pragma unroll
        for (int nt = 0; nt < 8; ++nt) {
            const int col = h * DKv + nt * 8 + 2 * c;
            *(uint32_t*)(o + row_lo * Dv + col) =
                h2pack(oacc[mt][nt][0] * inv_lo, oacc[mt][nt][1] * inv_lo);
            *(uint32_t*)(o + (row_lo + 8) * Dv + col) =
                h2pack(oacc[mt][nt][2] * inv_hi, oacc[mt][nt][3] * inv_hi);
        }
    }
}

// ---------------------------------------------------------------------------
// LN1: (x + wo-out), both fp32 standard -> h fp16 perm16 + h fp32 standard.
// Warp per row.
// ---------------------------------------------------------------------------
__global__ void __launch_bounds__(256) residual_ln1(
    const float* __restrict__ a, const float* __restrict__ r,
    const float* __restrict__ g, const float* __restrict__ be,
    __half* __restrict__ outh, float* __restrict__ outf)
{
    const size_t row = (size_t)blockIdx.x * 8 + (threadIdx.x >> 5);
    const int lane = threadIdx.x & 31;

    float v[32];
    float s = 0.f, s2 = 0.f;
#pragma unroll
    for (int gg = 0; gg < 4; ++gg) {
        const int gb = (gg * 32 + lane) * 8;
        const float4 a0 = *(const float4*)(a + row * Dv + gb);
        const float4 a1 = *(const float4*)(a + row * Dv + gb + 4);
        const float4 r0 = *(const float4*)(r + row * Dv + gb);
        const float4 r1 = *(const float4*)(r + row * Dv + gb + 4);
        float* vv = v + gg * 8;
        vv[0] = a0.x + r0.x; vv[1] = a0.y + r0.y; vv[2] = a0.z + r0.z; vv[3] = a0.w + r0.w;
        vv[4] = a1.x + r1.x; vv[5] = a1.y + r1.y; vv[6] = a1.z + r1.z; vv[7] = a1.w + r1.w;
#pragma unroll
        for (int i = 0; i < 8; ++i) { s += vv[i]; s2 += vv[i] * vv[i]; }
    }
#pragma unroll
    for (int o_ = 16; o_ > 0; o_ >>= 1) {
        s  += __shfl_xor_sync(0xffffffffu, s,  o_);
        s2 += __shfl_xor_sync(0xffffffffu, s2, o_);
    }
    const float mu  = s * (1.0f / Dv);
    const float var = s2 * (1.0f / Dv) - mu * mu;
    const float inv = rsqrtf(var + LN_EPS);

#pragma unroll
    for (int gg = 0; gg < 4; ++gg) {
        const int G  = gg * 32 + lane;
        const int gb = G * 8;
        const float4 g0 = *(const float4*)(g + gb);
        const float4 g1v = *(const float4*)(g + gb + 4);
        const float4 b0 = *(const float4*)(be + gb);
        const float4 b1v = *(const float4*)(be + gb + 4);
        const float* vv = v + gg * 8;
        float y[8];
        y[0] = (vv[0] - mu) * inv * g0.x  + b0.x;
        y[1] = (vv[1] - mu) * inv * g0.y  + b0.y;
        y[2] = (vv[2] - mu) * inv * g0.z  + b0.z;
        y[3] = (vv[3] - mu) * inv * g0.w  + b0.w;
        y[4] = (vv[4] - mu) * inv * g1v.x + b1v.x;
        y[5] = (vv[5] - mu) * inv * g1v.y + b1v.y;
        y[6] = (vv[6] - mu) * inv * g1v.z + b1v.z;
        y[7] = (vv[7] - mu) * inv * g1v.w + b1v.w;
        // fp32 standard
        float4 o0, o1;
        o0.x = y[0]; o0.y = y[1]; o0.z = y[2]; o0.w = y[3];
        o1.x = y[4]; o1.y = y[5]; o1.z = y[6]; o1.w = y[7];
        *(float4*)(outf + row * Dv + gb)     = o0;
        *(float4*)(outf + row * Dv + gb + 4) = o1;
        // fp16 perm16: 8-group G -> 16-group G>>1; pair slots
        __half* hb = outh + row * Dv + (G >> 1) * 16 + (G & 1) * 2;
        *(uint32_t*)(hb + 0)  = h2pack(y[0], y[1]);
        *(uint32_t*)(hb + 4)  = h2pack(y[2], y[3]);
        *(uint32_t*)(hb + 8)  = h2pack(y[4], y[5]);
        *(uint32_t*)(hb + 12) = h2pack(y[6], y[7]);
    }
}

// LN2: (h fp32 + ff2 fp32), both standard -> out fp32 standard. Warp per row.
__global__ void __launch_bounds__(256) residual_ln2(
    const float* __restrict__ a, const float* __restrict__ r,
    const float* __restrict__ g, const float* __restrict__ be,
    float* __restrict__ out)
{
    const size_t row = (size_t)blockIdx.x * 8 + (threadIdx.x >> 5);
    const int lane = threadIdx.x & 31;

    float v[32];
    float s = 0.f, s2 = 0.f;
#pragma unroll
    for (int gg = 0; gg < 4; ++gg) {
        const int gb = (gg * 32 + lane) * 8;
        const float4 a0 = *(const float4*)(a + row * Dv + gb);
        const float4 a1 = *(const float4*)(a + row * Dv + gb + 4);
        const float4 r0 = *(const float4*)(r + row * Dv + gb);
        const float4 r1 = *(const float4*)(r + row * Dv + gb + 4);
        float* vv = v + gg * 8;
        vv[0] = a0.x + r0.x; vv[1] = a0.y + r0.y; vv[2] = a0.z + r0.z; vv[3] = a0.w + r0.w;
        vv[4] = a1.x + r1.x; vv[5] = a1.y + r1.y; vv[6] = a1.z + r1.z; vv[7] = a1.w + r1.w;
#pragma unroll
        for (int i = 0; i < 8; ++i) { s += vv[i]; s2 += vv[i] * vv[i]; }
    }
#pragma unroll
    for (int o_ = 16; o_ > 0; o_ >>= 1) {
        s  += __shfl_xor_sync(0xffffffffu, s,  o_);
        s2 += __shfl_xor_sync(0xffffffffu, s2, o_);
    }
    const float mu  = s * (1.0f / Dv);
    const float var = s2 * (1.0f / Dv) - mu * mu;
    const float inv = rsqrtf(var + LN_EPS);

#pragma unroll
    for (int gg = 0; gg < 4; ++gg) {
        const int gb = (gg * 32 + lane) * 8;
        const float4 g0 = *(const float4*)(g + gb);
        const float4 g1v = *(const float4*)(g + gb + 4);
        const float4 b0 = *(const float4*)(be + gb);
        const float4 b1v = *(const float4*)(be + gb + 4);
        const float* vv = v + gg * 8;
        float4 o0, o1;
        o0.x = (vv[0] - mu) * inv * g0.x  + b0.x;
        o0.y = (vv[1] - mu) * inv * g0.y  + b0.y;
        o0.z = (vv[2] - mu) * inv * g0.z  + b0.z;
        o0.w = (vv[3] - mu) * inv * g0.w  + b0.w;
        o1.x = (vv[4] - mu) * inv * g1v.x + b1v.x;
        o1.y = (vv[5] - mu) * inv * g1v.y + b1v.y;
        o1.z = (vv[6] - mu) * inv * g1v.z + b1v.z;
        o1.w = (vv[7] - mu) * inv * g1v.w + b1v.w;
        *(float4*)(out + row * Dv + gb)     = o0;
        *(float4*)(out + row * Dv + gb + 4) = o1;
    }
}

// ---------------------------------------------------------------------------
// Launch
// ---------------------------------------------------------------------------
extern "C" void kernel_launch(void* const* d_in, const int* in_sizes, int n_in,
                              void* d_out, int out_size)
{
    const float* x  = (const float*)d_in[0];
    const float* wq = (const float*)d_in[1];
    const float* bq = (const float*)d_in[2];
    const float* wk = (const float*)d_in[3];
    const float* bk = (const float*)d_in[4];
    const float* wv = (const float*)d_in[5];
    const float* bv = (const float*)d_in[6];
    const float* wo = (const float*)d_in[7];
    const float* bo = (const float*)d_in[8];
    const float* w1 = (const float*)d_in[9];
    const float* b1 = (const float*)d_in[10];
    const float* w2 = (const float*)d_in[11];
    const float* b2 = (const float*)d_in[12];
    const float* g1 = (const float*)d_in[13];
    const float* be1= (const float*)d_in[14];
    const float* g2 = (const float*)d_in[15];
    const float* be2= (const float*)d_in[16];
    float* out = (float*)d_out;

    __half *qkv, *xr, *attn, *hh, *ff1, *vt, *wh;
    float *hf, *tmp, *tmp2, *bqkv;
    cudaGetSymbolAddress((void**)&qkv,  g_qkv);
    cudaGetSymbolAddress((void**)&xr,   g_xr);
    cudaGetSymbolAddress((void**)&attn, g_attn);
    cudaGetSymbolAddress((void**)&hh,   g_h);
    cudaGetSymbolAddress((void**)&hf,   g_hf);
    cudaGetSymbolAddress((void**)&ff1,  g_ff1);
    cudaGetSymbolAddress((void**)&vt,   g_vt);
    cudaGetSymbolAddress((void**)&wh,   g_w);
    cudaGetSymbolAddress((void**)&tmp,  g_tmp);
    cudaGetSymbolAddress((void**)&tmp2, g_tmp2);
    cudaGetSymbolAddress((void**)&bqkv, g_bqkv);

    const size_t MB1 = 1024 * 1024;
    __half* wqkvT = wh;               // [3072][1024]
    __half* woT   = wh + 3 * MB1;
    __half* w1T   = wh + 4 * MB1;     // [F, D]
    __half* w2T   = wh + 8 * MB1;     // [D, F]

    cudaFuncSetAttribute(gemm_h<false, true >,
        cudaFuncAttributeMaxDynamicSharedMemorySize, GSMEM_BYTES);
    cudaFuncSetAttribute(gemm_h<false, false>,
        cudaFuncAttributeMaxDynamicSharedMemorySize, GSMEM_BYTES);
    cudaFuncSetAttribute(gemm_h<true,  true >,
        cudaFuncAttributeMaxDynamicSharedMemorySize, GSMEM_BYTES);
    cudaFuncSetAttribute(flash_attn,
        cudaFuncAttributeMaxDynamicSharedMemorySize, FA_SMEM_BYTES);

    // Weight + input prep
    dim3 tb(32, 8);
    transpose4_f16<<<dim3(Dv / 32, Dv / 32, 4), tb>>>(wq, wk, wv, wo, wqkvT);
    transpose_f16<<<dim3(Fv / 32, Dv / 32), tb>>>(w1, w1T, Dv, Fv);
    transpose_f16<<<dim3(Dv / 32, Fv / 32), tb>>>(w2, w2T, Fv, Dv);
    prep_x_bias<<<PREP_XBLKS + 3, 256>>>(x, xr, bq, bk, bv, bqkv);

    // QKV projection -> qkv fp16 (cols perm16)
    gemm_h<false, true><<<dim3(QS / 128, Mv / 128), 128, GSMEM_BYTES>>>(
        Dv, QS, xr, wqkvT, bqkv, qkv);

    // V transpose for fp16 PV fragments
    transpose_v<<<dim3(Sv / 64, Dv / 64, Bv), tb>>>(qkv, vt);

    // Flash attention -> attn fp16 (dperm)
    flash_attn<<<dim3(Sv / 128, Bv * Hv), 128, FA_SMEM_BYTES>>>(qkv, vt, attn);

    const dim3 gDD(Dv / 128, Mv / 128);   // (8, 32)
    const dim3 gDF(Fv / 128, Mv / 128);   // (32, 32)

    // Output projection (fp32 standard) + LN1 (dual output)
    gemm_h<false, false><<<gDD, 128, GSMEM_BYTES>>>(Dv, Dv, attn, woT, bo, tmp);
    residual_ln1<<<Mv / 8, 256>>>(x, tmp, g1, be1, hh, hf);

    // FFN + LN2
    gemm_h<true,  true ><<<gDF, 128, GSMEM_BYTES>>>(Dv, Fv, hh, w1T, b1, ff1);
    gemm_h<false, false><<<gDD, 128, GSMEM_BYTES>>>(Fv, Dv, ff1, w2T, b2, tmp2);
    residual_ln2<<<Mv / 8, 256>>>(hf, tmp2, g2, be2, out);
}

// round 10
// speedup vs baseline: 7.1596x; 1.0147x over previous
#include <cuda_runtime.h>
#include <cuda_fp16.h>
#include <cstdint>

// Problem constants
#define Bv   2
#define Sv   2048
#define Dv   1024
#define Hv   16
#define DKv  64
#define Fv   4096
#define Mv   (Bv * Sv)      // 4096 rows
#define QS   3072           // qkv row stride (halves)
#define LN_EPS 1e-6f
#define QSCALE_F (0.125f * 1.4426950408889634f)

// fp16 k-permutation: within each 16-group, pair p=(k&15)>>1 stored at slot
// perm8(p) = p<4 ? 2p : 2p-7 -> mma fragment quads contiguous = LDS.64.

// ---------------------------------------------------------------------------
// Scratch
// ---------------------------------------------------------------------------
__device__ __half g_qkv [(size_t)Mv * QS];            // q|k|v fp16, d perm16 (q pre-scaled)
__device__ __half g_xr  [(size_t)Mv * Dv];            // x fp16, perm16
__device__ __half g_attn[(size_t)Mv * Dv];            // flash out fp16, perm16
__device__ __half g_h   [(size_t)Mv * Dv];            // LN1 out fp16, perm16
__device__ float  g_hf  [(size_t)Mv * Dv];            // LN1 out fp32, standard
__device__ __half g_ff1 [(size_t)Mv * Fv];            // ff1 out fp16, perm16
__device__ __half g_vt  [(size_t)Bv * Dv * Sv];       // V transposed [b][d][jperm]
__device__ float  g_tmp [(size_t)Mv * Dv];            // wo out fp32 standard
__device__ float  g_tmp2[(size_t)Mv * Dv];            // ff2 out fp32 standard
__device__ __half g_w   [(size_t)12 * 1024 * 1024];   // fp16 weights, k perm16
__device__ float  g_bqkv[QS];

// ---------------------------------------------------------------------------
// Helpers
// ---------------------------------------------------------------------------
__device__ __forceinline__ uint32_t smem_u32(const void* p) {
    uint32_t a;
    asm("{ .reg .u64 t; cvta.to.shared.u64 t, %1; cvt.u32.u64 %0, t; }"
        : "=r"(a) : "l"(p));
    return a;
}
__device__ __forceinline__ int perm8i(int t) { return (t < 4) ? 2 * t : 2 * t - 7; }
__device__ __forceinline__ int kperm16(int k) {
    return (k & ~15) | (2 * perm8i((k & 15) >> 1) + (k & 1));
}
__device__ __forceinline__ uint32_t h2pack(float x, float y) {
    __half2 h = __floats2half2_rn(x, y);
    return *(uint32_t*)&h;
}
__device__ __forceinline__ void mma_f16(
    float* d, uint32_t a0, uint32_t a1, uint32_t a2, uint32_t a3,
    uint32_t b0, uint32_t b1)
{
    asm volatile(
        "mma.sync.aligned.m16n8k16.row.col.f32.f16.f16.f32 "
        "{%0,%1,%2,%3}, {%4,%5,%6,%7}, {%8,%9}, {%0,%1,%2,%3};"
        : "+f"(d[0]), "+f"(d[1]), "+f"(d[2]), "+f"(d[3])
        : "r"(a0), "r"(a1), "r"(a2), "r"(a3), "r"(b0), "r"(b1));
}

// ---------------------------------------------------------------------------
// Weight transposes -> fp16, k-dim perm16. WT[n][perm16(k)] = h(W[k][n])
// ---------------------------------------------------------------------------
__global__ void __launch_bounds__(256) transpose4_f16(
    const float* __restrict__ w0, const float* __restrict__ w1,
    const float* __restrict__ w2, const float* __restrict__ w3,
    __half* __restrict__ dst)
{
    const float* srcs[4] = { w0, w1, w2, w3 };
    const float* W = srcs[blockIdx.z];
    __half* WT = dst + (size_t)blockIdx.z * Dv * Dv;

    __shared__ float t[32][33];
    const int k0 = blockIdx.y * 32, n0 = blockIdx.x * 32;
    const int tx = threadIdx.x, ty0 = threadIdx.y;
#pragma unroll
    for (int i = 0; i < 4; ++i) {
        const int ty = ty0 + i * 8;
        t[ty][tx] = W[(size_t)(k0 + ty) * Dv + n0 + tx];
    }
    __syncthreads();
    const int txs = kperm16(tx);
#pragma unroll
    for (int i = 0; i < 4; ++i) {
        const int ty = ty0 + i * 8;
        WT[(size_t)(n0 + ty) * Dv + k0 + txs] = __float2half_rn(t[tx][ty]);
    }
}

__global__ void __launch_bounds__(256) transpose_f16(
    const float* __restrict__ W, __half* __restrict__ WT, int K, int N)
{
    __shared__ float t[32][33];
    const int k0 = blockIdx.y * 32, n0 = blockIdx.x * 32;
    const int tx = threadIdx.x, ty0 = threadIdx.y;
#pragma unroll
    for (int i = 0; i < 4; ++i) {
        const int ty = ty0 + i * 8;
        t[ty][tx] = W[(size_t)(k0 + ty) * N + n0 + tx];
    }
    __syncthreads();
    const int txs = kperm16(tx);
#pragma unroll
    for (int i = 0; i < 4; ++i) {
        const int ty = ty0 + i * 8;
        WT[(size_t)(n0 + ty) * K + k0 + txs] = __float2half_rn(t[tx][ty]);
    }
}

// ---------------------------------------------------------------------------
// prep: x (fp32) -> xr (fp16, perm16), + bias pack. Thread = one 16-group.
// ---------------------------------------------------------------------------
#define PREP_XBLKS ((Mv * Dv / 16) / 256)   // 1024

__global__ void __launch_bounds__(256) prep_x_bias(
    const float* __restrict__ x, __half* __restrict__ y,
    const float* __restrict__ bq, const float* __restrict__ bk,
    const float* __restrict__ bv, float* __restrict__ bias)
{
    const int blk = blockIdx.x;
    if (blk < PREP_XBLKS) {
        const size_t base = ((size_t)blk * 256 + threadIdx.x) * 16;
        const float4 a = *(const float4*)(x + base);
        const float4 b = *(const float4*)(x + base + 4);
        const float4 cc = *(const float4*)(x + base + 8);
        const float4 d = *(const float4*)(x + base + 12);
        uint4 u0, u1;
        u0.x = h2pack(a.x, a.y);   u0.y = h2pack(cc.x, cc.y);
        u0.z = h2pack(a.z, a.w);   u0.w = h2pack(cc.z, cc.w);
        u1.x = h2pack(b.x, b.y);   u1.y = h2pack(d.x, d.y);
        u1.z = h2pack(b.z, b.w);   u1.w = h2pack(d.z, d.w);
        *(uint4*)(y + base)     = u0;
        *(uint4*)(y + base + 8) = u1;
    } else {
        const int j = blk - PREP_XBLKS;   // 0..2
        const float* src = (j == 0) ? bq : (j == 1) ? bk : bv;
        ((float4*)bias)[j * 256 + threadIdx.x] = ((const float4*)src)[threadIdx.x];
    }
}

// ---------------------------------------------------------------------------
// V transpose: qkv V-part [token][dperm] -> vt[b][dperm][jperm]
// ---------------------------------------------------------------------------
__global__ void __launch_bounds__(256) transpose_v(
    const __half* __restrict__ qkv, __half* __restrict__ vt)
{
    __shared__ __half t[64][66];
    const int j0 = blockIdx.x * 64, d0 = blockIdx.y * 64, b = blockIdx.z;
    const int tx = threadIdx.x, ty = threadIdx.y;   // 32 x 8

#pragma unroll
    for (int i = 0; i < 8; ++i) {
        const int j = ty + i * 8;
        const __half2 v = *(const __half2*)(
            qkv + (size_t)(b * Sv + j0 + j) * QS + 2048 + d0 + 2 * tx);
        t[2 * tx][j]     = __low2half(v);
        t[2 * tx + 1][j] = __high2half(v);
    }
    __syncthreads();
    const int js0 = kperm16(tx);
    const int js1 = kperm16(tx + 32);
#pragma unroll
    for (int i = 0; i < 8; ++i) {
        const int d = ty + i * 8;
        __half* dst = vt + ((size_t)b * Dv + d0 + d) * Sv + j0;
        dst[js0] = t[d][tx];
        dst[js1] = t[d][tx + 32];
    }
}

// ---------------------------------------------------------------------------
// fp16 tensor-core GEMM: C = A[M,K] @ WT[N,K]^T + bias.
// 4 warps, 64x64 warp tiles, BK=64 halves, 2-stage cp.async, stride 80 halves.
// SINGLE barrier per k-tile: wait -> sync -> issue next load -> compute.
// QSC: scale q columns (col < 1024) by QSCALE_F in the epilogue.
// ---------------------------------------------------------------------------
#define GBK 64
#define GSTR 80
#define GSM_H (128 * GSTR)
#define GSMEM_BYTES (4 * GSM_H * 2)   // 81920

template <bool RELU, bool HALFOUT, bool QSC>
__global__ void __launch_bounds__(128)
gemm_h(int K, int N, const __half* __restrict__ A,
       const __half* __restrict__ W, const float* __restrict__ bias,
       void* __restrict__ Cv)
{
    extern __shared__ __half smh[];
    const int m0 = blockIdx.y * 128;
    const int n0 = blockIdx.x * 128;
    const int tid  = threadIdx.x;
    const int lane = tid & 31;
    const int wid  = tid >> 5;
    const int wm = (wid >> 1) * 64;
    const int wn = (wid & 1) * 64;

    __half* tA[2] = { smh,           smh + 2 * GSM_H };
    __half* tB[2] = { smh + GSM_H,   smh + 3 * GSM_H };
    const uint32_t uA[2] = { smem_u32(tA[0]), smem_u32(tA[1]) };
    const uint32_t uB[2] = { smem_u32(tB[0]), smem_u32(tB[1]) };

    const __half* Ab = A + (size_t)m0 * K;
    const __half* Bb = W + (size_t)n0 * K;
    const int nk = K / GBK;

    float acc[4][8][4] = {};

    auto load_stage = [&](int buf, int kt) {
#pragma unroll
        for (int i = 0; i < 8; ++i) {
            const int s   = tid + i * 128;   // 0..1023
            const int row = s >> 3;
            const int f   = s & 7;
            const __half* ga = Ab + (size_t)row * K + kt * GBK + f * 8;
            const __half* gb = Bb + (size_t)row * K + kt * GBK + f * 8;
            const uint32_t da = uA[buf] + (uint32_t)(row * (GSTR * 2) + f * 16);
            const uint32_t db = uB[buf] + (uint32_t)(row * (GSTR * 2) + f * 16);
            asm volatile("cp.async.cg.shared.global [%0], [%1], 16;" :: "r"(da), "l"(ga));
            asm volatile("cp.async.cg.shared.global [%0], [%1], 16;" :: "r"(db), "l"(gb));
        }
        asm volatile("cp.async.commit_group;" ::: "memory");
    };

    load_stage(0, 0);

    const int r = lane >> 2;
    const int c = lane & 3;

    for (int kt = 0; kt < nk; ++kt) {
        const int buf = kt & 1;
        // stage kt is the only outstanding group
        asm volatile("cp.async.wait_group 0;" ::: "memory");
        __syncthreads();   // stage ready; all warps done reading buf^1 (kt-1)
        if (kt + 1 < nk) load_stage(buf ^ 1, kt + 1);

        const __half* sa = tA[buf];
        const __half* sb = tB[buf];

#pragma unroll
        for (int kk = 0; kk < 4; ++kk) {           // 16-group within BK=64
            const int koff = kk * 16 + 4 * c;
            uint32_t afr[4][4];
            uint32_t bfr[8][2];
#pragma unroll
            for (int mt = 0; mt < 4; ++mt) {
                const __half* base = sa + (size_t)(wm + mt * 16 + r) * GSTR + koff;
                const uint2 u0 = *(const uint2*)base;
                const uint2 u8 = *(const uint2*)(base + 8 * GSTR);
                afr[mt][0] = u0.x; afr[mt][1] = u8.x;
                afr[mt][2] = u0.y; afr[mt][3] = u8.y;
            }
#pragma unroll
            for (int nt = 0; nt < 8; ++nt) {
                const uint2 bb = *(const uint2*)(
                    sb + (size_t)(wn + nt * 8 + r) * GSTR + koff);
                bfr[nt][0] = bb.x; bfr[nt][1] = bb.y;
            }
#pragma unroll
            for (int mt = 0; mt < 4; ++mt)
#pragma unroll
                for (int nt = 0; nt < 8; ++nt)
                    mma_f16(acc[mt][nt], afr[mt][0], afr[mt][1], afr[mt][2],
                            afr[mt][3], bfr[nt][0], bfr[nt][1]);
        }
    }

#pragma unroll
    for (int mt = 0; mt < 4; ++mt) {
        const int rg = m0 + wm + mt * 16 + r;
#pragma unroll
        for (int nt = 0; nt < 8; ++nt) {
            const int cgb = n0 + wn + nt * 8;
            const float b0 = bias[cgb + 2 * c], b1 = bias[cgb + 2 * c + 1];
            float v00 = acc[mt][nt][0] + b0, v01 = acc[mt][nt][1] + b1;
            float v10 = acc[mt][nt][2] + b0, v11 = acc[mt][nt][3] + b1;
            if (RELU) {
                v00 = fmaxf(v00, 0.f); v01 = fmaxf(v01, 0.f);
                v10 = fmaxf(v10, 0.f); v11 = fmaxf(v11, 0.f);
            }
            if (QSC && cgb < 1024) {   // q columns: fold softmax scale
                v00 *= QSCALE_F; v01 *= QSCALE_F;
                v10 *= QSCALE_F; v11 *= QSCALE_F;
            }
            if (HALFOUT) {
                __half* C = (__half*)Cv;
                const int off = n0 + wn + (nt >> 1) * 16 + 4 * c + (nt & 1) * 2;
                *(uint32_t*)(C + (size_t)rg * N + off)       = h2pack(v00, v01);
                *(uint32_t*)(C + (size_t)(rg + 8) * N + off) = h2pack(v10, v11);
            } else {
                float* C = (float*)Cv;
                float2 w0, w1;
                w0.x = v00; w0.y = v01; w1.x = v10; w1.y = v11;
                *(float2*)(C + (size_t)rg * N + cgb + 2 * c)       = w0;
                *(float2*)(C + (size_t)(rg + 8) * N + cgb + 2 * c) = w1;
            }
        }
    }
}

// ---------------------------------------------------------------------------
// fp16 flash attention. CTA = 128 Q rows of one (b,h); 4 warps x 32 rows.
// Q pre-scaled (QKV epilogue) -> scores are already in base-2 log domain.
// SINGLE barrier per KV tile.
// ---------------------------------------------------------------------------
#define FSTR 80
#define FA_SMEM_HALVES (4 * 64 * FSTR + 128 * FSTR)   // 30720
#define FA_SMEM_BYTES  (FA_SMEM_HALVES * 2)           // 61440

__global__ void __launch_bounds__(128, 2)
flash_attn(const __half* __restrict__ qkv, const __half* __restrict__ vt,
           __half* __restrict__ o)
{
    extern __shared__ __half fsh[];
    __half* Kt[2] = { fsh,               fsh + 64 * FSTR };
    __half* Vt[2] = { fsh + 2*64*FSTR,   fsh + 3*64*FSTR };
    __half* Pt    = fsh + 4*64*FSTR;

    const int bh = blockIdx.y;
    const int b  = bh >> 4;
    const int h  = bh & 15;
    const int i0 = blockIdx.x * 128;

    const int tid  = threadIdx.x;
    const int lane = tid & 31;
    const int wid  = tid >> 5;
    const int r = lane >> 2;
    const int c = lane & 3;

    const uint32_t uK[2] = { smem_u32(Kt[0]), smem_u32(Kt[1]) };
    const uint32_t uV[2] = { smem_u32(Vt[0]), smem_u32(Vt[1]) };
    __half* Pw = Pt + wid * 32 * FSTR;

    // Q fragments (already scaled by 0.125*log2e at QKV epilogue)
    uint32_t qa[2][4][4];
    {
        const __half* qb = qkv + (size_t)(b * Sv + i0 + wid * 32) * QS + h * DKv;
#pragma unroll
        for (int mt = 0; mt < 2; ++mt)
#pragma unroll
            for (int g = 0; g < 4; ++g) {
                const __half* q0 = qb + (size_t)(mt * 16 + r) * QS + g * 16 + 4 * c;
                const __half* q8 = q0 + (size_t)8 * QS;
                const uint2 u0 = *(const uint2*)q0;
                const uint2 u8 = *(const uint2*)q8;
                qa[mt][g][0] = u0.x; qa[mt][g][1] = u8.x;
                qa[mt][g][2] = u0.y; qa[mt][g][3] = u8.y;
            }
    }

    float oacc[2][8][4] = {};
    float mrow[4] = { -1e30f, -1e30f, -1e30f, -1e30f };
    float lrow[4] = { 0.f, 0.f, 0.f, 0.f };

    auto load_kv = [&](int buf, int jt) {
        const __half* kb = qkv + (size_t)(b * Sv + jt * 64) * QS + 1024 + h * DKv;
        const __half* vb = vt + ((size_t)b * Dv + h * DKv) * Sv + jt * 64;
#pragma unroll
        for (int i = 0; i < 4; ++i) {
            const int s   = tid + i * 128;   // 0..511
            const int row = s >> 3;          // 0..63
            const int f   = s & 7;
            const uint32_t dk_ = uK[buf] + (uint32_t)(row * (FSTR * 2) + f * 16);
            const uint32_t dv_ = uV[buf] + (uint32_t)(row * (FSTR * 2) + f * 16);
            asm volatile("cp.async.cg.shared.global [%0], [%1], 16;"
                         :: "r"(dk_), "l"(kb + (size_t)row * QS + f * 8));
            asm volatile("cp.async.cg.shared.global [%0], [%1], 16;"
                         :: "r"(dv_), "l"(vb + (size_t)row * Sv + f * 8));
        }
        asm volatile("cp.async.commit_group;" ::: "memory");
    };

    load_kv(0, 0);

    const int NT = Sv / 64;
    for (int jt = 0; jt < NT; ++jt) {
        const int buf = jt & 1;
        asm volatile("cp.async.wait_group 0;" ::: "memory");
        __syncthreads();   // tile ready; all warps done with buf^1
        if (jt + 1 < NT) load_kv(buf ^ 1, jt + 1);

        const __half* ks = Kt[buf];
        const __half* vs = Vt[buf];

        // ---- S = Q K^T (already in log2 domain) ----
        float sacc[2][8][4] = {};
#pragma unroll
        for (int g = 0; g < 4; ++g) {
            const int koff = g * 16 + 4 * c;
#pragma unroll
            for (int nt = 0; nt < 8; ++nt) {
                const uint2 bb = *(const uint2*)(
                    ks + (size_t)(nt * 8 + r) * FSTR + koff);
                mma_f16(sacc[0][nt], qa[0][g][0], qa[0][g][1], qa[0][g][2],
                        qa[0][g][3], bb.x, bb.y);
                mma_f16(sacc[1][nt], qa[1][g][0], qa[1][g][1], qa[1][g][2],
                        qa[1][g][3], bb.x, bb.y);
            }
        }

        // ---- base-2 online softmax + fp16 P (jperm stores) ----
#pragma unroll
        for (int mt = 0; mt < 2; ++mt) {
            float tl = -1e30f, th = -1e30f;
#pragma unroll
            for (int nt = 0; nt < 8; ++nt) {
                tl = fmaxf(tl, fmaxf(sacc[mt][nt][0], sacc[mt][nt][1]));
                th = fmaxf(th, fmaxf(sacc[mt][nt][2], sacc[mt][nt][3]));
            }
            tl = fmaxf(tl, __shfl_xor_sync(0xffffffffu, tl, 1));
            tl = fmaxf(tl, __shfl_xor_sync(0xffffffffu, tl, 2));
            th = fmaxf(th, __shfl_xor_sync(0xffffffffu, th, 1));
            th = fmaxf(th, __shfl_xor_sync(0xffffffffu, th, 2));

            const float mnl = fmaxf(mrow[2 * mt],     tl);
            const float mnh = fmaxf(mrow[2 * mt + 1], th);
            const float crl = exp2f(mrow[2 * mt]     - mnl);
            const float crh = exp2f(mrow[2 * mt + 1] - mnh);

            float sl = 0.f, sh = 0.f;
            __half* prow0 = Pw + (size_t)(mt * 16 + r)     * FSTR;
            __half* prow8 = Pw + (size_t)(mt * 16 + r + 8) * FSTR;
#pragma unroll
            for (int nt = 0; nt < 8; ++nt) {
                const float p0 = exp2f(sacc[mt][nt][0] - mnl);
                const float p1 = exp2f(sacc[mt][nt][1] - mnl);
                const float p2 = exp2f(sacc[mt][nt][2] - mnh);
                const float p3 = exp2f(sacc[mt][nt][3] - mnh);
                sl += p0 + p1;
                sh += p2 + p3;
                const int off = (nt >> 1) * 16 + 4 * c + (nt & 1) * 2;
                *(uint32_t*)(prow0 + off) = h2pack(p0, p1);
                *(uint32_t*)(prow8 + off) = h2pack(p2, p3);
                oacc[mt][nt][0] *= crl; oacc[mt][nt][1] *= crl;
                oacc[mt][nt][2] *= crh; oacc[mt][nt][3] *= crh;
            }
            sl += __shfl_xor_sync(0xffffffffu, sl, 1);
            sl += __shfl_xor_sync(0xffffffffu, sl, 2);
            sh += __shfl_xor_sync(0xffffffffu, sh, 1);
            sh += __shfl_xor_sync(0xffffffffu, sh, 2);

            lrow[2 * mt]     = lrow[2 * mt]     * crl + sl;
            lrow[2 * mt + 1] = lrow[2 * mt + 1] * crh + sh;
            mrow[2 * mt]     = mnl;
            mrow[2 * mt + 1] = mnh;
        }
        __syncwarp();

        // ---- O += P V ----
#pragma unroll
        for (int g = 0; g < 4; ++g) {
            const int koff = g * 16 + 4 * c;
            uint32_t pa[2][4];
#pragma unroll
            for (int mt = 0; mt < 2; ++mt) {
                const __half* p0 = Pw + (size_t)(mt * 16 + r) * FSTR + koff;
                const uint2 u0 = *(const uint2*)p0;
                const uint2 u8 = *(const uint2*)(p0 + 8 * FSTR);
                pa[mt][0] = u0.x; pa[mt][1] = u8.x;
                pa[mt][2] = u0.y; pa[mt][3] = u8.y;
            }
#pragma unroll
            for (int nt = 0; nt < 8; ++nt) {
                const uint2 vv = *(const uint2*)(
                    vs + (size_t)(nt * 8 + r) * FSTR + koff);
                mma_f16(oacc[0][nt], pa[0][0], pa[0][1], pa[0][2], pa[0][3],
                        vv.x, vv.y);
                mma_f16(oacc[1][nt], pa[1][0], pa[1][1], pa[1][2], pa[1][3],
                        vv.x, vv.y);
            }
        }
    }

    // ---- epilogue: normalize, fp16 store (cols already dperm) ----
#pragma unroll
    for (int mt = 0; mt < 2; ++mt) {
        const float inv_lo = 1.0f / lrow[2 * mt];
        const float inv_hi = 1.0f / lrow[2 * mt + 1];
        const size_t row_lo = (size_t)(b * Sv + i0 + wid * 32 + mt * 16 + r);
#pragma unroll
        for (int nt = 0; nt < 8; ++nt) {
            const int col = h * DKv + nt * 8 + 2 * c;
            *(uint32_t*)(o + row_lo * Dv + col) =
                h2pack(oacc[mt][nt][0] * inv_lo, oacc[mt][nt][1] * inv_lo);
            *(uint32_t*)(o + (row_lo + 8) * Dv + col) =
                h2pack(oacc[mt][nt][2] * inv_hi, oacc[mt][nt][3] * inv_hi);
        }
    }
}

// ---------------------------------------------------------------------------
// LN1: (x + wo-out), fp32 standard -> h fp16 perm16 + h fp32 standard.
// ---------------------------------------------------------------------------
__global__ void __launch_bounds__(256) residual_ln1(
    const float* __restrict__ a, const float* __restrict__ r,
    const float* __restrict__ g, const float* __restrict__ be,
    __half* __restrict__ outh, float* __restrict__ outf)
{
    const size_t row = (size_t)blockIdx.x * 8 + (threadIdx.x >> 5);
    const int lane = threadIdx.x & 31;

    float v[32];
    float s = 0.f, s2 = 0.f;
#pragma unroll
    for (int gg = 0; gg < 4; ++gg) {
        const int gb = (gg * 32 + lane) * 8;
        const float4 a0 = *(const float4*)(a + row * Dv + gb);
        const float4 a1 = *(const float4*)(a + row * Dv + gb + 4);
        const float4 r0 = *(const float4*)(r + row * Dv + gb);
        const float4 r1 = *(const float4*)(r + row * Dv + gb + 4);
        float* vv = v + gg * 8;
        vv[0] = a0.x + r0.x; vv[1] = a0.y + r0.y; vv[2] = a0.z + r0.z; vv[3] = a0.w + r0.w;
        vv[4] = a1.x + r1.x; vv[5] = a1.y + r1.y; vv[6] = a1.z + r1.z; vv[7] = a1.w + r1.w;
#pragma unroll
        for (int i = 0; i < 8; ++i) { s += vv[i]; s2 += vv[i] * vv[i]; }
    }
#pragma unroll
    for (int o_ = 16; o_ > 0; o_ >>= 1) {
        s  += __shfl_xor_sync(0xffffffffu, s,  o_);
        s2 += __shfl_xor_sync(0xffffffffu, s2, o_);
    }
    const float mu  = s * (1.0f / Dv);
    const float var = s2 * (1.0f / Dv) - mu * mu;
    const float inv = rsqrtf(var + LN_EPS);

#pragma unroll
    for (int gg = 0; gg < 4; ++gg) {
        const int G  = gg * 32 + lane;
        const int gb = G * 8;
        const float4 g0 = *(const float4*)(g + gb);
        const float4 g1v = *(const float4*)(g + gb + 4);
        const float4 b0 = *(const float4*)(be + gb);
        const float4 b1v = *(const float4*)(be + gb + 4);
        const float* vv = v + gg * 8;
        float y[8];
        y[0] = (vv[0] - mu) * inv * g0.x  + b0.x;
        y[1] = (vv[1] - mu) * inv * g0.y  + b0.y;
        y[2] = (vv[2] - mu) * inv * g0.z  + b0.z;
        y[3] = (vv[3] - mu) * inv * g0.w  + b0.w;
        y[4] = (vv[4] - mu) * inv * g1v.x + b1v.x;
        y[5] = (vv[5] - mu) * inv * g1v.y + b1v.y;
        y[6] = (vv[6] - mu) * inv * g1v.z + b1v.z;
        y[7] = (vv[7] - mu) * inv * g1v.w + b1v.w;
        float4 o0, o1;
        o0.x = y[0]; o0.y = y[1]; o0.z = y[2]; o0.w = y[3];
        o1.x = y[4]; o1.y = y[5]; o1.z = y[6]; o1.w = y[7];
        *(float4*)(outf + row * Dv + gb)     = o0;
        *(float4*)(outf + row * Dv + gb + 4) = o1;
        __half* hb = outh + row * Dv + (G >> 1) * 16 + (G & 1) * 2;
        *(uint32_t*)(hb + 0)  = h2pack(y[0], y[1]);
        *(uint32_t*)(hb + 4)  = h2pack(y[2], y[3]);
        *(uint32_t*)(hb + 8)  = h2pack(y[4], y[5]);
        *(uint32_t*)(hb + 12) = h2pack(y[6], y[7]);
    }
}

// LN2: (h fp32 + ff2 fp32), standard -> out fp32 standard.
__global__ void __launch_bounds__(256) residual_ln2(
    const float* __restrict__ a, const float* __restrict__ r,
    const float* __restrict__ g, const float* __restrict__ be,
    float* __restrict__ out)
{
    const size_t row = (size_t)blockIdx.x * 8 + (threadIdx.x >> 5);
    const int lane = threadIdx.x & 31;

    float v[32];
    float s = 0.f, s2 = 0.f;
#pragma unroll
    for (int gg = 0; gg < 4; ++gg) {
        const int gb = (gg * 32 + lane) * 8;
        const float4 a0 = *(const float4*)(a + row * Dv + gb);
        const float4 a1 = *(const float4*)(a + row * Dv + gb + 4);
        const float4 r0 = *(const float4*)(r + row * Dv + gb);
        const float4 r1 = *(const float4*)(r + row * Dv + gb + 4);
        float* vv = v + gg * 8;
        vv[0] = a0.x + r0.x; vv[1] = a0.y + r0.y; vv[2] = a0.z + r0.z; vv[3] = a0.w + r0.w;
        vv[4] = a1.x + r1.x; vv[5] = a1.y + r1.y; vv[6] = a1.z + r1.z; vv[7] = a1.w + r1.w;
#pragma unroll
        for (int i = 0; i < 8; ++i) { s += vv[i]; s2 += vv[i] * vv[i]; }
    }
#pragma unroll
    for (int o_ = 16; o_ > 0; o_ >>= 1) {
        s  += __shfl_xor_sync(0xffffffffu, s,  o_);
        s2 += __shfl_xor_sync(0xffffffffu, s2, o_);
    }
    const float mu  = s * (1.0f / Dv);
    const float var = s2 * (1.0f / Dv) - mu * mu;
    const float inv = rsqrtf(var + LN_EPS);

#pragma unroll
    for (int gg = 0; gg < 4; ++gg) {
        const int gb = (gg * 32 + lane) * 8;
        const float4 g0 = *(const float4*)(g + gb);
        const float4 g1v = *(const float4*)(g + gb + 4);
        const float4 b0 = *(const float4*)(be + gb);
        const float4 b1v = *(const float4*)(be + gb + 4);
        const float* vv = v + gg * 8;
        float4 o0, o1;
        o0.x = (vv[0] - mu) * inv * g0.x  + b0.x;
        o0.y = (vv[1] - mu) * inv * g0.y  + b0.y;
        o0.z = (vv[2] - mu) * inv * g0.z  + b0.z;
        o0.w = (vv[3] - mu) * inv * g0.w  + b0.w;
        o1.x = (vv[4] - mu) * inv * g1v.x + b1v.x;
        o1.y = (vv[5] - mu) * inv * g1v.y + b1v.y;
        o1.z = (vv[6] - mu) * inv * g1v.z + b1v.z;
        o1.w = (vv[7] - mu) * inv * g1v.w + b1v.w;
        *(float4*)(out + row * Dv + gb)     = o0;
        *(float4*)(out + row * Dv + gb + 4) = o1;
    }
}

// ---------------------------------------------------------------------------
// Launch
// ---------------------------------------------------------------------------
extern "C" void kernel_launch(void* const* d_in, const int* in_sizes, int n_in,
                              void* d_out, int out_size)
{
    const float* x  = (const float*)d_in[0];
    const float* wq = (const float*)d_in[1];
    const float* bq = (const float*)d_in[2];
    const float* wk = (const float*)d_in[3];
    const float* bk = (const float*)d_in[4];
    const float* wv = (const float*)d_in[5];
    const float* bv = (const float*)d_in[6];
    const float* wo = (const float*)d_in[7];
    const float* bo = (const float*)d_in[8];
    const float* w1 = (const float*)d_in[9];
    const float* b1 = (const float*)d_in[10];
    const float* w2 = (const float*)d_in[11];
    const float* b2 = (const float*)d_in[12];
    const float* g1 = (const float*)d_in[13];
    const float* be1= (const float*)d_in[14];
    const float* g2 = (const float*)d_in[15];
    const float* be2= (const float*)d_in[16];
    float* out = (float*)d_out;

    __half *qkv, *xr, *attn, *hh, *ff1, *vt, *wh;
    float *hf, *tmp, *tmp2, *bqkv;
    cudaGetSymbolAddress((void**)&qkv,  g_qkv);
    cudaGetSymbolAddress((void**)&xr,   g_xr);
    cudaGetSymbolAddress((void**)&attn, g_attn);
    cudaGetSymbolAddress((void**)&hh,   g_h);
    cudaGetSymbolAddress((void**)&hf,   g_hf);
    cudaGetSymbolAddress((void**)&ff1,  g_ff1);
    cudaGetSymbolAddress((void**)&vt,   g_vt);
    cudaGetSymbolAddress((void**)&wh,   g_w);
    cudaGetSymbolAddress((void**)&tmp,  g_tmp);
    cudaGetSymbolAddress((void**)&tmp2, g_tmp2);
    cudaGetSymbolAddress((void**)&bqkv, g_bqkv);

    const size_t MB1 = 1024 * 1024;
    __half* wqkvT = wh;               // [3072][1024]
    __half* woT   = wh + 3 * MB1;
    __half* w1T   = wh + 4 * MB1;     // [F, D]
    __half* w2T   = wh + 8 * MB1;     // [D, F]

    cudaFuncSetAttribute(gemm_h<false, true,  true >,
        cudaFuncAttributeMaxDynamicSharedMemorySize, GSMEM_BYTES);
    cudaFuncSetAttribute(gemm_h<false, false, false>,
        cudaFuncAttributeMaxDynamicSharedMemorySize, GSMEM_BYTES);
    cudaFuncSetAttribute(gemm_h<true,  true,  false>,
        cudaFuncAttributeMaxDynamicSharedMemorySize, GSMEM_BYTES);
    cudaFuncSetAttribute(flash_attn,
        cudaFuncAttributeMaxDynamicSharedMemorySize, FA_SMEM_BYTES);

    // Weight + input prep
    dim3 tb(32, 8);
    transpose4_f16<<<dim3(Dv / 32, Dv / 32, 4), tb>>>(wq, wk, wv, wo, wqkvT);
    transpose_f16<<<dim3(Fv / 32, Dv / 32), tb>>>(w1, w1T, Dv, Fv);
    transpose_f16<<<dim3(Dv / 32, Fv / 32), tb>>>(w2, w2T, Fv, Dv);
    prep_x_bias<<<PREP_XBLKS + 3, 256>>>(x, xr, bq, bk, bv, bqkv);

    // QKV projection -> qkv fp16 (cols perm16, q pre-scaled)
    gemm_h<false, true, true><<<dim3(QS / 128, Mv / 128), 128, GSMEM_BYTES>>>(
        Dv, QS, xr, wqkvT, bqkv, qkv);

    // V transpose for fp16 PV fragments
    transpose_v<<<dim3(Sv / 64, Dv / 64, Bv), tb>>>(qkv, vt);

    // Flash attention -> attn fp16 (dperm)
    flash_attn<<<dim3(Sv / 128, Bv * Hv), 128, FA_SMEM_BYTES>>>(qkv, vt, attn);

    const dim3 gDD(Dv / 128, Mv / 128);   // (8, 32)
    const dim3 gDF(Fv / 128, Mv / 128);   // (32, 32)

    // Output projection (fp32 standard) + LN1 (dual output)
    gemm_h<false, false, false><<<gDD, 128, GSMEM_BYTES>>>(Dv, Dv, attn, woT, bo, tmp);
    residual_ln1<<<Mv / 8, 256>>>(x, tmp, g1, be1, hh, hf);

    // FFN + LN2
    gemm_h<true,  true,  false><<<gDF, 128, GSMEM_BYTES>>>(Dv, Fv, hh, w1T, b1, ff1);
    gemm_h<false, false, false><<<gDD, 128, GSMEM_BYTES>>>(Fv, Dv, ff1, w2T, b2, tmp2);
    residual_ln2<<<Mv / 8, 256>>>(hf, tmp2, g2, be2, out);
}